// round 1
// baseline (speedup 1.0000x reference)
#include <cuda_runtime.h>

// Problem constants
#define TT 2048
#define EE 768
#define SSP 256
#define HHD 150
#define E3D 2304

// ---------------- scratch (device global, zero-init .bss) ----------------
// layout (floats):
//  h1tok  2048*160
//  h2tok  2048*160
//  we     2048*768
//  g      256*2304
//  mh1    256*160
//  mh2    256*160
//  m      256
//  hi     256*160
//  hj     256*160
//  h1p    65536*160
static constexpr long OFF_H1TOK = 0;
static constexpr long OFF_H2TOK = OFF_H1TOK + 2048L * 160;
static constexpr long OFF_WE    = OFF_H2TOK + 2048L * 160;
static constexpr long OFF_G     = OFF_WE    + 2048L * 768;
static constexpr long OFF_MH1   = OFF_G     + 256L * 2304;
static constexpr long OFF_MH2   = OFF_MH1   + 256L * 160;
static constexpr long OFF_M     = OFF_MH2   + 256L * 160;
static constexpr long OFF_HI    = OFF_M     + 256L;
static constexpr long OFF_HJ    = OFF_HI    + 256L * 160;
static constexpr long OFF_H1P   = OFF_HJ    + 256L * 160;
static constexpr long SCRATCH_TOTAL = OFF_H1P + 65536L * 160;

__device__ __align__(16) float g_scratch[SCRATCH_TOTAL];

// ---------------- generic GEMM: C[M,150] = act(A[M,K] @ W[K,150] + b) ----
// BM=64 rows/block, N fixed at 150 (padded to 160), 256 threads,
// thread tile 4 rows x 10 cols. A may come from scratch (aOff) or external.
template <int ACT, int HASBIAS>
__global__ __launch_bounds__(256) void gemm150(
    const float* __restrict__ Aext, long aOff, int lda,
    const float* __restrict__ W,
    const float* __restrict__ bias,
    long cOff, int ldc, int M, int K)
{
    const float* A = Aext ? Aext : (g_scratch + aOff);
    float* C = g_scratch + cOff;

    __shared__ float sA[16][68];   // [k][row], padded for banks + 16B align
    __shared__ float sW[16][160];

    int tid = threadIdx.x;
    int rg = tid >> 4;      // row group 0..15 -> rows rg*4..rg*4+3
    int cg = tid & 15;      // col group 0..15 -> cols cg*10..cg*10+9
    int row0 = blockIdx.x * 64;

    float acc[4][10];
#pragma unroll
    for (int a = 0; a < 4; a++)
#pragma unroll
        for (int b = 0; b < 10; b++) acc[a][b] = 0.f;

    int nCh = (K + 15) >> 4;
    for (int ch = 0; ch < nCh; ch++) {
        int k0 = ch * 16;
        // load A tile (64 rows x 16 k), coalesced on k
        {
            int c = tid & 15, r = tid >> 4;
#pragma unroll
            for (int pass = 0; pass < 4; pass++) {
                int rl = pass * 16 + r;
                float v = 0.f;
                if (k0 + c < K) v = A[(long)(row0 + rl) * lda + k0 + c];
                sA[c][rl] = v;
            }
        }
        // load W tile (16 x 160), zero-padded
#pragma unroll
        for (int i = 0; i < 10; i++) {
            int idx = tid + i * 256;
            int k = idx / 160, h = idx - k * 160;
            float v = 0.f;
            if (k0 + k < K && h < 150) v = W[(long)(k0 + k) * 150 + h];
            sW[k][h] = v;
        }
        __syncthreads();
#pragma unroll
        for (int k = 0; k < 16; k++) {
            float4 a4 = *(const float4*)&sA[k][rg * 4];
            float av0 = a4.x, av1 = a4.y, av2 = a4.z, av3 = a4.w;
#pragma unroll
            for (int hh = 0; hh < 10; hh += 2) {
                float2 w = *(const float2*)&sW[k][cg * 10 + hh];
                acc[0][hh]     += av0 * w.x;  acc[0][hh + 1] += av0 * w.y;
                acc[1][hh]     += av1 * w.x;  acc[1][hh + 1] += av1 * w.y;
                acc[2][hh]     += av2 * w.x;  acc[2][hh + 1] += av2 * w.y;
                acc[3][hh]     += av3 * w.x;  acc[3][hh + 1] += av3 * w.y;
            }
        }
        __syncthreads();
    }

#pragma unroll
    for (int rr = 0; rr < 4; rr++) {
        int row = row0 + rg * 4 + rr;
#pragma unroll
        for (int hh = 0; hh < 10; hh++) {
            int h = cg * 10 + hh;
            if (h < 150) {
                float v = acc[rr][hh];
                if (HASBIAS) v += bias[h];
                if (ACT) v = fmaxf(v, 0.f);
                C[(long)row * ldc + h] = v;
            }
        }
    }
}

// ---------------- attn = h2 . aW3 + b; we = e * attn -------------------
__global__ __launch_bounds__(256) void attn_we_kernel(
    const float* __restrict__ w3, const float* __restrict__ b3,
    const float* __restrict__ e)
{
    __shared__ float red[256];
    const float* h2 = g_scratch + OFF_H2TOK;
    float* we = g_scratch + OFF_WE;
    int t = blockIdx.x, tid = threadIdx.x;
    float v = 0.f;
    if (tid < 150) v = h2[(long)t * 160 + tid] * w3[tid];
    red[tid] = v;
    __syncthreads();
    for (int s = 128; s > 0; s >>= 1) {
        if (tid < s) red[tid] += red[tid + s];
        __syncthreads();
    }
    float attn = red[0] + b3[0];
#pragma unroll
    for (int i = 0; i < 3; i++) {
        int c = tid + i * 256;
        we[(long)t * 768 + c] = e[(long)t * 768 + c] * attn;
    }
}

// ---------------- row dot: out[r] = A[r,:150] . w + b -------------------
__global__ __launch_bounds__(256) void rowdot_kernel(
    long aOff, const float* __restrict__ w, const float* __restrict__ b,
    long oOff)
{
    __shared__ float red[256];
    const float* A = g_scratch + aOff;
    float* out = g_scratch + oOff;
    int r = blockIdx.x, tid = threadIdx.x;
    float v = 0.f;
    if (tid < 150) v = A[(long)r * 160 + tid] * w[tid];
    red[tid] = v;
    __syncthreads();
    for (int s = 128; s > 0; s >>= 1) {
        if (tid < s) red[tid] += red[tid + s];
        __syncthreads();
    }
    if (tid == 0) out[r] = red[0] + b[0];
}

// ---------------- g = [e_start | e_end | span_sum] ----------------------
__global__ __launch_bounds__(256) void gather_g_kernel(
    const float* __restrict__ e,
    const int* __restrict__ sp, const int* __restrict__ wd)
{
    const float* we = g_scratch + OFF_WE;
    float* g = g_scratch + OFF_G;
    int s = blockIdx.x, tid = threadIdx.x;
    int st = sp[s];
    int en = st + wd[s];
    if (en > TT - 1) en = TT - 1;
    if (en < 0) en = 0;
#pragma unroll
    for (int i = 0; i < 3; i++) {
        int c = tid + i * 256;
        g[(long)s * 2304 + c]        = e[(long)st * 768 + c];
        g[(long)s * 2304 + 768 + c]  = e[(long)en * 768 + c];
        float sum = 0.f;
        for (int t = st; t <= en; t++) sum += we[(long)t * 768 + c];
        g[(long)s * 2304 + 1536 + c] = sum;
    }
}

// ---------------- big pairwise kernel: h1p[i,j,:] -----------------------
// grid (32,32) of 8x8-pair tiles; 256 threads; thread tile 4 pairs x 10 h.
__global__ __launch_bounds__(256) void pair_h1_kernel(
    const float* __restrict__ Wc, const float* __restrict__ pb1)
{
    __shared__ float sGi[8][32], sGj[8][32];
    __shared__ float sX[32][64];     // [e][pair]
    __shared__ float sW[32][160];    // [e][h]

    const float* g  = g_scratch + OFF_G;
    const float* hi = g_scratch + OFF_HI;
    const float* hj = g_scratch + OFF_HJ;
    float* h1p      = g_scratch + OFF_H1P;

    int tid = threadIdx.x;
    int pg = tid >> 4;   // pair group: pairs pg*4..pg*4+3
    int hg = tid & 15;   // h group: h = hg*10..hg*10+9
    int ibase = blockIdx.x * 8, jbase = blockIdx.y * 8;

    float acc[4][10];
#pragma unroll
    for (int a = 0; a < 4; a++)
#pragma unroll
        for (int b = 0; b < 10; b++) acc[a][b] = 0.f;

    for (int ch = 0; ch < 72; ch++) {
        int e0 = ch * 32;
        {
            int r = tid >> 5, c = tid & 31;
            sGi[r][c] = g[(long)(ibase + r) * 2304 + e0 + c];
            sGj[r][c] = g[(long)(jbase + r) * 2304 + e0 + c];
        }
#pragma unroll
        for (int i = 0; i < 20; i++) {
            int idx = tid + i * 256;
            int e = idx / 160, h = idx - e * 160;
            sW[e][h] = (h < 150) ? Wc[(long)(e0 + e) * 150 + h] : 0.f;
        }
        __syncthreads();
#pragma unroll
        for (int i = 0; i < 8; i++) {
            int idx = tid + i * 256;
            int e = idx >> 6, p = idx & 63;
            sX[e][p] = sGi[p >> 3][e] * sGj[p & 7][e];
        }
        __syncthreads();
#pragma unroll 8
        for (int e = 0; e < 32; e++) {
            float4 x4 = *(const float4*)&sX[e][pg * 4];
            float x0 = x4.x, x1 = x4.y, x2 = x4.z, x3 = x4.w;
#pragma unroll
            for (int hh = 0; hh < 10; hh += 2) {
                float2 w = *(const float2*)&sW[e][hg * 10 + hh];
                acc[0][hh]     += x0 * w.x;  acc[0][hh + 1] += x0 * w.y;
                acc[1][hh]     += x1 * w.x;  acc[1][hh + 1] += x1 * w.y;
                acc[2][hh]     += x2 * w.x;  acc[2][hh + 1] += x2 * w.y;
                acc[3][hh]     += x3 * w.x;  acc[3][hh + 1] += x3 * w.y;
            }
        }
        __syncthreads();
    }

#pragma unroll
    for (int pp = 0; pp < 4; pp++) {
        int p = pg * 4 + pp, ri = p >> 3, rj = p & 7;
        int i = ibase + ri, j = jbase + rj;
        long base = ((long)i * 256 + j) * 160;
#pragma unroll
        for (int hh = 0; hh < 10; hh++) {
            int h = hg * 10 + hh;
            float v = 0.f;
            if (h < 150)
                v = fmaxf(acc[pp][hh] + hi[i * 160 + h] + hj[j * 160 + h] + pb1[h], 0.f);
            h1p[base + h] = v;   // padded cols written as 0 for pair_out
        }
    }
}

// ---------------- per-pair h2 GEMM + score + clip -----------------------
// block = 32 pairs, 256 threads, thread tile 2 pairs x 10 h'
__global__ __launch_bounds__(256) void pair_out_kernel(
    const float* __restrict__ W2, const float* __restrict__ pb2,
    const float* __restrict__ w3, const float* __restrict__ pb3,
    float* __restrict__ out)
{
    __shared__ float sH1[32][160];
    __shared__ float sW2[32][160];
    __shared__ float sRed[32][16];

    const float* h1p = g_scratch + OFF_H1P;
    const float* m   = g_scratch + OFF_M;

    int tid = threadIdx.x;
    int pg = tid >> 4, hg = tid & 15;
    long p0 = (long)blockIdx.x * 32;

    {
        const float4* src = (const float4*)(h1p + p0 * 160);
        float4* dst = (float4*)&sH1[0][0];
#pragma unroll
        for (int i = 0; i < 5; i++) dst[tid + i * 256] = src[tid + i * 256];
    }

    float acc[2][10];
#pragma unroll
    for (int a = 0; a < 2; a++)
#pragma unroll
        for (int b = 0; b < 10; b++) acc[a][b] = 0.f;

    for (int kc = 0; kc < 5; kc++) {
        int kb = kc * 32;
#pragma unroll
        for (int i = 0; i < 20; i++) {
            int idx = tid + i * 256;
            int e = idx / 160, h = idx - e * 160;
            int kk = kb + e;
            sW2[e][h] = (kk < 150 && h < 150) ? W2[(long)kk * 150 + h] : 0.f;
        }
        __syncthreads();
#pragma unroll 8
        for (int e = 0; e < 32; e++) {
            float x0 = sH1[pg * 2][kb + e];
            float x1 = sH1[pg * 2 + 1][kb + e];
#pragma unroll
            for (int hh = 0; hh < 10; hh += 2) {
                float2 w = *(const float2*)&sW2[e][hg * 10 + hh];
                acc[0][hh]     += x0 * w.x;  acc[0][hh + 1] += x0 * w.y;
                acc[1][hh]     += x1 * w.x;  acc[1][hh + 1] += x1 * w.y;
            }
        }
        __syncthreads();
    }

#pragma unroll
    for (int pp = 0; pp < 2; pp++) {
        float sacc = 0.f;
#pragma unroll
        for (int hh = 0; hh < 10; hh++) {
            int h = hg * 10 + hh;
            if (h < 150) {
                float v = fmaxf(acc[pp][hh] + pb2[h], 0.f);
                sacc += v * w3[h];
            }
        }
        sRed[pg * 2 + pp][hg] = sacc;
    }
    __syncthreads();
    if (tid < 32) {
        float s = pb3[0];
#pragma unroll
        for (int h = 0; h < 16; h++) s += sRed[tid][h];
        long pr = p0 + tid;
        int i = (int)(pr >> 8), j = (int)(pr & 255);
        float v = (m[i] + m[j] + s) * (1.f / 3.f);
        v = fminf(fmaxf(v, 0.f), 1.f);
        out[pr] = v;
    }
}

// ---------------- launch ------------------------------------------------
extern "C" void kernel_launch(void* const* d_in, const int* in_sizes, int n_in,
                              void* d_out, int out_size)
{
    const float* e   = (const float*)d_in[0];
    const int*   sp  = (const int*)d_in[1];
    const int*   wd  = (const int*)d_in[2];
    const float* aW1 = (const float*)d_in[3];
    const float* ab1 = (const float*)d_in[4];
    const float* aW2 = (const float*)d_in[5];
    const float* ab2 = (const float*)d_in[6];
    const float* aW3 = (const float*)d_in[7];
    const float* ab3 = (const float*)d_in[8];
    const float* mW1 = (const float*)d_in[9];
    const float* mb1 = (const float*)d_in[10];
    const float* mW2 = (const float*)d_in[11];
    const float* mb2 = (const float*)d_in[12];
    const float* mW3 = (const float*)d_in[13];
    const float* mb3 = (const float*)d_in[14];
    const float* pW1 = (const float*)d_in[15];
    const float* pb1 = (const float*)d_in[16];
    const float* pW2 = (const float*)d_in[17];
    const float* pb2 = (const float*)d_in[18];
    const float* pW3 = (const float*)d_in[19];
    const float* pb3 = (const float*)d_in[20];
    float* out = (float*)d_out;

    // token MLP
    gemm150<1, 1><<<2048 / 64, 256>>>(e, 0, 768, aW1, ab1, OFF_H1TOK, 160, 2048, 768);
    gemm150<1, 1><<<2048 / 64, 256>>>(nullptr, OFF_H1TOK, 160, aW2, ab2, OFF_H2TOK, 160, 2048, 150);
    attn_we_kernel<<<2048, 256>>>(aW3, ab3, e);

    // span features
    gather_g_kernel<<<256, 256>>>(e, sp, wd);

    // m MLP
    gemm150<1, 1><<<256 / 64, 256>>>(nullptr, OFF_G, 2304, mW1, mb1, OFF_MH1, 160, 256, 2304);
    gemm150<1, 1><<<256 / 64, 256>>>(nullptr, OFF_MH1, 160, mW2, mb2, OFF_MH2, 160, 256, 150);
    rowdot_kernel<<<256, 256>>>(OFF_MH2, mW3, mb3, OFF_M);

    // hi = g @ Wa, hj = g @ Wb  (no bias/act)
    gemm150<0, 0><<<256 / 64, 256>>>(nullptr, OFF_G, 2304, pW1, nullptr, OFF_HI, 160, 256, 2304);
    gemm150<0, 0><<<256 / 64, 256>>>(nullptr, OFF_G, 2304, pW1 + 2304L * 150, nullptr, OFF_HJ, 160, 256, 2304);

    // pairwise
    pair_h1_kernel<<<dim3(32, 32), 256>>>(pW1 + 4608L * 150, pb1);
    pair_out_kernel<<<65536 / 32, 256>>>(pW2, pb2, pW3, pb3, out);
}

// round 3
// speedup vs baseline: 1.6155x; 1.6155x over previous
#include <cuda_runtime.h>
#include <cuda_bf16.h>
#include <cstdint>

// Problem constants
#define TT 2048
#define EE 768
#define SSP 256
#define HHD 150
#define E3D 2304

// ---------------- scratch (device global, zero-init .bss) ----------------
static constexpr long OFF_H1TOK = 0;
static constexpr long OFF_H2TOK = OFF_H1TOK + 2048L * 160;
static constexpr long OFF_WE    = OFF_H2TOK + 2048L * 160;
static constexpr long OFF_G     = OFF_WE    + 2048L * 768;
static constexpr long OFF_MH1   = OFF_G     + 256L * 2304;
static constexpr long OFF_MH2   = OFF_MH1   + 256L * 160;
static constexpr long OFF_M     = OFF_MH2   + 256L * 160;
static constexpr long OFF_HI    = OFF_M     + 256L;
static constexpr long OFF_HJ    = OFF_HI    + 256L * 160;
static constexpr long OFF_H1P   = OFF_HJ    + 256L * 160;
static constexpr long SCRATCH_TOTAL = OFF_H1P + 65536L * 160;

__device__ __align__(16) float g_scratch[SCRATCH_TOTAL];

// Wc transposed + split into bf16 hi/lo: [160 n][2304 k], n>=150 zero-padded
__device__ __align__(16) unsigned short g_wct_h[160L * 2304];
__device__ __align__(16) unsigned short g_wct_l[160L * 2304];

// ======================= helpers ==========================
__device__ __forceinline__ uint32_t smem_u32(const void* p) {
    uint32_t a;
    asm("{ .reg .u64 t; cvta.to.shared.u64 t, %1; cvt.u32.u64 %0, t; }"
        : "=r"(a) : "l"(p));
    return a;
}
#define SWZ(x) ((x) ^ (((x) >> 3) & 0x70))
#define STS128(a0, a1, a2, a3, addr) \
    asm volatile("st.shared.v4.b32 [%0], {%1,%2,%3,%4};" \
                 :: "r"(addr), "r"(a0), "r"(a1), "r"(a2), "r"(a3) : "memory")
// packed bf16x2: low half = lo, high half = hi
#define CVT2(d, lo, hi) \
    asm("cvt.rn.bf16x2.f32 %0, %1, %2;" : "=r"(d) : "f"(hi), "f"(lo))

__device__ __forceinline__ float bf_lo(uint32_t w) { return __uint_as_float(w << 16); }
__device__ __forceinline__ float bf_hi(uint32_t w) { return __uint_as_float(w & 0xffff0000u); }

#define LDSM_X4(r0, r1, r2, r3, a) \
    asm volatile("ldmatrix.sync.aligned.m8n8.x4.shared.b16 {%0,%1,%2,%3}, [%4];" \
                 : "=r"(r0), "=r"(r1), "=r"(r2), "=r"(r3) : "r"(a))
#define LDSM_X2(r0, r1, a) \
    asm volatile("ldmatrix.sync.aligned.m8n8.x2.shared.b16 {%0,%1}, [%2];" \
                 : "=r"(r0), "=r"(r1) : "r"(a))
#define MMA16816(c, A0, A1, A2, A3, B0, B1) \
    asm volatile("mma.sync.aligned.m16n8k16.row.col.f32.bf16.bf16.f32 " \
                 "{%0,%1,%2,%3}, {%4,%5,%6,%7}, {%8,%9}, {%0,%1,%2,%3};" \
                 : "+f"((c)[0]), "+f"((c)[1]), "+f"((c)[2]), "+f"((c)[3]) \
                 : "r"(A0), "r"(A1), "r"(A2), "r"(A3), "r"(B0), "r"(B1))

// ---------------- generic GEMM: C[M,150] = act(A[M,K] @ W[K,150] + b) ----
template <int ACT, int HASBIAS>
__global__ __launch_bounds__(256) void gemm150(
    const float* __restrict__ Aext, long aOff, int lda,
    const float* __restrict__ W,
    const float* __restrict__ bias,
    long cOff, int ldc, int M, int K)
{
    const float* A = Aext ? Aext : (g_scratch + aOff);
    float* C = g_scratch + cOff;

    __shared__ float sA[16][68];
    __shared__ float sW[16][160];

    int tid = threadIdx.x;
    int rg = tid >> 4;
    int cg = tid & 15;
    int row0 = blockIdx.x * 64;

    float acc[4][10];
#pragma unroll
    for (int a = 0; a < 4; a++)
#pragma unroll
        for (int b = 0; b < 10; b++) acc[a][b] = 0.f;

    int nCh = (K + 15) >> 4;
    for (int ch = 0; ch < nCh; ch++) {
        int k0 = ch * 16;
        {
            int c = tid & 15, r = tid >> 4;
#pragma unroll
            for (int pass = 0; pass < 4; pass++) {
                int rl = pass * 16 + r;
                float v = 0.f;
                if (k0 + c < K) v = A[(long)(row0 + rl) * lda + k0 + c];
                sA[c][rl] = v;
            }
        }
#pragma unroll
        for (int i = 0; i < 10; i++) {
            int idx = tid + i * 256;
            int k = idx / 160, h = idx - k * 160;
            float v = 0.f;
            if (k0 + k < K && h < 150) v = W[(long)(k0 + k) * 150 + h];
            sW[k][h] = v;
        }
        __syncthreads();
#pragma unroll
        for (int k = 0; k < 16; k++) {
            float4 a4 = *(const float4*)&sA[k][rg * 4];
            float av0 = a4.x, av1 = a4.y, av2 = a4.z, av3 = a4.w;
#pragma unroll
            for (int hh = 0; hh < 10; hh += 2) {
                float2 w = *(const float2*)&sW[k][cg * 10 + hh];
                acc[0][hh]     += av0 * w.x;  acc[0][hh + 1] += av0 * w.y;
                acc[1][hh]     += av1 * w.x;  acc[1][hh + 1] += av1 * w.y;
                acc[2][hh]     += av2 * w.x;  acc[2][hh + 1] += av2 * w.y;
                acc[3][hh]     += av3 * w.x;  acc[3][hh + 1] += av3 * w.y;
            }
        }
        __syncthreads();
    }

#pragma unroll
    for (int rr = 0; rr < 4; rr++) {
        int row = row0 + rg * 4 + rr;
#pragma unroll
        for (int hh = 0; hh < 10; hh++) {
            int h = cg * 10 + hh;
            if (h < 150) {
                float v = acc[rr][hh];
                if (HASBIAS) v += bias[h];
                if (ACT) v = fmaxf(v, 0.f);
                C[(long)row * ldc + h] = v;
            }
        }
    }
}

// ---------------- attn = h2 . aW3 + b; we = e * attn -------------------
__global__ __launch_bounds__(256) void attn_we_kernel(
    const float* __restrict__ w3, const float* __restrict__ b3,
    const float* __restrict__ e)
{
    __shared__ float red[256];
    const float* h2 = g_scratch + OFF_H2TOK;
    float* we = g_scratch + OFF_WE;
    int t = blockIdx.x, tid = threadIdx.x;
    float v = 0.f;
    if (tid < 150) v = h2[(long)t * 160 + tid] * w3[tid];
    red[tid] = v;
    __syncthreads();
    for (int s = 128; s > 0; s >>= 1) {
        if (tid < s) red[tid] += red[tid + s];
        __syncthreads();
    }
    float attn = red[0] + b3[0];
#pragma unroll
    for (int i = 0; i < 3; i++) {
        int c = tid + i * 256;
        we[(long)t * 768 + c] = e[(long)t * 768 + c] * attn;
    }
}

// ---------------- row dot: out[r] = A[r,:150] . w + b -------------------
__global__ __launch_bounds__(256) void rowdot_kernel(
    long aOff, const float* __restrict__ w, const float* __restrict__ b,
    long oOff)
{
    __shared__ float red[256];
    const float* A = g_scratch + aOff;
    float* out = g_scratch + oOff;
    int r = blockIdx.x, tid = threadIdx.x;
    float v = 0.f;
    if (tid < 150) v = A[(long)r * 160 + tid] * w[tid];
    red[tid] = v;
    __syncthreads();
    for (int s = 128; s > 0; s >>= 1) {
        if (tid < s) red[tid] += red[tid + s];
        __syncthreads();
    }
    if (tid == 0) out[r] = red[0] + b[0];
}

// ---------------- g = [e_start | e_end | span_sum] ----------------------
__global__ __launch_bounds__(256) void gather_g_kernel(
    const float* __restrict__ e,
    const int* __restrict__ sp, const int* __restrict__ wd)
{
    const float* we = g_scratch + OFF_WE;
    float* g = g_scratch + OFF_G;
    int s = blockIdx.x, tid = threadIdx.x;
    int st = sp[s];
    int en = st + wd[s];
    if (en > TT - 1) en = TT - 1;
    if (en < 0) en = 0;
#pragma unroll
    for (int i = 0; i < 3; i++) {
        int c = tid + i * 256;
        g[(long)s * 2304 + c]        = e[(long)st * 768 + c];
        g[(long)s * 2304 + 768 + c]  = e[(long)en * 768 + c];
        float sum = 0.f;
        for (int t = st; t <= en; t++) sum += we[(long)t * 768 + c];
        g[(long)s * 2304 + 1536 + c] = sum;
    }
}

// ---------------- Wc -> transposed bf16 hi/lo split ---------------------
__global__ __launch_bounds__(256) void wct_split_kernel(const float* __restrict__ Wc)
{
    long idx = (long)blockIdx.x * 256 + threadIdx.x;   // 0 .. 160*2304-1
    int n = (int)(idx / 2304);
    int k = (int)(idx - (long)n * 2304);
    float w = (n < 150) ? Wc[(long)k * 150 + n] : 0.f;
    __nv_bfloat16 h = __float2bfloat16(w);
    float hf = __bfloat162float(h);
    __nv_bfloat16 l = __float2bfloat16(w - hf);
    g_wct_h[idx] = __bfloat16_as_ushort(h);
    g_wct_l[idx] = __bfloat16_as_ushort(l);
}

// ================= pair_h1 via mma.sync bf16 3-pass =====================
// Grid (256 j, 2 i-half). CTA: M=128 rows i, N=160 cols h, K=2304.
// 512 threads = 16 warps in 4(m) x 4(n) layout; warp tile 32x40.
// K chunks of 64, double buffered in SMEM (hi/lo bf16 for A and B).
#define PH1_AH 0
#define PH1_AL 16384
#define PH1_BH 32768
#define PH1_BL 53248
#define PH1_BUF 73728
#define PH1_SMEM (2 * PH1_BUF)

__global__ void __launch_bounds__(512, 1) pair_h1_mma(const float* __restrict__ pb1)
{
    extern __shared__ char smem[];
    __shared__ float sHJ[160], sB1[160];
    uint32_t sb = smem_u32(smem);

    const float* g    = g_scratch + OFF_G;
    const float* hi_g = g_scratch + OFF_HI;
    const float* hj_g = g_scratch + OFF_HJ;
    float* h1p        = g_scratch + OFF_H1P;

    int tid  = threadIdx.x;
    int lane = tid & 31;
    int wid  = tid >> 5;
    int j    = blockIdx.x;
    int ih   = blockIdx.y;
    int wm   = (wid & 3) * 32;
    int wn   = (wid >> 2) * 40;

    if (tid < 160) {
        sHJ[tid] = hj_g[(long)j * 160 + tid];
        sB1[tid] = (tid < 150) ? pb1[tid] : 0.f;
    }

    float acc[2][5][4];
#pragma unroll
    for (int a = 0; a < 2; a++)
#pragma unroll
        for (int b = 0; b < 5; b++)
#pragma unroll
            for (int c = 0; c < 4; c++) acc[a][b][c] = 0.f;

    // per-thread staging coords
    int arow = tid >> 2;              // 0..127
    int akq  = (tid & 3) * 16;        // k offset within chunk (16 floats)
    const float* gi_base = g + ((long)ih * 128 + arow) * 2304 + akq;
    const float* gj_base = g + (long)j * 2304 + akq;

    auto stage = [&](int ch) {
        uint32_t tb = sb + (uint32_t)(ch & 1) * PH1_BUF;
        int k0 = ch * 64;
        // ---- A: row arow, 16 k values -> bf16 hi/lo, swizzled ----
        {
            const float4* gi4 = (const float4*)(gi_base + k0);
            const float4* gj4 = (const float4*)(gj_base + k0);
#pragma unroll
            for (int u = 0; u < 2; u++) {
                float4 a0 = gi4[u * 2], a1 = gi4[u * 2 + 1];
                float4 w0 = gj4[u * 2], w1 = gj4[u * 2 + 1];
                float p0 = a0.x * w0.x, p1 = a0.y * w0.y;
                float p2 = a0.z * w0.z, p3 = a0.w * w0.w;
                float p4 = a1.x * w1.x, p5 = a1.y * w1.y;
                float p6 = a1.z * w1.z, p7 = a1.w * w1.w;
                uint32_t h01, h23, h45, h67;
                CVT2(h01, p0, p1); CVT2(h23, p2, p3);
                CVT2(h45, p4, p5); CVT2(h67, p6, p7);
                uint32_t l01, l23, l45, l67;
                CVT2(l01, p0 - bf_lo(h01), p1 - bf_hi(h01));
                CVT2(l23, p2 - bf_lo(h23), p3 - bf_hi(h23));
                CVT2(l45, p4 - bf_lo(h45), p5 - bf_hi(h45));
                CVT2(l67, p6 - bf_lo(h67), p7 - bf_hi(h67));
                uint32_t sw = SWZ((uint32_t)(arow * 128 + akq * 2 + u * 16));
                STS128(h01, h23, h45, h67, tb + PH1_AH + sw);
                STS128(l01, l23, l45, l67, tb + PH1_AL + sw);
            }
        }
        // ---- B: 160 rows x 64 k, copy pre-split bf16 ----
#pragma unroll
        for (int t = 0; t < 3; t++) {
            int idx = tid + t * 512;
            if (idx < 1280) {
                int n = idx >> 3, u = idx & 7;
                long so = (long)n * 2304 + k0 + u * 8;
                uint4 vh = *(const uint4*)(g_wct_h + so);
                uint4 vl = *(const uint4*)(g_wct_l + so);
                uint32_t sw = SWZ((uint32_t)(n * 128 + u * 16));
                STS128(vh.x, vh.y, vh.z, vh.w, tb + PH1_BH + sw);
                STS128(vl.x, vl.y, vl.z, vl.w, tb + PH1_BL + sw);
            }
        }
    };

    stage(0);
    __syncthreads();

    for (int ch = 0; ch < 36; ch++) {
        if (ch < 35) stage(ch + 1);
        uint32_t tb = sb + (uint32_t)(ch & 1) * PH1_BUF;
#pragma unroll
        for (int ks = 0; ks < 4; ks++) {
            uint32_t Bh[5][2], Bl[5][2];
#pragma unroll
            for (int nt = 0; nt < 5; nt++) {
                int n = wn + nt * 8 + (lane & 7);
                uint32_t off = SWZ((uint32_t)(n * 128 + ks * 32 + ((lane >> 3) & 1) * 16));
                LDSM_X2(Bh[nt][0], Bh[nt][1], tb + PH1_BH + off);
                LDSM_X2(Bl[nt][0], Bl[nt][1], tb + PH1_BL + off);
            }
#pragma unroll
            for (int mt = 0; mt < 2; mt++) {
                int r = wm + mt * 16 + (lane & 15);
                uint32_t aoff = SWZ((uint32_t)(r * 128 + ks * 32 + (lane >> 4) * 16));
                uint32_t A0, A1, A2, A3;
                LDSM_X4(A0, A1, A2, A3, tb + PH1_AH + aoff);
#pragma unroll
                for (int nt = 0; nt < 5; nt++) {
                    MMA16816(acc[mt][nt], A0, A1, A2, A3, Bh[nt][0], Bh[nt][1]);
                    MMA16816(acc[mt][nt], A0, A1, A2, A3, Bl[nt][0], Bl[nt][1]);
                }
                LDSM_X4(A0, A1, A2, A3, tb + PH1_AL + aoff);
#pragma unroll
                for (int nt = 0; nt < 5; nt++)
                    MMA16816(acc[mt][nt], A0, A1, A2, A3, Bh[nt][0], Bh[nt][1]);
            }
        }
        __syncthreads();
    }

    // ---- epilogue: + hi + hj + b, relu, store ----
#pragma unroll
    for (int mt = 0; mt < 2; mt++) {
#pragma unroll
        for (int nt = 0; nt < 5; nt++) {
            int c = wn + nt * 8 + (lane & 3) * 2;
#pragma unroll
            for (int h = 0; h < 2; h++) {
                int i = ih * 128 + wm + mt * 16 + (lane >> 2) + h * 8;
                float o0 = 0.f, o1 = 0.f;
                if (c < 150) {
                    float base0 = hi_g[(long)i * 160 + c] + sHJ[c] + sB1[c];
                    o0 = fmaxf(acc[mt][nt][h * 2] + base0, 0.f);
                    if (c + 1 < 150) {
                        float base1 = hi_g[(long)i * 160 + c + 1] + sHJ[c + 1] + sB1[c + 1];
                        o1 = fmaxf(acc[mt][nt][h * 2 + 1] + base1, 0.f);
                    }
                }
                *(float2*)(h1p + ((long)i * 256 + j) * 160 + c) = make_float2(o0, o1);
            }
        }
    }
}

// ---------------- per-pair h2 GEMM + score + clip -----------------------
__global__ __launch_bounds__(256) void pair_out_kernel(
    const float* __restrict__ W2, const float* __restrict__ pb2,
    const float* __restrict__ w3, const float* __restrict__ pb3,
    float* __restrict__ out)
{
    __shared__ float sH1[32][160];
    __shared__ float sW2[32][160];
    __shared__ float sRed[32][16];

    const float* h1p = g_scratch + OFF_H1P;
    const float* m   = g_scratch + OFF_M;

    int tid = threadIdx.x;
    int pg = tid >> 4, hg = tid & 15;
    long p0 = (long)blockIdx.x * 32;

    {
        const float4* src = (const float4*)(h1p + p0 * 160);
        float4* dst = (float4*)&sH1[0][0];
#pragma unroll
        for (int i = 0; i < 5; i++) dst[tid + i * 256] = src[tid + i * 256];
    }

    float acc[2][10];
#pragma unroll
    for (int a = 0; a < 2; a++)
#pragma unroll
        for (int b = 0; b < 10; b++) acc[a][b] = 0.f;

    for (int kc = 0; kc < 5; kc++) {
        int kb = kc * 32;
#pragma unroll
        for (int i = 0; i < 20; i++) {
            int idx = tid + i * 256;
            int e = idx / 160, h = idx - e * 160;
            int kk = kb + e;
            sW2[e][h] = (kk < 150 && h < 150) ? W2[(long)kk * 150 + h] : 0.f;
        }
        __syncthreads();
#pragma unroll 8
        for (int e = 0; e < 32; e++) {
            float x0 = sH1[pg * 2][kb + e];
            float x1 = sH1[pg * 2 + 1][kb + e];
#pragma unroll
            for (int hh = 0; hh < 10; hh += 2) {
                float2 w = *(const float2*)&sW2[e][hg * 10 + hh];
                acc[0][hh]     += x0 * w.x;  acc[0][hh + 1] += x0 * w.y;
                acc[1][hh]     += x1 * w.x;  acc[1][hh + 1] += x1 * w.y;
            }
        }
        __syncthreads();
    }

#pragma unroll
    for (int pp = 0; pp < 2; pp++) {
        float sacc = 0.f;
#pragma unroll
        for (int hh = 0; hh < 10; hh++) {
            int h = hg * 10 + hh;
            if (h < 150) {
                float v = fmaxf(acc[pp][hh] + pb2[h], 0.f);
                sacc += v * w3[h];
            }
        }
        sRed[pg * 2 + pp][hg] = sacc;
    }
    __syncthreads();
    if (tid < 32) {
        float s = pb3[0];
#pragma unroll
        for (int h = 0; h < 16; h++) s += sRed[tid][h];
        long pr = p0 + tid;
        int i = (int)(pr >> 8), jj = (int)(pr & 255);
        float v = (m[i] + m[jj] + s) * (1.f / 3.f);
        v = fminf(fmaxf(v, 0.f), 1.f);
        out[pr] = v;
    }
}

// ---------------- launch ------------------------------------------------
extern "C" void kernel_launch(void* const* d_in, const int* in_sizes, int n_in,
                              void* d_out, int out_size)
{
    const float* e   = (const float*)d_in[0];
    const int*   sp  = (const int*)d_in[1];
    const int*   wd  = (const int*)d_in[2];
    const float* aW1 = (const float*)d_in[3];
    const float* ab1 = (const float*)d_in[4];
    const float* aW2 = (const float*)d_in[5];
    const float* ab2 = (const float*)d_in[6];
    const float* aW3 = (const float*)d_in[7];
    const float* ab3 = (const float*)d_in[8];
    const float* mW1 = (const float*)d_in[9];
    const float* mb1 = (const float*)d_in[10];
    const float* mW2 = (const float*)d_in[11];
    const float* mb2 = (const float*)d_in[12];
    const float* mW3 = (const float*)d_in[13];
    const float* mb3 = (const float*)d_in[14];
    const float* pW1 = (const float*)d_in[15];
    const float* pb1 = (const float*)d_in[16];
    const float* pW2 = (const float*)d_in[17];
    const float* pb2 = (const float*)d_in[18];
    const float* pW3 = (const float*)d_in[19];
    const float* pb3 = (const float*)d_in[20];
    float* out = (float*)d_out;

    cudaFuncSetAttribute(pair_h1_mma, cudaFuncAttributeMaxDynamicSharedMemorySize,
                         PH1_SMEM);

    // Wc transpose + bf16 split (independent)
    wct_split_kernel<<<1440, 256>>>(pW1 + 4608L * 150);

    // token MLP
    gemm150<1, 1><<<2048 / 64, 256>>>(e, 0, 768, aW1, ab1, OFF_H1TOK, 160, 2048, 768);
    gemm150<1, 1><<<2048 / 64, 256>>>(nullptr, OFF_H1TOK, 160, aW2, ab2, OFF_H2TOK, 160, 2048, 150);
    attn_we_kernel<<<2048, 256>>>(aW3, ab3, e);

    // span features
    gather_g_kernel<<<256, 256>>>(e, sp, wd);

    // m MLP
    gemm150<1, 1><<<256 / 64, 256>>>(nullptr, OFF_G, 2304, mW1, mb1, OFF_MH1, 160, 256, 2304);
    gemm150<1, 1><<<256 / 64, 256>>>(nullptr, OFF_MH1, 160, mW2, mb2, OFF_MH2, 160, 256, 150);
    rowdot_kernel<<<256, 256>>>(OFF_MH2, mW3, mb3, OFF_M);

    // hi = g @ Wa, hj = g @ Wb
    gemm150<0, 0><<<256 / 64, 256>>>(nullptr, OFF_G, 2304, pW1, nullptr, OFF_HI, 160, 256, 2304);
    gemm150<0, 0><<<256 / 64, 256>>>(nullptr, OFF_G, 2304, pW1 + 2304L * 150, nullptr, OFF_HJ, 160, 256, 2304);

    // pairwise h1 on tensor cores (mma.sync)
    pair_h1_mma<<<dim3(256, 2), 512, PH1_SMEM>>>(pb1);

    // pairwise output
    pair_out_kernel<<<65536 / 32, 256>>>(pW2, pb2, pW3, pb3, out);
}

// round 4
// speedup vs baseline: 2.1451x; 1.3278x over previous
#include <cuda_runtime.h>
#include <cuda_fp16.h>
#include <cstdint>

// Problem constants
#define TT 2048
#define EE 768
#define SSP 256
#define HHD 150
#define E3D 2304

// ---------------- scratch (device global, zero-init .bss) ----------------
static constexpr long OFF_H1TOK = 0;
static constexpr long OFF_H2TOK = OFF_H1TOK + 2048L * 160;
static constexpr long OFF_WE    = OFF_H2TOK + 2048L * 160;
static constexpr long OFF_G     = OFF_WE    + 2048L * 768;
static constexpr long OFF_MH1   = OFF_G     + 256L * 2304;
static constexpr long OFF_MH2   = OFF_MH1   + 256L * 160;
static constexpr long OFF_M     = OFF_MH2   + 256L * 160;
static constexpr long OFF_HI    = OFF_M     + 256L;
static constexpr long OFF_HJ    = OFF_HI    + 256L * 160;
static constexpr long OFF_HJB   = OFF_HJ    + 256L * 160;
static constexpr long OFF_H1P   = OFF_HJB   + 256L * 160;
static constexpr long SCRATCH_TOTAL = OFF_H1P + 65536L * 160;

__device__ __align__(16) float g_scratch[SCRATCH_TOTAL];

// Wc transposed, f16: [160 n][2304 k], n>=150 zero-padded
__device__ __align__(16) unsigned short g_wct[160L * 2304];

// ======================= helpers ==========================
__device__ __forceinline__ uint32_t smem_u32(const void* p) {
    uint32_t a;
    asm("{ .reg .u64 t; cvta.to.shared.u64 t, %1; cvt.u32.u64 %0, t; }"
        : "=r"(a) : "l"(p));
    return a;
}
#define SWZ(x) ((x) ^ (((x) >> 3) & 0x70))
#define STS128(a0, a1, a2, a3, addr) \
    asm volatile("st.shared.v4.b32 [%0], {%1,%2,%3,%4};" \
                 :: "r"(addr), "r"(a0), "r"(a1), "r"(a2), "r"(a3) : "memory")

// pack two f32 -> f16x2 (lo in low half)
__device__ __forceinline__ uint32_t pack_h2(float lo, float hi) {
    uint32_t d;
    asm("cvt.rn.f16x2.f32 %0, %1, %2;" : "=r"(d) : "f"(hi), "f"(lo));
    return d;
}
__device__ __forceinline__ float h2_lo(uint32_t w) {
    float f; asm("{ .reg .b16 l, h; mov.b32 {l, h}, %1; cvt.f32.f16 %0, l; }"
                 : "=f"(f) : "r"(w));
    return f;
}
__device__ __forceinline__ float h2_hi(uint32_t w) {
    float f; asm("{ .reg .b16 l, h; mov.b32 {l, h}, %1; cvt.f32.f16 %0, h; }"
                 : "=f"(f) : "r"(w));
    return f;
}

#define LDSM_X4(r0, r1, r2, r3, a) \
    asm volatile("ldmatrix.sync.aligned.m8n8.x4.shared.b16 {%0,%1,%2,%3}, [%4];" \
                 : "=r"(r0), "=r"(r1), "=r"(r2), "=r"(r3) : "r"(a))
#define LDSM_X2(r0, r1, a) \
    asm volatile("ldmatrix.sync.aligned.m8n8.x2.shared.b16 {%0,%1}, [%2];" \
                 : "=r"(r0), "=r"(r1) : "r"(a))
#define MMAF16(c, A0, A1, A2, A3, B0, B1) \
    asm volatile("mma.sync.aligned.m16n8k16.row.col.f32.f16.f16.f32 " \
                 "{%0,%1,%2,%3}, {%4,%5,%6,%7}, {%8,%9}, {%0,%1,%2,%3};" \
                 : "+f"((c)[0]), "+f"((c)[1]), "+f"((c)[2]), "+f"((c)[3]) \
                 : "r"(A0), "r"(A1), "r"(A2), "r"(A3), "r"(B0), "r"(B1))

// ---------------- generic GEMM: C[M,150] = act(A[M,K] @ W[K,150] + b) ----
template <int ACT, int HASBIAS>
__global__ __launch_bounds__(256) void gemm150(
    const float* __restrict__ Aext, long aOff, int lda,
    const float* __restrict__ W,
    const float* __restrict__ bias,
    long cOff, int ldc, int M, int K)
{
    const float* A = Aext ? Aext : (g_scratch + aOff);
    float* C = g_scratch + cOff;

    __shared__ float sA[16][68];
    __shared__ float sW[16][160];

    int tid = threadIdx.x;
    int rg = tid >> 4;
    int cg = tid & 15;
    int row0 = blockIdx.x * 64;

    float acc[4][10];
#pragma unroll
    for (int a = 0; a < 4; a++)
#pragma unroll
        for (int b = 0; b < 10; b++) acc[a][b] = 0.f;

    int nCh = (K + 15) >> 4;
    for (int ch = 0; ch < nCh; ch++) {
        int k0 = ch * 16;
        {
            int c = tid & 15, r = tid >> 4;
#pragma unroll
            for (int pass = 0; pass < 4; pass++) {
                int rl = pass * 16 + r;
                float v = 0.f;
                if (k0 + c < K) v = A[(long)(row0 + rl) * lda + k0 + c];
                sA[c][rl] = v;
            }
        }
#pragma unroll
        for (int i = 0; i < 10; i++) {
            int idx = tid + i * 256;
            int k = idx / 160, h = idx - k * 160;
            float v = 0.f;
            if (k0 + k < K && h < 150) v = W[(long)(k0 + k) * 150 + h];
            sW[k][h] = v;
        }
        __syncthreads();
#pragma unroll
        for (int k = 0; k < 16; k++) {
            float4 a4 = *(const float4*)&sA[k][rg * 4];
            float av0 = a4.x, av1 = a4.y, av2 = a4.z, av3 = a4.w;
#pragma unroll
            for (int hh = 0; hh < 10; hh += 2) {
                float2 w = *(const float2*)&sW[k][cg * 10 + hh];
                acc[0][hh]     += av0 * w.x;  acc[0][hh + 1] += av0 * w.y;
                acc[1][hh]     += av1 * w.x;  acc[1][hh + 1] += av1 * w.y;
                acc[2][hh]     += av2 * w.x;  acc[2][hh + 1] += av2 * w.y;
                acc[3][hh]     += av3 * w.x;  acc[3][hh + 1] += av3 * w.y;
            }
        }
        __syncthreads();
    }

#pragma unroll
    for (int rr = 0; rr < 4; rr++) {
        int row = row0 + rg * 4 + rr;
#pragma unroll
        for (int hh = 0; hh < 10; hh++) {
            int h = cg * 10 + hh;
            if (h < 150) {
                float v = acc[rr][hh];
                if (HASBIAS) v += bias[h];
                if (ACT) v = fmaxf(v, 0.f);
                C[(long)row * ldc + h] = v;
            }
        }
    }
}

// ---------------- attn = h2 . aW3 + b; we = e * attn -------------------
__global__ __launch_bounds__(256) void attn_we_kernel(
    const float* __restrict__ w3, const float* __restrict__ b3,
    const float* __restrict__ e)
{
    __shared__ float red[256];
    const float* h2 = g_scratch + OFF_H2TOK;
    float* we = g_scratch + OFF_WE;
    int t = blockIdx.x, tid = threadIdx.x;
    float v = 0.f;
    if (tid < 150) v = h2[(long)t * 160 + tid] * w3[tid];
    red[tid] = v;
    __syncthreads();
    for (int s = 128; s > 0; s >>= 1) {
        if (tid < s) red[tid] += red[tid + s];
        __syncthreads();
    }
    float attn = red[0] + b3[0];
#pragma unroll
    for (int i = 0; i < 3; i++) {
        int c = tid + i * 256;
        we[(long)t * 768 + c] = e[(long)t * 768 + c] * attn;
    }
}

// ---------------- row dot: out[r] = A[r,:150] . w + b -------------------
__global__ __launch_bounds__(256) void rowdot_kernel(
    long aOff, const float* __restrict__ w, const float* __restrict__ b,
    long oOff)
{
    __shared__ float red[256];
    const float* A = g_scratch + aOff;
    float* out = g_scratch + oOff;
    int r = blockIdx.x, tid = threadIdx.x;
    float v = 0.f;
    if (tid < 150) v = A[(long)r * 160 + tid] * w[tid];
    red[tid] = v;
    __syncthreads();
    for (int s = 128; s > 0; s >>= 1) {
        if (tid < s) red[tid] += red[tid + s];
        __syncthreads();
    }
    if (tid == 0) out[r] = red[0] + b[0];
}

// ---------------- g = [e_start | e_end | span_sum] ----------------------
__global__ __launch_bounds__(256) void gather_g_kernel(
    const float* __restrict__ e,
    const int* __restrict__ sp, const int* __restrict__ wd)
{
    const float* we = g_scratch + OFF_WE;
    float* g = g_scratch + OFF_G;
    int s = blockIdx.x, tid = threadIdx.x;
    int st = sp[s];
    int en = st + wd[s];
    if (en > TT - 1) en = TT - 1;
    if (en < 0) en = 0;
#pragma unroll
    for (int i = 0; i < 3; i++) {
        int c = tid + i * 256;
        g[(long)s * 2304 + c]        = e[(long)st * 768 + c];
        g[(long)s * 2304 + 768 + c]  = e[(long)en * 768 + c];
        float sum = 0.f;
        for (int t = st; t <= en; t++) sum += we[(long)t * 768 + c];
        g[(long)s * 2304 + 1536 + c] = sum;
    }
}

// ---------------- Wc -> transposed f16 ----------------------------------
__global__ __launch_bounds__(256) void wct_split_kernel(const float* __restrict__ Wc)
{
    long idx = (long)blockIdx.x * 256 + threadIdx.x;   // 0 .. 160*2304-1
    int n = (int)(idx / 2304);
    int k = (int)(idx - (long)n * 2304);
    float w = (n < 150) ? Wc[(long)k * 150 + n] : 0.f;
    __half h = __float2half_rn(w);
    g_wct[idx] = __half_as_ushort(h);
}

// ---------------- hjb[j][c] = hj[j][c] + pb1[c] (padded) ----------------
__global__ __launch_bounds__(160) void hjb_prep_kernel(const float* __restrict__ pb1)
{
    int j = blockIdx.x, c = threadIdx.x;
    const float* hj = g_scratch + OFF_HJ;
    float* hjb = g_scratch + OFF_HJB;
    float b = (c < 150) ? pb1[c] : 0.f;
    hjb[(long)j * 160 + c] = hj[(long)j * 160 + c] + b;
}

// ================= pair_h1: lower-triangle hij via f16 2-pass mma =======
// Grid (256 j, 2 ih). CTA computes rows i in [i0, i0+M) (i >= j at 16-row
// granularity), all 150 h, K=2304. 512 threads = 16 warps, 4m x 4n layout.
// A = X split into f16 hi/lo (exact pair), B = Wc^T in f16 (single).
// Stores RAW hij (no bias/relu) into h1p.
#define PH1_AH 0
#define PH1_AL 16384
#define PH1_B  32768
#define PH1_BUF 53248
#define PH1_SMEM (2 * PH1_BUF)

__global__ void __launch_bounds__(512, 1) pair_h1_mma()
{
    extern __shared__ __align__(1024) char smem[];
    uint32_t sb = smem_u32(smem);

    const float* g = g_scratch + OFF_G;
    float* h1p     = g_scratch + OFF_H1P;

    int tid  = threadIdx.x;
    int lane = tid & 31;
    int wid  = tid >> 5;
    int j    = blockIdx.x;
    int ih   = blockIdx.y;

    int fj = j & ~15;
    int i0, M;
    if (ih == 0) {
        if (j >= 128) return;
        i0 = fj; M = 128 - fj;
    } else {
        i0 = (fj > 128) ? fj : 128;
        M = 256 - i0;
    }

    int wm = (wid >> 2) * 32;        // m-tile (balanced across SMSPs)
    int wn = (wid & 3) * 40;         // n-tile

    float acc[2][5][4];
#pragma unroll
    for (int a = 0; a < 2; a++)
#pragma unroll
        for (int b = 0; b < 5; b++)
#pragma unroll
            for (int c = 0; c < 4; c++) acc[a][b][c] = 0.f;

    int arow = tid >> 2;              // local row 0..127
    int akq  = (tid & 3) * 16;        // k offset within chunk
    const float* gi_base = g + ((long)(i0 + arow)) * 2304 + akq;
    const float* gj_base = g + (long)j * 2304 + akq;

    auto stage = [&](int ch) {
        uint32_t tb = sb + (uint32_t)(ch & 1) * PH1_BUF;
        int k0 = ch * 64;
        // ---- A: X = gi*gj -> f16 hi/lo pair, swizzled ----
        if (arow < M) {
            const float4* gi4 = (const float4*)(gi_base + k0);
            const float4* gj4 = (const float4*)(gj_base + k0);
#pragma unroll
            for (int u = 0; u < 2; u++) {
                float4 a0 = gi4[u * 2], a1 = gi4[u * 2 + 1];
                float4 w0 = gj4[u * 2], w1 = gj4[u * 2 + 1];
                float p0 = a0.x * w0.x, p1 = a0.y * w0.y;
                float p2 = a0.z * w0.z, p3 = a0.w * w0.w;
                float p4 = a1.x * w1.x, p5 = a1.y * w1.y;
                float p6 = a1.z * w1.z, p7 = a1.w * w1.w;
                uint32_t h01 = pack_h2(p0, p1), h23 = pack_h2(p2, p3);
                uint32_t h45 = pack_h2(p4, p5), h67 = pack_h2(p6, p7);
                uint32_t l01 = pack_h2(p0 - h2_lo(h01), p1 - h2_hi(h01));
                uint32_t l23 = pack_h2(p2 - h2_lo(h23), p3 - h2_hi(h23));
                uint32_t l45 = pack_h2(p4 - h2_lo(h45), p5 - h2_hi(h45));
                uint32_t l67 = pack_h2(p6 - h2_lo(h67), p7 - h2_hi(h67));
                uint32_t sw = SWZ((uint32_t)(arow * 128 + akq * 2 + u * 16));
                STS128(h01, h23, h45, h67, tb + PH1_AH + sw);
                STS128(l01, l23, l45, l67, tb + PH1_AL + sw);
            }
        }
        // ---- B: 160 rows x 64 k f16 ----
#pragma unroll
        for (int t = 0; t < 3; t++) {
            int idx = tid + t * 512;
            if (idx < 1280) {
                int n = idx >> 3, u = idx & 7;
                uint4 v = *(const uint4*)(g_wct + (long)n * 2304 + k0 + u * 8);
                uint32_t sw = SWZ((uint32_t)(n * 128 + u * 16));
                STS128(v.x, v.y, v.z, v.w, tb + PH1_B + sw);
            }
        }
    };

    stage(0);
    __syncthreads();

    for (int ch = 0; ch < 36; ch++) {
        if (ch < 35) stage(ch + 1);
        uint32_t tb = sb + (uint32_t)(ch & 1) * PH1_BUF;
        if (wm < M) {
#pragma unroll
            for (int ks = 0; ks < 4; ks++) {
                uint32_t Bf[5][2];
                // nts 0,1 via x4
                {
                    int m = lane >> 3;
                    int n = wn + (m >> 1) * 8 + (lane & 7);
                    uint32_t off = SWZ((uint32_t)(n * 128 + ks * 32 + (m & 1) * 16));
                    LDSM_X4(Bf[0][0], Bf[0][1], Bf[1][0], Bf[1][1], tb + PH1_B + off);
                }
                // nts 2,3 via x4
                {
                    int m = lane >> 3;
                    int n = wn + 16 + (m >> 1) * 8 + (lane & 7);
                    uint32_t off = SWZ((uint32_t)(n * 128 + ks * 32 + (m & 1) * 16));
                    LDSM_X4(Bf[2][0], Bf[2][1], Bf[3][0], Bf[3][1], tb + PH1_B + off);
                }
                // nt 4 via x2
                {
                    int n = wn + 32 + (lane & 7);
                    uint32_t off = SWZ((uint32_t)(n * 128 + ks * 32 + ((lane >> 3) & 1) * 16));
                    LDSM_X2(Bf[4][0], Bf[4][1], tb + PH1_B + off);
                }
#pragma unroll
                for (int mt = 0; mt < 2; mt++) {
                    if (wm + mt * 16 >= M) continue;
                    int r = wm + mt * 16 + (lane & 15);
                    uint32_t aoff = SWZ((uint32_t)(r * 128 + ks * 32 + (lane >> 4) * 16));
                    uint32_t A0, A1, A2, A3;
                    LDSM_X4(A0, A1, A2, A3, tb + PH1_AH + aoff);
#pragma unroll
                    for (int nt = 0; nt < 5; nt++)
                        MMAF16(acc[mt][nt], A0, A1, A2, A3, Bf[nt][0], Bf[nt][1]);
                    LDSM_X4(A0, A1, A2, A3, tb + PH1_AL + aoff);
#pragma unroll
                    for (int nt = 0; nt < 5; nt++)
                        MMAF16(acc[mt][nt], A0, A1, A2, A3, Bf[nt][0], Bf[nt][1]);
                }
            }
        }
        __syncthreads();
    }

    // ---- epilogue: store RAW hij ----
    if (wm < M) {
#pragma unroll
        for (int mt = 0; mt < 2; mt++) {
            if (wm + mt * 16 >= M) continue;
#pragma unroll
            for (int nt = 0; nt < 5; nt++) {
                int c = wn + nt * 8 + (lane & 3) * 2;
#pragma unroll
                for (int h = 0; h < 2; h++) {
                    int i = i0 + wm + mt * 16 + (lane >> 2) + h * 8;
                    *(float2*)(h1p + ((long)i * 256 + j) * 160 + c) =
                        make_float2(acc[mt][nt][h * 2], acc[mt][nt][h * 2 + 1]);
                }
            }
        }
    }
}

// ---------------- per-pair: h1 assemble + h2 GEMM + score + clip --------
__global__ __launch_bounds__(256) void pair_out_kernel(
    const float* __restrict__ W2, const float* __restrict__ pb2,
    const float* __restrict__ w3, const float* __restrict__ pb3,
    float* __restrict__ out)
{
    __shared__ float sH1[32][160];
    __shared__ float sW2[32][160];
    __shared__ float sRed[32][16];

    const float* h1p = g_scratch + OFF_H1P;
    const float* m   = g_scratch + OFF_M;
    const float* hi  = g_scratch + OFF_HI;
    const float* hjb = g_scratch + OFF_HJB;

    int tid = threadIdx.x;
    int pg = tid >> 4, hg = tid & 15;
    long p0 = (long)blockIdx.x * 32;
    int i_fix = (int)(p0 >> 8);
    int j0 = (int)(p0 & 255);

    // assemble h1 = relu(hij + hi_i + hj_j + b); mirror read for i<j
    {
        int r = tid >> 3, q = tid & 7;
        int j = j0 + r;
        long src = (j <= i_fix) ? ((long)i_fix * 256 + j) : ((long)j * 256 + i_fix);
        const float4* s4 = (const float4*)(h1p + src * 160);
        const float4* hi4 = (const float4*)(hi + (long)i_fix * 160);
        const float4* hb4 = (const float4*)(hjb + (long)j * 160);
        float4* d4 = (float4*)&sH1[r][0];
#pragma unroll
        for (int v = 0; v < 5; v++) {
            int idx = q + v * 8;
            float4 a = s4[idx], b = hi4[idx], c = hb4[idx];
            float4 o;
            o.x = fmaxf(a.x + b.x + c.x, 0.f);
            o.y = fmaxf(a.y + b.y + c.y, 0.f);
            o.z = fmaxf(a.z + b.z + c.z, 0.f);
            o.w = fmaxf(a.w + b.w + c.w, 0.f);
            d4[idx] = o;
        }
    }

    float acc[2][10];
#pragma unroll
    for (int a = 0; a < 2; a++)
#pragma unroll
        for (int b = 0; b < 10; b++) acc[a][b] = 0.f;

    for (int kc = 0; kc < 5; kc++) {
        int kb = kc * 32;
#pragma unroll
        for (int i = 0; i < 20; i++) {
            int idx = tid + i * 256;
            int e = idx / 160, h = idx - e * 160;
            int kk = kb + e;
            sW2[e][h] = (kk < 150 && h < 150) ? W2[(long)kk * 150 + h] : 0.f;
        }
        __syncthreads();
#pragma unroll 8
        for (int e = 0; e < 32; e++) {
            float x0 = sH1[pg * 2][kb + e];
            float x1 = sH1[pg * 2 + 1][kb + e];
#pragma unroll
            for (int hh = 0; hh < 10; hh += 2) {
                float2 w = *(const float2*)&sW2[e][hg * 10 + hh];
                acc[0][hh]     += x0 * w.x;  acc[0][hh + 1] += x0 * w.y;
                acc[1][hh]     += x1 * w.x;  acc[1][hh + 1] += x1 * w.y;
            }
        }
        __syncthreads();
    }

#pragma unroll
    for (int pp = 0; pp < 2; pp++) {
        float sacc = 0.f;
#pragma unroll
        for (int hh = 0; hh < 10; hh++) {
            int h = hg * 10 + hh;
            if (h < 150) {
                float v = fmaxf(acc[pp][hh] + pb2[h], 0.f);
                sacc += v * w3[h];
            }
        }
        sRed[pg * 2 + pp][hg] = sacc;
    }
    __syncthreads();
    if (tid < 32) {
        float s = pb3[0];
#pragma unroll
        for (int h = 0; h < 16; h++) s += sRed[tid][h];
        long pr = p0 + tid;
        int i = (int)(pr >> 8), jj = (int)(pr & 255);
        float v = (m[i] + m[jj] + s) * (1.f / 3.f);
        v = fminf(fmaxf(v, 0.f), 1.f);
        out[pr] = v;
    }
}

// ---------------- launch ------------------------------------------------
extern "C" void kernel_launch(void* const* d_in, const int* in_sizes, int n_in,
                              void* d_out, int out_size)
{
    const float* e   = (const float*)d_in[0];
    const int*   sp  = (const int*)d_in[1];
    const int*   wd  = (const int*)d_in[2];
    const float* aW1 = (const float*)d_in[3];
    const float* ab1 = (const float*)d_in[4];
    const float* aW2 = (const float*)d_in[5];
    const float* ab2 = (const float*)d_in[6];
    const float* aW3 = (const float*)d_in[7];
    const float* ab3 = (const float*)d_in[8];
    const float* mW1 = (const float*)d_in[9];
    const float* mb1 = (const float*)d_in[10];
    const float* mW2 = (const float*)d_in[11];
    const float* mb2 = (const float*)d_in[12];
    const float* mW3 = (const float*)d_in[13];
    const float* mb3 = (const float*)d_in[14];
    const float* pW1 = (const float*)d_in[15];
    const float* pb1 = (const float*)d_in[16];
    const float* pW2 = (const float*)d_in[17];
    const float* pb2 = (const float*)d_in[18];
    const float* pW3 = (const float*)d_in[19];
    const float* pb3 = (const float*)d_in[20];
    float* out = (float*)d_out;

    cudaFuncSetAttribute(pair_h1_mma, cudaFuncAttributeMaxDynamicSharedMemorySize,
                         PH1_SMEM);

    // Wc transpose -> f16 (independent)
    wct_split_kernel<<<1440, 256>>>(pW1 + 4608L * 150);

    // token MLP
    gemm150<1, 1><<<2048 / 64, 256>>>(e, 0, 768, aW1, ab1, OFF_H1TOK, 160, 2048, 768);
    gemm150<1, 1><<<2048 / 64, 256>>>(nullptr, OFF_H1TOK, 160, aW2, ab2, OFF_H2TOK, 160, 2048, 150);
    attn_we_kernel<<<2048, 256>>>(aW3, ab3, e);

    // span features
    gather_g_kernel<<<256, 256>>>(e, sp, wd);

    // m MLP
    gemm150<1, 1><<<256 / 64, 256>>>(nullptr, OFF_G, 2304, mW1, mb1, OFF_MH1, 160, 256, 2304);
    gemm150<1, 1><<<256 / 64, 256>>>(nullptr, OFF_MH1, 160, mW2, mb2, OFF_MH2, 160, 256, 150);
    rowdot_kernel<<<256, 256>>>(OFF_MH2, mW3, mb3, OFF_M);

    // hi = g @ Wa, hj = g @ Wb, hjb = hj + pb1
    gemm150<0, 0><<<256 / 64, 256>>>(nullptr, OFF_G, 2304, pW1, nullptr, OFF_HI, 160, 256, 2304);
    gemm150<0, 0><<<256 / 64, 256>>>(nullptr, OFF_G, 2304, pW1 + 2304L * 150, nullptr, OFF_HJ, 160, 256, 2304);
    hjb_prep_kernel<<<256, 160>>>(pb1);

    // lower-triangle hij on tensor cores (f16 2-pass)
    pair_h1_mma<<<dim3(256, 2), 512, PH1_SMEM>>>();

    // pairwise output (handles mirror + bias + relu)
    pair_out_kernel<<<65536 / 32, 256>>>(pW2, pb2, pW3, pb3, out);
}

// round 5
// speedup vs baseline: 2.2162x; 1.0332x over previous
#include <cuda_runtime.h>
#include <cuda_fp16.h>
#include <cstdint>

// Problem constants
#define TT 2048
#define EE 768
#define SSP 256
#define HHD 150
#define E3D 2304

// ---------------- scratch (device global, zero-init .bss) ----------------
static constexpr long OFF_H1TOK = 0;
static constexpr long OFF_H2TOK = OFF_H1TOK + 2048L * 160;
static constexpr long OFF_WE    = OFF_H2TOK + 2048L * 160;
static constexpr long OFF_G     = OFF_WE    + 2048L * 768;
static constexpr long OFF_MH1   = OFF_G     + 256L * 2304;
static constexpr long OFF_MH2   = OFF_MH1   + 256L * 160;
static constexpr long OFF_M     = OFF_MH2   + 256L * 160;
static constexpr long OFF_HI    = OFF_M     + 256L;
static constexpr long OFF_HJ    = OFF_HI    + 256L * 160;
static constexpr long OFF_HJB   = OFF_HJ    + 256L * 160;
static constexpr long OFF_H1P   = OFF_HJB   + 256L * 160;
static constexpr long SCRATCH_TOTAL = OFF_H1P + 65536L * 160;

__device__ __align__(16) float g_scratch[SCRATCH_TOTAL];

// Wc transposed, f16: [160 n][2304 k], n>=150 zero-padded
__device__ __align__(16) unsigned short g_wct[160L * 2304];

// ======================= helpers ==========================
__device__ __forceinline__ uint32_t smem_u32(const void* p) {
    uint32_t a;
    asm("{ .reg .u64 t; cvta.to.shared.u64 t, %1; cvt.u32.u64 %0, t; }"
        : "=r"(a) : "l"(p));
    return a;
}
#define SWZ(x) ((x) ^ (((x) >> 3) & 0x70))
#define STS128(a0, a1, a2, a3, addr) \
    asm volatile("st.shared.v4.b32 [%0], {%1,%2,%3,%4};" \
                 :: "r"(addr), "r"(a0), "r"(a1), "r"(a2), "r"(a3) : "memory")

// pack two f32 -> f16x2 (lo in low half)
__device__ __forceinline__ uint32_t pack_h2(float lo, float hi) {
    uint32_t d;
    asm("cvt.rn.f16x2.f32 %0, %1, %2;" : "=r"(d) : "f"(hi), "f"(lo));
    return d;
}

#define LDSM_X4(r0, r1, r2, r3, a) \
    asm volatile("ldmatrix.sync.aligned.m8n8.x4.shared.b16 {%0,%1,%2,%3}, [%4];" \
                 : "=r"(r0), "=r"(r1), "=r"(r2), "=r"(r3) : "r"(a))
#define LDSM_X2(r0, r1, a) \
    asm volatile("ldmatrix.sync.aligned.m8n8.x2.shared.b16 {%0,%1}, [%2];" \
                 : "=r"(r0), "=r"(r1) : "r"(a))
#define MMAF16(c, A0, A1, A2, A3, B0, B1) \
    asm volatile("mma.sync.aligned.m16n8k16.row.col.f32.f16.f16.f32 " \
                 "{%0,%1,%2,%3}, {%4,%5,%6,%7}, {%8,%9}, {%0,%1,%2,%3};" \
                 : "+f"((c)[0]), "+f"((c)[1]), "+f"((c)[2]), "+f"((c)[3]) \
                 : "r"(A0), "r"(A1), "r"(A2), "r"(A3), "r"(B0), "r"(B1))

// ---------------- generic GEMM: C[M,150] = act(A[M,K] @ W[K,150] + b) ----
template <int ACT, int HASBIAS>
__global__ __launch_bounds__(256) void gemm150(
    const float* __restrict__ Aext, long aOff, int lda,
    const float* __restrict__ W,
    const float* __restrict__ bias,
    long cOff, int ldc, int M, int K)
{
    const float* A = Aext ? Aext : (g_scratch + aOff);
    float* C = g_scratch + cOff;

    __shared__ float sA[16][68];
    __shared__ float sW[16][160];

    int tid = threadIdx.x;
    int rg = tid >> 4;
    int cg = tid & 15;
    int row0 = blockIdx.x * 64;

    float acc[4][10];
#pragma unroll
    for (int a = 0; a < 4; a++)
#pragma unroll
        for (int b = 0; b < 10; b++) acc[a][b] = 0.f;

    int nCh = (K + 15) >> 4;
    for (int ch = 0; ch < nCh; ch++) {
        int k0 = ch * 16;
        {
            int c = tid & 15, r = tid >> 4;
#pragma unroll
            for (int pass = 0; pass < 4; pass++) {
                int rl = pass * 16 + r;
                float v = 0.f;
                if (k0 + c < K) v = A[(long)(row0 + rl) * lda + k0 + c];
                sA[c][rl] = v;
            }
        }
#pragma unroll
        for (int i = 0; i < 10; i++) {
            int idx = tid + i * 256;
            int k = idx / 160, h = idx - k * 160;
            float v = 0.f;
            if (k0 + k < K && h < 150) v = W[(long)(k0 + k) * 150 + h];
            sW[k][h] = v;
        }
        __syncthreads();
#pragma unroll
        for (int k = 0; k < 16; k++) {
            float4 a4 = *(const float4*)&sA[k][rg * 4];
            float av0 = a4.x, av1 = a4.y, av2 = a4.z, av3 = a4.w;
#pragma unroll
            for (int hh = 0; hh < 10; hh += 2) {
                float2 w = *(const float2*)&sW[k][cg * 10 + hh];
                acc[0][hh]     += av0 * w.x;  acc[0][hh + 1] += av0 * w.y;
                acc[1][hh]     += av1 * w.x;  acc[1][hh + 1] += av1 * w.y;
                acc[2][hh]     += av2 * w.x;  acc[2][hh + 1] += av2 * w.y;
                acc[3][hh]     += av3 * w.x;  acc[3][hh + 1] += av3 * w.y;
            }
        }
        __syncthreads();
    }

#pragma unroll
    for (int rr = 0; rr < 4; rr++) {
        int row = row0 + rg * 4 + rr;
#pragma unroll
        for (int hh = 0; hh < 10; hh++) {
            int h = cg * 10 + hh;
            if (h < 150) {
                float v = acc[rr][hh];
                if (HASBIAS) v += bias[h];
                if (ACT) v = fmaxf(v, 0.f);
                C[(long)row * ldc + h] = v;
            }
        }
    }
}

// ---------------- attn = h2 . aW3 + b; we = e * attn -------------------
__global__ __launch_bounds__(256) void attn_we_kernel(
    const float* __restrict__ w3, const float* __restrict__ b3,
    const float* __restrict__ e)
{
    __shared__ float red[256];
    const float* h2 = g_scratch + OFF_H2TOK;
    float* we = g_scratch + OFF_WE;
    int t = blockIdx.x, tid = threadIdx.x;
    float v = 0.f;
    if (tid < 150) v = h2[(long)t * 160 + tid] * w3[tid];
    red[tid] = v;
    __syncthreads();
    for (int s = 128; s > 0; s >>= 1) {
        if (tid < s) red[tid] += red[tid + s];
        __syncthreads();
    }
    float attn = red[0] + b3[0];
#pragma unroll
    for (int i = 0; i < 3; i++) {
        int c = tid + i * 256;
        we[(long)t * 768 + c] = e[(long)t * 768 + c] * attn;
    }
}

// ---------------- row dot: out[r] = A[r,:150] . w + b -------------------
__global__ __launch_bounds__(256) void rowdot_kernel(
    long aOff, const float* __restrict__ w, const float* __restrict__ b,
    long oOff)
{
    __shared__ float red[256];
    const float* A = g_scratch + aOff;
    float* out = g_scratch + oOff;
    int r = blockIdx.x, tid = threadIdx.x;
    float v = 0.f;
    if (tid < 150) v = A[(long)r * 160 + tid] * w[tid];
    red[tid] = v;
    __syncthreads();
    for (int s = 128; s > 0; s >>= 1) {
        if (tid < s) red[tid] += red[tid + s];
        __syncthreads();
    }
    if (tid == 0) out[r] = red[0] + b[0];
}

// ---------------- g = [e_start | e_end | span_sum] ----------------------
__global__ __launch_bounds__(256) void gather_g_kernel(
    const float* __restrict__ e,
    const int* __restrict__ sp, const int* __restrict__ wd)
{
    const float* we = g_scratch + OFF_WE;
    float* g = g_scratch + OFF_G;
    int s = blockIdx.x, tid = threadIdx.x;
    int st = sp[s];
    int en = st + wd[s];
    if (en > TT - 1) en = TT - 1;
    if (en < 0) en = 0;
#pragma unroll
    for (int i = 0; i < 3; i++) {
        int c = tid + i * 256;
        g[(long)s * 2304 + c]        = e[(long)st * 768 + c];
        g[(long)s * 2304 + 768 + c]  = e[(long)en * 768 + c];
        float sum = 0.f;
        for (int t = st; t <= en; t++) sum += we[(long)t * 768 + c];
        g[(long)s * 2304 + 1536 + c] = sum;
    }
}

// ---------------- Wc -> transposed f16 ----------------------------------
__global__ __launch_bounds__(256) void wct_split_kernel(const float* __restrict__ Wc)
{
    long idx = (long)blockIdx.x * 256 + threadIdx.x;   // 0 .. 160*2304-1
    int n = (int)(idx / 2304);
    int k = (int)(idx - (long)n * 2304);
    float w = (n < 150) ? Wc[(long)k * 150 + n] : 0.f;
    __half h = __float2half_rn(w);
    g_wct[idx] = __half_as_ushort(h);
}

// ---------------- hjb[j][c] = hj[j][c] + pb1[c] (padded) ----------------
__global__ __launch_bounds__(160) void hjb_prep_kernel(const float* __restrict__ pb1)
{
    int j = blockIdx.x, c = threadIdx.x;
    const float* hj = g_scratch + OFF_HJ;
    float* hjb = g_scratch + OFF_HJB;
    float b = (c < 150) ? pb1[c] : 0.f;
    hjb[(long)j * 160 + c] = hj[(long)j * 160 + c] + b;
}

// ================= pair_h1: lower-triangle hij via f16 1-pass mma =======
// Grid (256 j, 4 ib). CTA: rows i in [i0, i0+M), M<=64, i0 = fj + ib*64.
// 256 threads = 8 warps in 2(m) x 4(n) layout; warp tile 32x40.
// K chunks of 64, double buffered. A = X rounded f16, B = Wc^T f16.
// Stores RAW hij into h1p.
#define PH1_A 0
#define PH1_B 8192
#define PH1_BUF 28672
#define PH1_SMEM (2 * PH1_BUF)

__global__ void __launch_bounds__(256, 2) pair_h1_mma()
{
    extern __shared__ __align__(1024) char smem[];
    uint32_t sb = smem_u32(smem);

    const float* g = g_scratch + OFF_G;
    float* h1p     = g_scratch + OFF_H1P;

    int tid  = threadIdx.x;
    int lane = tid & 31;
    int wid  = tid >> 5;
    int j    = blockIdx.x;
    int ib   = blockIdx.y;

    int fj = j & ~15;
    int i0 = fj + ib * 64;
    if (i0 >= 256) return;
    int M = 256 - i0;
    if (M > 64) M = 64;

    int wm = (wid >> 2) * 32;        // m-tile
    int wn = (wid & 3) * 40;         // n-tile

    float acc[2][5][4];
#pragma unroll
    for (int a = 0; a < 2; a++)
#pragma unroll
        for (int b = 0; b < 5; b++)
#pragma unroll
            for (int c = 0; c < 4; c++) acc[a][b][c] = 0.f;

    int arow = tid >> 2;              // local row 0..63
    int akq  = (tid & 3) * 16;        // k offset within chunk
    const float* gi_base = g + ((long)(i0 + arow)) * 2304 + akq;
    const float* gj_base = g + (long)j * 2304 + akq;

    auto stage = [&](int ch) {
        uint32_t tb = sb + (uint32_t)(ch & 1) * PH1_BUF;
        int k0 = ch * 64;
        // ---- A: X = gi*gj -> f16, swizzled ----
        if (arow < M) {
            const float4* gi4 = (const float4*)(gi_base + k0);
            const float4* gj4 = (const float4*)(gj_base + k0);
#pragma unroll
            for (int u = 0; u < 2; u++) {
                float4 a0 = gi4[u * 2], a1 = gi4[u * 2 + 1];
                float4 w0 = gj4[u * 2], w1 = gj4[u * 2 + 1];
                uint32_t h01 = pack_h2(a0.x * w0.x, a0.y * w0.y);
                uint32_t h23 = pack_h2(a0.z * w0.z, a0.w * w0.w);
                uint32_t h45 = pack_h2(a1.x * w1.x, a1.y * w1.y);
                uint32_t h67 = pack_h2(a1.z * w1.z, a1.w * w1.w);
                uint32_t sw = SWZ((uint32_t)(arow * 128 + akq * 2 + u * 16));
                STS128(h01, h23, h45, h67, tb + PH1_A + sw);
            }
        }
        // ---- B: 160 rows x 64 k f16 ----
#pragma unroll
        for (int t = 0; t < 5; t++) {
            int idx = tid + t * 256;
            int n = idx >> 3, u = idx & 7;
            uint4 v = *(const uint4*)(g_wct + (long)n * 2304 + k0 + u * 8);
            uint32_t sw = SWZ((uint32_t)(n * 128 + u * 16));
            STS128(v.x, v.y, v.z, v.w, tb + PH1_B + sw);
        }
    };

    stage(0);
    __syncthreads();

    for (int ch = 0; ch < 36; ch++) {
        if (ch < 35) stage(ch + 1);
        uint32_t tb = sb + (uint32_t)(ch & 1) * PH1_BUF;
        if (wm < M) {
#pragma unroll
            for (int ks = 0; ks < 4; ks++) {
                uint32_t Bf[5][2];
                {
                    int m = lane >> 3;
                    int n = wn + (m >> 1) * 8 + (lane & 7);
                    uint32_t off = SWZ((uint32_t)(n * 128 + ks * 32 + (m & 1) * 16));
                    LDSM_X4(Bf[0][0], Bf[0][1], Bf[1][0], Bf[1][1], tb + PH1_B + off);
                }
                {
                    int m = lane >> 3;
                    int n = wn + 16 + (m >> 1) * 8 + (lane & 7);
                    uint32_t off = SWZ((uint32_t)(n * 128 + ks * 32 + (m & 1) * 16));
                    LDSM_X4(Bf[2][0], Bf[2][1], Bf[3][0], Bf[3][1], tb + PH1_B + off);
                }
                {
                    int n = wn + 32 + (lane & 7);
                    uint32_t off = SWZ((uint32_t)(n * 128 + ks * 32 + ((lane >> 3) & 1) * 16));
                    LDSM_X2(Bf[4][0], Bf[4][1], tb + PH1_B + off);
                }
#pragma unroll
                for (int mt = 0; mt < 2; mt++) {
                    if (wm + mt * 16 >= M) continue;
                    int r = wm + mt * 16 + (lane & 15);
                    uint32_t aoff = SWZ((uint32_t)(r * 128 + ks * 32 + (lane >> 4) * 16));
                    uint32_t A0, A1, A2, A3;
                    LDSM_X4(A0, A1, A2, A3, tb + PH1_A + aoff);
#pragma unroll
                    for (int nt = 0; nt < 5; nt++)
                        MMAF16(acc[mt][nt], A0, A1, A2, A3, Bf[nt][0], Bf[nt][1]);
                }
            }
        }
        __syncthreads();
    }

    // ---- epilogue: store RAW hij ----
    if (wm < M) {
#pragma unroll
        for (int mt = 0; mt < 2; mt++) {
            if (wm + mt * 16 >= M) continue;
#pragma unroll
            for (int nt = 0; nt < 5; nt++) {
                int c = wn + nt * 8 + (lane & 3) * 2;
#pragma unroll
                for (int h = 0; h < 2; h++) {
                    int i = i0 + wm + mt * 16 + (lane >> 2) + h * 8;
                    *(float2*)(h1p + ((long)i * 256 + j) * 160 + c) =
                        make_float2(acc[mt][nt][h * 2], acc[mt][nt][h * 2 + 1]);
                }
            }
        }
    }
}

// ---------------- per-pair: h1 assemble + h2 GEMM + score + clip --------
__global__ __launch_bounds__(256) void pair_out_kernel(
    const float* __restrict__ W2, const float* __restrict__ pb2,
    const float* __restrict__ w3, const float* __restrict__ pb3,
    float* __restrict__ out)
{
    __shared__ float sH1[32][160];
    __shared__ float sW2[32][160];
    __shared__ float sRed[32][16];

    const float* h1p = g_scratch + OFF_H1P;
    const float* m   = g_scratch + OFF_M;
    const float* hi  = g_scratch + OFF_HI;
    const float* hjb = g_scratch + OFF_HJB;

    int tid = threadIdx.x;
    int pg = tid >> 4, hg = tid & 15;
    long p0 = (long)blockIdx.x * 32;
    int i_fix = (int)(p0 >> 8);
    int j0 = (int)(p0 & 255);

    // assemble h1 = relu(hij + hi_i + hj_j + b); mirror read for i<j
    {
        int r = tid >> 3, q = tid & 7;
        int j = j0 + r;
        long src = (j <= i_fix) ? ((long)i_fix * 256 + j) : ((long)j * 256 + i_fix);
        const float4* s4 = (const float4*)(h1p + src * 160);
        const float4* hi4 = (const float4*)(hi + (long)i_fix * 160);
        const float4* hb4 = (const float4*)(hjb + (long)j * 160);
        float4* d4 = (float4*)&sH1[r][0];
#pragma unroll
        for (int v = 0; v < 5; v++) {
            int idx = q + v * 8;
            float4 a = s4[idx], b = hi4[idx], c = hb4[idx];
            float4 o;
            o.x = fmaxf(a.x + b.x + c.x, 0.f);
            o.y = fmaxf(a.y + b.y + c.y, 0.f);
            o.z = fmaxf(a.z + b.z + c.z, 0.f);
            o.w = fmaxf(a.w + b.w + c.w, 0.f);
            d4[idx] = o;
        }
    }

    float acc[2][10];
#pragma unroll
    for (int a = 0; a < 2; a++)
#pragma unroll
        for (int b = 0; b < 10; b++) acc[a][b] = 0.f;

    for (int kc = 0; kc < 5; kc++) {
        int kb = kc * 32;
#pragma unroll
        for (int i = 0; i < 20; i++) {
            int idx = tid + i * 256;
            int e = idx / 160, h = idx - e * 160;
            int kk = kb + e;
            sW2[e][h] = (kk < 150 && h < 150) ? W2[(long)kk * 150 + h] : 0.f;
        }
        __syncthreads();
#pragma unroll 8
        for (int e = 0; e < 32; e++) {
            float x0 = sH1[pg * 2][kb + e];
            float x1 = sH1[pg * 2 + 1][kb + e];
#pragma unroll
            for (int hh = 0; hh < 10; hh += 2) {
                float2 w = *(const float2*)&sW2[e][hg * 10 + hh];
                acc[0][hh]     += x0 * w.x;  acc[0][hh + 1] += x0 * w.y;
                acc[1][hh]     += x1 * w.x;  acc[1][hh + 1] += x1 * w.y;
            }
        }
        __syncthreads();
    }

#pragma unroll
    for (int pp = 0; pp < 2; pp++) {
        float sacc = 0.f;
#pragma unroll
        for (int hh = 0; hh < 10; hh++) {
            int h = hg * 10 + hh;
            if (h < 150) {
                float v = fmaxf(acc[pp][hh] + pb2[h], 0.f);
                sacc += v * w3[h];
            }
        }
        sRed[pg * 2 + pp][hg] = sacc;
    }
    __syncthreads();
    if (tid < 32) {
        float s = pb3[0];
#pragma unroll
        for (int h = 0; h < 16; h++) s += sRed[tid][h];
        long pr = p0 + tid;
        int i = (int)(pr >> 8), jj = (int)(pr & 255);
        float v = (m[i] + m[jj] + s) * (1.f / 3.f);
        v = fminf(fmaxf(v, 0.f), 1.f);
        out[pr] = v;
    }
}

// ---------------- launch ------------------------------------------------
extern "C" void kernel_launch(void* const* d_in, const int* in_sizes, int n_in,
                              void* d_out, int out_size)
{
    const float* e   = (const float*)d_in[0];
    const int*   sp  = (const int*)d_in[1];
    const int*   wd  = (const int*)d_in[2];
    const float* aW1 = (const float*)d_in[3];
    const float* ab1 = (const float*)d_in[4];
    const float* aW2 = (const float*)d_in[5];
    const float* ab2 = (const float*)d_in[6];
    const float* aW3 = (const float*)d_in[7];
    const float* ab3 = (const float*)d_in[8];
    const float* mW1 = (const float*)d_in[9];
    const float* mb1 = (const float*)d_in[10];
    const float* mW2 = (const float*)d_in[11];
    const float* mb2 = (const float*)d_in[12];
    const float* mW3 = (const float*)d_in[13];
    const float* mb3 = (const float*)d_in[14];
    const float* pW1 = (const float*)d_in[15];
    const float* pb1 = (const float*)d_in[16];
    const float* pW2 = (const float*)d_in[17];
    const float* pb2 = (const float*)d_in[18];
    const float* pW3 = (const float*)d_in[19];
    const float* pb3 = (const float*)d_in[20];
    float* out = (float*)d_out;

    cudaFuncSetAttribute(pair_h1_mma, cudaFuncAttributeMaxDynamicSharedMemorySize,
                         PH1_SMEM);

    // launches 0..4: prerequisites of pair_h1 (so ncu -s 5 lands on it)
    wct_split_kernel<<<1440, 256>>>(pW1 + 4608L * 150);
    gemm150<1, 1><<<2048 / 64, 256>>>(e, 0, 768, aW1, ab1, OFF_H1TOK, 160, 2048, 768);
    gemm150<1, 1><<<2048 / 64, 256>>>(nullptr, OFF_H1TOK, 160, aW2, ab2, OFF_H2TOK, 160, 2048, 150);
    attn_we_kernel<<<2048, 256>>>(aW3, ab3, e);
    gather_g_kernel<<<256, 256>>>(e, sp, wd);

    // launch 5: the dominant kernel — lower-triangle hij (f16 1-pass)
    pair_h1_mma<<<dim3(256, 4), 256, PH1_SMEM>>>();

    // m MLP
    gemm150<1, 1><<<256 / 64, 256>>>(nullptr, OFF_G, 2304, mW1, mb1, OFF_MH1, 160, 256, 2304);
    gemm150<1, 1><<<256 / 64, 256>>>(nullptr, OFF_MH1, 160, mW2, mb2, OFF_MH2, 160, 256, 150);
    rowdot_kernel<<<256, 256>>>(OFF_MH2, mW3, mb3, OFF_M);

    // hi = g @ Wa, hj = g @ Wb, hjb = hj + pb1
    gemm150<0, 0><<<256 / 64, 256>>>(nullptr, OFF_G, 2304, pW1, nullptr, OFF_HI, 160, 256, 2304);
    gemm150<0, 0><<<256 / 64, 256>>>(nullptr, OFF_G, 2304, pW1 + 2304L * 150, nullptr, OFF_HJ, 160, 256, 2304);
    hjb_prep_kernel<<<256, 160>>>(pb1);

    // pairwise output (handles mirror + bias + relu)
    pair_out_kernel<<<65536 / 32, 256>>>(pW2, pb2, pW3, pb3, out);
}

// round 6
// speedup vs baseline: 5.0316x; 2.2703x over previous
#include <cuda_runtime.h>
#include <cuda_fp16.h>
#include <cstdint>

// Problem constants
#define TT 2048
#define EE 768
#define SSP 256
#define HHD 150
#define E3D 2304

// ---------------- scratch (device global, zero-init .bss) ----------------
static constexpr long OFF_H1TOK = 0;
static constexpr long OFF_H2TOK = OFF_H1TOK + 2048L * 160;
static constexpr long OFF_WE    = OFF_H2TOK + 2048L * 160;
static constexpr long OFF_G     = OFF_WE    + 2048L * 768;
static constexpr long OFF_MH1   = OFF_G     + 256L * 2304;
static constexpr long OFF_MH2   = OFF_MH1   + 256L * 160;
static constexpr long OFF_M     = OFF_MH2   + 256L * 160;
static constexpr long OFF_HI    = OFF_M     + 256L;
static constexpr long OFF_HJB   = OFF_HI    + 256L * 160;
static constexpr long OFF_H1P   = OFF_HJB   + 256L * 160;
static constexpr long SCRATCH_TOTAL = OFF_H1P + 65536L * 160;
// split-K partial buffers alias the h1p region (consumed before pair_h1 runs)
static constexpr long OFF_PART  = OFF_H1P;

__device__ __align__(16) float g_scratch[SCRATCH_TOTAL];

// Wc transposed, f16: [160 n][2304 k], n>=150 zero-padded
__device__ __align__(16) unsigned short g_wct[160L * 2304];

// ======================= helpers ==========================
__device__ __forceinline__ uint32_t smem_u32(const void* p) {
    uint32_t a;
    asm("{ .reg .u64 t; cvta.to.shared.u64 t, %1; cvt.u32.u64 %0, t; }"
        : "=r"(a) : "l"(p));
    return a;
}
#define SWZ(x) ((x) ^ (((x) >> 3) & 0x70))
#define STS128(a0, a1, a2, a3, addr) \
    asm volatile("st.shared.v4.b32 [%0], {%1,%2,%3,%4};" \
                 :: "r"(addr), "r"(a0), "r"(a1), "r"(a2), "r"(a3) : "memory")

__device__ __forceinline__ uint32_t pack_h2(float lo, float hi) {
    uint32_t d;
    asm("cvt.rn.f16x2.f32 %0, %1, %2;" : "=r"(d) : "f"(hi), "f"(lo));
    return d;
}

#define LDSM_X4(r0, r1, r2, r3, a) \
    asm volatile("ldmatrix.sync.aligned.m8n8.x4.shared.b16 {%0,%1,%2,%3}, [%4];" \
                 : "=r"(r0), "=r"(r1), "=r"(r2), "=r"(r3) : "r"(a))
#define LDSM_X2(r0, r1, a) \
    asm volatile("ldmatrix.sync.aligned.m8n8.x2.shared.b16 {%0,%1}, [%2];" \
                 : "=r"(r0), "=r"(r1) : "r"(a))
#define MMAF16(c, A0, A1, A2, A3, B0, B1) \
    asm volatile("mma.sync.aligned.m16n8k16.row.col.f32.f16.f16.f32 " \
                 "{%0,%1,%2,%3}, {%4,%5,%6,%7}, {%8,%9}, {%0,%1,%2,%3};" \
                 : "+f"((c)[0]), "+f"((c)[1]), "+f"((c)[2]), "+f"((c)[3]) \
                 : "r"(A0), "r"(A1), "r"(A2), "r"(A3), "r"(B0), "r"(B1))

// ---------------- generic GEMM: C[M,150] = act(A[M,K] @ W[K,150] + b) ----
template <int ACT, int HASBIAS>
__global__ __launch_bounds__(256) void gemm150(
    const float* __restrict__ Aext, long aOff, int lda,
    const float* __restrict__ W,
    const float* __restrict__ bias,
    long cOff, int ldc, int M, int K)
{
    const float* A = Aext ? Aext : (g_scratch + aOff);
    float* C = g_scratch + cOff;

    __shared__ float sA[16][68];
    __shared__ float sW[16][160];

    int tid = threadIdx.x;
    int rg = tid >> 4;
    int cg = tid & 15;
    int row0 = blockIdx.x * 64;

    float acc[4][10];
#pragma unroll
    for (int a = 0; a < 4; a++)
#pragma unroll
        for (int b = 0; b < 10; b++) acc[a][b] = 0.f;

    int nCh = (K + 15) >> 4;
    for (int ch = 0; ch < nCh; ch++) {
        int k0 = ch * 16;
        {
            int c = tid & 15, r = tid >> 4;
#pragma unroll
            for (int pass = 0; pass < 4; pass++) {
                int rl = pass * 16 + r;
                float v = 0.f;
                if (k0 + c < K) v = A[(long)(row0 + rl) * lda + k0 + c];
                sA[c][rl] = v;
            }
        }
#pragma unroll
        for (int i = 0; i < 10; i++) {
            int idx = tid + i * 256;
            int k = idx / 160, h = idx - k * 160;
            float v = 0.f;
            if (k0 + k < K && h < 150) v = W[(long)(k0 + k) * 150 + h];
            sW[k][h] = v;
        }
        __syncthreads();
#pragma unroll
        for (int k = 0; k < 16; k++) {
            float4 a4 = *(const float4*)&sA[k][rg * 4];
            float av0 = a4.x, av1 = a4.y, av2 = a4.z, av3 = a4.w;
#pragma unroll
            for (int hh = 0; hh < 10; hh += 2) {
                float2 w = *(const float2*)&sW[k][cg * 10 + hh];
                acc[0][hh]     += av0 * w.x;  acc[0][hh + 1] += av0 * w.y;
                acc[1][hh]     += av1 * w.x;  acc[1][hh + 1] += av1 * w.y;
                acc[2][hh]     += av2 * w.x;  acc[2][hh + 1] += av2 * w.y;
                acc[3][hh]     += av3 * w.x;  acc[3][hh + 1] += av3 * w.y;
            }
        }
        __syncthreads();
    }

#pragma unroll
    for (int rr = 0; rr < 4; rr++) {
        int row = row0 + rg * 4 + rr;
#pragma unroll
        for (int hh = 0; hh < 10; hh++) {
            int h = cg * 10 + hh;
            if (h < 150) {
                float v = acc[rr][hh];
                if (HASBIAS) v += bias[h];
                if (ACT) v = fmaxf(v, 0.f);
                C[(long)row * ldc + h] = v;
            }
        }
    }
}

// ---------------- split-K GEMM: partials, no bias/act -------------------
// Grid (Mblocks, nSplits, nW). W selected by blockIdx.z.
// P[z][split][row][160] = A[row, ksplit] @ W[ksplit, 150]
__global__ __launch_bounds__(256) void gemm_split(
    const float* __restrict__ Aext, long aOff, int lda,
    const float* __restrict__ W0, const float* __restrict__ W1,
    const float* __restrict__ W2,
    long partOff, int Mtot, int kPerSplit)
{
    const float* A = Aext ? Aext : (g_scratch + aOff);
    const float* W = (blockIdx.z == 0) ? W0 : ((blockIdx.z == 1) ? W1 : W2);
    float* P = g_scratch + partOff
             + ((long)(blockIdx.z * gridDim.y + blockIdx.y) * Mtot) * 160;

    __shared__ float sA[16][68];
    __shared__ float sW[16][160];

    int tid = threadIdx.x;
    int rg = tid >> 4;
    int cg = tid & 15;
    int row0 = blockIdx.x * 64;
    int kbase = blockIdx.y * kPerSplit;

    float acc[4][10];
#pragma unroll
    for (int a = 0; a < 4; a++)
#pragma unroll
        for (int b = 0; b < 10; b++) acc[a][b] = 0.f;

    int nCh = kPerSplit >> 4;
    for (int ch = 0; ch < nCh; ch++) {
        int k0 = kbase + ch * 16;
        {
            int c = tid & 15, r = tid >> 4;
#pragma unroll
            for (int pass = 0; pass < 4; pass++) {
                int rl = pass * 16 + r;
                sA[c][rl] = A[(long)(row0 + rl) * lda + k0 + c];
            }
        }
#pragma unroll
        for (int i = 0; i < 10; i++) {
            int idx = tid + i * 256;
            int k = idx / 160, h = idx - k * 160;
            sW[k][h] = (h < 150) ? W[(long)(k0 + k) * 150 + h] : 0.f;
        }
        __syncthreads();
#pragma unroll
        for (int k = 0; k < 16; k++) {
            float4 a4 = *(const float4*)&sA[k][rg * 4];
            float av0 = a4.x, av1 = a4.y, av2 = a4.z, av3 = a4.w;
#pragma unroll
            for (int hh = 0; hh < 10; hh += 2) {
                float2 w = *(const float2*)&sW[k][cg * 10 + hh];
                acc[0][hh]     += av0 * w.x;  acc[0][hh + 1] += av0 * w.y;
                acc[1][hh]     += av1 * w.x;  acc[1][hh + 1] += av1 * w.y;
                acc[2][hh]     += av2 * w.x;  acc[2][hh + 1] += av2 * w.y;
                acc[3][hh]     += av3 * w.x;  acc[3][hh + 1] += av3 * w.y;
            }
        }
        __syncthreads();
    }

#pragma unroll
    for (int rr = 0; rr < 4; rr++) {
        int row = row0 + rg * 4 + rr;
#pragma unroll
        for (int hh = 0; hh < 10; hh++) {
            int h = cg * 10 + hh;
            if (h < 150) P[(long)row * 160 + h] = acc[rr][hh];
        }
    }
}

// ---------------- token reduce: h1tok = relu(sum parts + ab1) -----------
__global__ __launch_bounds__(160) void reduce_tok(const float* __restrict__ ab1)
{
    int row = blockIdx.x, c = threadIdx.x;
    float s = 0.f;
    if (c < 150) {
#pragma unroll
        for (int k = 0; k < 6; k++)
            s += g_scratch[OFF_PART + ((long)k * 2048 + row) * 160 + c];
        s = fmaxf(s + ab1[c], 0.f);
    }
    g_scratch[OFF_H1TOK + (long)row * 160 + c] = s;
}

// ---------------- 3-way reduce: mh1 / hi / hjb --------------------------
__global__ __launch_bounds__(160) void reduce_3(
    const float* __restrict__ mb1, const float* __restrict__ pb1)
{
    int row = blockIdx.x, z = blockIdx.y, c = threadIdx.x;
    float s = 0.f;
    if (c < 150) {
#pragma unroll
        for (int k = 0; k < 12; k++)
            s += g_scratch[OFF_PART + ((long)(z * 12 + k) * 256 + row) * 160 + c];
    }
    if (z == 0) {
        float v = (c < 150) ? fmaxf(s + mb1[c], 0.f) : 0.f;
        g_scratch[OFF_MH1 + (long)row * 160 + c] = v;
    } else if (z == 1) {
        g_scratch[OFF_HI + (long)row * 160 + c] = s;
    } else {
        float v = s + ((c < 150) ? pb1[c] : 0.f);
        g_scratch[OFF_HJB + (long)row * 160 + c] = v;
    }
}

// ---------------- attn = h2 . aW3 + b; we = e * attn -------------------
__global__ __launch_bounds__(256) void attn_we_kernel(
    const float* __restrict__ w3, const float* __restrict__ b3,
    const float* __restrict__ e)
{
    __shared__ float red[256];
    const float* h2 = g_scratch + OFF_H2TOK;
    float* we = g_scratch + OFF_WE;
    int t = blockIdx.x, tid = threadIdx.x;
    float v = 0.f;
    if (tid < 150) v = h2[(long)t * 160 + tid] * w3[tid];
    red[tid] = v;
    __syncthreads();
    for (int s = 128; s > 0; s >>= 1) {
        if (tid < s) red[tid] += red[tid + s];
        __syncthreads();
    }
    float attn = red[0] + b3[0];
#pragma unroll
    for (int i = 0; i < 3; i++) {
        int c = tid + i * 256;
        we[(long)t * 768 + c] = e[(long)t * 768 + c] * attn;
    }
}

// ---------------- row dot: out[r] = A[r,:150] . w + b -------------------
__global__ __launch_bounds__(256) void rowdot_kernel(
    long aOff, const float* __restrict__ w, const float* __restrict__ b,
    long oOff)
{
    __shared__ float red[256];
    const float* A = g_scratch + aOff;
    float* out = g_scratch + oOff;
    int r = blockIdx.x, tid = threadIdx.x;
    float v = 0.f;
    if (tid < 150) v = A[(long)r * 160 + tid] * w[tid];
    red[tid] = v;
    __syncthreads();
    for (int s = 128; s > 0; s >>= 1) {
        if (tid < s) red[tid] += red[tid + s];
        __syncthreads();
    }
    if (tid == 0) out[r] = red[0] + b[0];
}

// ---------------- g = [e_start | e_end | span_sum] ----------------------
__global__ __launch_bounds__(256) void gather_g_kernel(
    const float* __restrict__ e,
    const int* __restrict__ sp, const int* __restrict__ wd)
{
    const float* we = g_scratch + OFF_WE;
    float* g = g_scratch + OFF_G;
    int s = blockIdx.x, tid = threadIdx.x;
    int st = sp[s];
    int en = st + wd[s];
    if (en > TT - 1) en = TT - 1;
    if (en < 0) en = 0;
#pragma unroll
    for (int i = 0; i < 3; i++) {
        int c = tid + i * 256;
        g[(long)s * 2304 + c]        = e[(long)st * 768 + c];
        g[(long)s * 2304 + 768 + c]  = e[(long)en * 768 + c];
        float sum = 0.f;
        for (int t = st; t <= en; t++) sum += we[(long)t * 768 + c];
        g[(long)s * 2304 + 1536 + c] = sum;
    }
}

// ---------------- Wc -> transposed f16 ----------------------------------
__global__ __launch_bounds__(256) void wct_split_kernel(const float* __restrict__ Wc)
{
    long idx = (long)blockIdx.x * 256 + threadIdx.x;   // 0 .. 160*2304-1
    int n = (int)(idx / 2304);
    int k = (int)(idx - (long)n * 2304);
    float w = (n < 150) ? Wc[(long)k * 150 + n] : 0.f;
    __half h = __float2half_rn(w);
    g_wct[idx] = __half_as_ushort(h);
}

// ================= pair_h1: lower-triangle hij via f16 1-pass mma =======
#define PH1_A 0
#define PH1_B 8192
#define PH1_BUF 28672
#define PH1_SMEM (2 * PH1_BUF)

__global__ void __launch_bounds__(256, 2) pair_h1_mma()
{
    extern __shared__ __align__(1024) char smem[];
    uint32_t sb = smem_u32(smem);

    const float* g = g_scratch + OFF_G;
    float* h1p     = g_scratch + OFF_H1P;

    int tid  = threadIdx.x;
    int lane = tid & 31;
    int wid  = tid >> 5;
    int j    = blockIdx.x;
    int ib   = blockIdx.y;

    int fj = j & ~15;
    int i0 = fj + ib * 64;
    if (i0 >= 256) return;
    int M = 256 - i0;
    if (M > 64) M = 64;

    int wm = (wid >> 2) * 32;        // m-tile
    int wn = (wid & 3) * 40;         // n-tile

    float acc[2][5][4];
#pragma unroll
    for (int a = 0; a < 2; a++)
#pragma unroll
        for (int b = 0; b < 5; b++)
#pragma unroll
            for (int c = 0; c < 4; c++) acc[a][b][c] = 0.f;

    int arow = tid >> 2;              // local row 0..63
    int akq  = (tid & 3) * 16;        // k offset within chunk
    const float* gi_base = g + ((long)(i0 + arow)) * 2304 + akq;
    const float* gj_base = g + (long)j * 2304 + akq;

    auto stage = [&](int ch) {
        uint32_t tb = sb + (uint32_t)(ch & 1) * PH1_BUF;
        int k0 = ch * 64;
        if (arow < M) {
            const float4* gi4 = (const float4*)(gi_base + k0);
            const float4* gj4 = (const float4*)(gj_base + k0);
#pragma unroll
            for (int u = 0; u < 2; u++) {
                float4 a0 = gi4[u * 2], a1 = gi4[u * 2 + 1];
                float4 w0 = gj4[u * 2], w1 = gj4[u * 2 + 1];
                uint32_t h01 = pack_h2(a0.x * w0.x, a0.y * w0.y);
                uint32_t h23 = pack_h2(a0.z * w0.z, a0.w * w0.w);
                uint32_t h45 = pack_h2(a1.x * w1.x, a1.y * w1.y);
                uint32_t h67 = pack_h2(a1.z * w1.z, a1.w * w1.w);
                uint32_t sw = SWZ((uint32_t)(arow * 128 + akq * 2 + u * 16));
                STS128(h01, h23, h45, h67, tb + PH1_A + sw);
            }
        }
#pragma unroll
        for (int t = 0; t < 5; t++) {
            int idx = tid + t * 256;
            int n = idx >> 3, u = idx & 7;
            uint4 v = *(const uint4*)(g_wct + (long)n * 2304 + k0 + u * 8);
            uint32_t sw = SWZ((uint32_t)(n * 128 + u * 16));
            STS128(v.x, v.y, v.z, v.w, tb + PH1_B + sw);
        }
    };

    stage(0);
    __syncthreads();

    for (int ch = 0; ch < 36; ch++) {
        if (ch < 35) stage(ch + 1);
        uint32_t tb = sb + (uint32_t)(ch & 1) * PH1_BUF;
        if (wm < M) {
#pragma unroll
            for (int ks = 0; ks < 4; ks++) {
                uint32_t Bf[5][2];
                {
                    int m = lane >> 3;
                    int n = wn + (m >> 1) * 8 + (lane & 7);
                    uint32_t off = SWZ((uint32_t)(n * 128 + ks * 32 + (m & 1) * 16));
                    LDSM_X4(Bf[0][0], Bf[0][1], Bf[1][0], Bf[1][1], tb + PH1_B + off);
                }
                {
                    int m = lane >> 3;
                    int n = wn + 16 + (m >> 1) * 8 + (lane & 7);
                    uint32_t off = SWZ((uint32_t)(n * 128 + ks * 32 + (m & 1) * 16));
                    LDSM_X4(Bf[2][0], Bf[2][1], Bf[3][0], Bf[3][1], tb + PH1_B + off);
                }
                {
                    int n = wn + 32 + (lane & 7);
                    uint32_t off = SWZ((uint32_t)(n * 128 + ks * 32 + ((lane >> 3) & 1) * 16));
                    LDSM_X2(Bf[4][0], Bf[4][1], tb + PH1_B + off);
                }
#pragma unroll
                for (int mt = 0; mt < 2; mt++) {
                    if (wm + mt * 16 >= M) continue;
                    int r = wm + mt * 16 + (lane & 15);
                    uint32_t aoff = SWZ((uint32_t)(r * 128 + ks * 32 + (lane >> 4) * 16));
                    uint32_t A0, A1, A2, A3;
                    LDSM_X4(A0, A1, A2, A3, tb + PH1_A + aoff);
#pragma unroll
                    for (int nt = 0; nt < 5; nt++)
                        MMAF16(acc[mt][nt], A0, A1, A2, A3, Bf[nt][0], Bf[nt][1]);
                }
            }
        }
        __syncthreads();
    }

    if (wm < M) {
#pragma unroll
        for (int mt = 0; mt < 2; mt++) {
            if (wm + mt * 16 >= M) continue;
#pragma unroll
            for (int nt = 0; nt < 5; nt++) {
                int c = wn + nt * 8 + (lane & 3) * 2;
#pragma unroll
                for (int h = 0; h < 2; h++) {
                    int i = i0 + wm + mt * 16 + (lane >> 2) + h * 8;
                    *(float2*)(h1p + ((long)i * 256 + j) * 160 + c) =
                        make_float2(acc[mt][nt][h * 2], acc[mt][nt][h * 2 + 1]);
                }
            }
        }
    }
}

// ---------------- per-pair: h1 assemble + h2 GEMM + score + clip --------
__global__ __launch_bounds__(256) void pair_out_kernel(
    const float* __restrict__ W2, const float* __restrict__ pb2,
    const float* __restrict__ w3, const float* __restrict__ pb3,
    float* __restrict__ out)
{
    __shared__ float sH1[32][160];
    __shared__ float sW2[32][160];
    __shared__ float sRed[32][16];

    const float* h1p = g_scratch + OFF_H1P;
    const float* m   = g_scratch + OFF_M;
    const float* hi  = g_scratch + OFF_HI;
    const float* hjb = g_scratch + OFF_HJB;

    int tid = threadIdx.x;
    int pg = tid >> 4, hg = tid & 15;
    long p0 = (long)blockIdx.x * 32;
    int i_fix = (int)(p0 >> 8);
    int j0 = (int)(p0 & 255);

    // assemble h1 = relu(hij + hi_i + hj_j + b); mirror read for i<j
    {
        int r = tid >> 3, q = tid & 7;
        int j = j0 + r;
        long src = (j <= i_fix) ? ((long)i_fix * 256 + j) : ((long)j * 256 + i_fix);
        const float4* s4 = (const float4*)(h1p + src * 160);
        const float4* hi4 = (const float4*)(hi + (long)i_fix * 160);
        const float4* hb4 = (const float4*)(hjb + (long)j * 160);
        float4* d4 = (float4*)&sH1[r][0];
#pragma unroll
        for (int v = 0; v < 5; v++) {
            int idx = q + v * 8;
            float4 a = s4[idx], b = hi4[idx], c = hb4[idx];
            float4 o;
            o.x = fmaxf(a.x + b.x + c.x, 0.f);
            o.y = fmaxf(a.y + b.y + c.y, 0.f);
            o.z = fmaxf(a.z + b.z + c.z, 0.f);
            o.w = fmaxf(a.w + b.w + c.w, 0.f);
            d4[idx] = o;
        }
    }

    float acc[2][10];
#pragma unroll
    for (int a = 0; a < 2; a++)
#pragma unroll
        for (int b = 0; b < 10; b++) acc[a][b] = 0.f;

    for (int kc = 0; kc < 5; kc++) {
        int kb = kc * 32;
#pragma unroll
        for (int i = 0; i < 20; i++) {
            int idx = tid + i * 256;
            int e = idx / 160, h = idx - e * 160;
            int kk = kb + e;
            sW2[e][h] = (kk < 150 && h < 150) ? W2[(long)kk * 150 + h] : 0.f;
        }
        __syncthreads();
#pragma unroll 8
        for (int e = 0; e < 32; e++) {
            float x0 = sH1[pg * 2][kb + e];
            float x1 = sH1[pg * 2 + 1][kb + e];
#pragma unroll
            for (int hh = 0; hh < 10; hh += 2) {
                float2 w = *(const float2*)&sW2[e][hg * 10 + hh];
                acc[0][hh]     += x0 * w.x;  acc[0][hh + 1] += x0 * w.y;
                acc[1][hh]     += x1 * w.x;  acc[1][hh + 1] += x1 * w.y;
            }
        }
        __syncthreads();
    }

#pragma unroll
    for (int pp = 0; pp < 2; pp++) {
        float sacc = 0.f;
#pragma unroll
        for (int hh = 0; hh < 10; hh++) {
            int h = hg * 10 + hh;
            if (h < 150) {
                float v = fmaxf(acc[pp][hh] + pb2[h], 0.f);
                sacc += v * w3[h];
            }
        }
        sRed[pg * 2 + pp][hg] = sacc;
    }
    __syncthreads();
    if (tid < 32) {
        float s = pb3[0];
#pragma unroll
        for (int h = 0; h < 16; h++) s += sRed[tid][h];
        long pr = p0 + tid;
        int i = (int)(pr >> 8), jj = (int)(pr & 255);
        float v = (m[i] + m[jj] + s) * (1.f / 3.f);
        v = fminf(fmaxf(v, 0.f), 1.f);
        out[pr] = v;
    }
}

// ---------------- launch ------------------------------------------------
extern "C" void kernel_launch(void* const* d_in, const int* in_sizes, int n_in,
                              void* d_out, int out_size)
{
    const float* e   = (const float*)d_in[0];
    const int*   sp  = (const int*)d_in[1];
    const int*   wd  = (const int*)d_in[2];
    const float* aW1 = (const float*)d_in[3];
    const float* ab1 = (const float*)d_in[4];
    const float* aW2 = (const float*)d_in[5];
    const float* ab2 = (const float*)d_in[6];
    const float* aW3 = (const float*)d_in[7];
    const float* ab3 = (const float*)d_in[8];
    const float* mW1 = (const float*)d_in[9];
    const float* mb1 = (const float*)d_in[10];
    const float* mW2 = (const float*)d_in[11];
    const float* mb2 = (const float*)d_in[12];
    const float* mW3 = (const float*)d_in[13];
    const float* mb3 = (const float*)d_in[14];
    const float* pW1 = (const float*)d_in[15];
    const float* pb1 = (const float*)d_in[16];
    const float* pW2 = (const float*)d_in[17];
    const float* pb2 = (const float*)d_in[18];
    const float* pW3 = (const float*)d_in[19];
    const float* pb3 = (const float*)d_in[20];
    float* out = (float*)d_out;

    cudaFuncSetAttribute(pair_h1_mma, cudaFuncAttributeMaxDynamicSharedMemorySize,
                         PH1_SMEM);

    // Wc transpose -> f16 (independent)
    wct_split_kernel<<<1440, 256>>>(pW1 + 4608L * 150);

    // token MLP layer 1: split-K (6 x 128) -> partials -> reduce
    gemm_split<<<dim3(32, 6, 1), 256>>>(e, 0, 768, aW1, nullptr, nullptr,
                                        OFF_PART, 2048, 128);
    reduce_tok<<<2048, 160>>>(ab1);
    gemm150<1, 1><<<2048 / 64, 256>>>(nullptr, OFF_H1TOK, 160, aW2, ab2,
                                      OFF_H2TOK, 160, 2048, 150);
    attn_we_kernel<<<2048, 256>>>(aW3, ab3, e);

    // span features
    gather_g_kernel<<<256, 256>>>(e, sp, wd);

    // fused mh1 / hi / hjb: split-K (12 x 192) x 3 weights -> reduce
    gemm_split<<<dim3(4, 12, 3), 256>>>(nullptr, OFF_G, 2304,
                                        mW1, pW1, pW1 + 2304L * 150,
                                        OFF_PART, 256, 192);
    reduce_3<<<dim3(256, 3), 160>>>(mb1, pb1);

    // lower-triangle hij on tensor cores (f16 1-pass)
    pair_h1_mma<<<dim3(256, 4), 256, PH1_SMEM>>>();

    // m MLP tail
    gemm150<1, 1><<<256 / 64, 256>>>(nullptr, OFF_MH1, 160, mW2, mb2,
                                     OFF_MH2, 160, 256, 150);
    rowdot_kernel<<<256, 256>>>(OFF_MH2, mW3, mb3, OFF_M);

    // pairwise output (handles mirror + bias + relu)
    pair_out_kernel<<<65536 / 32, 256>>>(pW2, pb2, pW3, pb3, out);
}

// round 7
// speedup vs baseline: 5.5808x; 1.1092x over previous
#include <cuda_runtime.h>
#include <cuda_fp16.h>
#include <cstdint>

// Problem constants
#define TT 2048
#define EE 768
#define SSP 256
#define HHD 150
#define E3D 2304

// ---------------- scratch (device global, zero-init .bss) ----------------
static constexpr long OFF_H1TOK = 0;
static constexpr long OFF_H2TOK = OFF_H1TOK + 2048L * 160;
static constexpr long OFF_WE    = OFF_H2TOK + 2048L * 160;
static constexpr long OFF_G     = OFF_WE    + 2048L * 768;
static constexpr long OFF_MH1   = OFF_G     + 256L * 2304;
static constexpr long OFF_MH2   = OFF_MH1   + 256L * 160;
static constexpr long OFF_M     = OFF_MH2   + 256L * 160;
static constexpr long OFF_HI    = OFF_M     + 256L;
static constexpr long OFF_HJB   = OFF_HI    + 256L * 160;
static constexpr long OFF_H1P   = OFF_HJB   + 256L * 160;   // k-split partial 0
static constexpr long OFF_H1P2  = OFF_H1P   + 65536L * 160; // k-split partial 1
static constexpr long SCRATCH_TOTAL = OFF_H1P2 + 65536L * 160;
// split-K partial buffers for the skinny GEMMs alias the h1p region
// (consumed by reduce kernels before pair_h1 writes it; single stream)
static constexpr long OFF_PART  = OFF_H1P;

__device__ __align__(16) float g_scratch[SCRATCH_TOTAL];

// Wc transposed, f16: [160 n][2304 k], n>=150 zero-padded
__device__ __align__(16) unsigned short g_wct[160L * 2304];

// ======================= helpers ==========================
__device__ __forceinline__ uint32_t smem_u32(const void* p) {
    uint32_t a;
    asm("{ .reg .u64 t; cvta.to.shared.u64 t, %1; cvt.u32.u64 %0, t; }"
        : "=r"(a) : "l"(p));
    return a;
}
#define SWZ(x) ((x) ^ (((x) >> 3) & 0x70))
#define STS128(a0, a1, a2, a3, addr) \
    asm volatile("st.shared.v4.b32 [%0], {%1,%2,%3,%4};" \
                 :: "r"(addr), "r"(a0), "r"(a1), "r"(a2), "r"(a3) : "memory")

__device__ __forceinline__ uint32_t pack_h2(float lo, float hi) {
    uint32_t d;
    asm("cvt.rn.f16x2.f32 %0, %1, %2;" : "=r"(d) : "f"(hi), "f"(lo));
    return d;
}

#define LDSM_X4(r0, r1, r2, r3, a) \
    asm volatile("ldmatrix.sync.aligned.m8n8.x4.shared.b16 {%0,%1,%2,%3}, [%4];" \
                 : "=r"(r0), "=r"(r1), "=r"(r2), "=r"(r3) : "r"(a))
#define LDSM_X2(r0, r1, a) \
    asm volatile("ldmatrix.sync.aligned.m8n8.x2.shared.b16 {%0,%1}, [%2];" \
                 : "=r"(r0), "=r"(r1) : "r"(a))
#define MMAF16(c, A0, A1, A2, A3, B0, B1) \
    asm volatile("mma.sync.aligned.m16n8k16.row.col.f32.f16.f16.f32 " \
                 "{%0,%1,%2,%3}, {%4,%5,%6,%7}, {%8,%9}, {%0,%1,%2,%3};" \
                 : "+f"((c)[0]), "+f"((c)[1]), "+f"((c)[2]), "+f"((c)[3]) \
                 : "r"(A0), "r"(A1), "r"(A2), "r"(A3), "r"(B0), "r"(B1))

// ---------------- gemm150: C[M,150] = act(A[M,K] @ W[K,150] + b) --------
// BM rows per block (16 or 64), 256 threads, thread tile (BM/16) x 10.
template <int ACT, int HASBIAS, int BM>
__global__ __launch_bounds__(256) void gemm150(
    const float* __restrict__ Aext, long aOff, int lda,
    const float* __restrict__ W,
    const float* __restrict__ bias,
    long cOff, int ldc, int M, int K)
{
    constexpr int RPT = BM / 16;
    const float* A = Aext ? Aext : (g_scratch + aOff);
    float* C = g_scratch + cOff;

    __shared__ float sA[16][BM + 4];
    __shared__ float sW[16][160];

    int tid = threadIdx.x;
    int rg = tid >> 4;
    int cg = tid & 15;
    int row0 = blockIdx.x * BM;

    float acc[RPT][10];
#pragma unroll
    for (int a = 0; a < RPT; a++)
#pragma unroll
        for (int b = 0; b < 10; b++) acc[a][b] = 0.f;

    int nCh = (K + 15) >> 4;
    for (int ch = 0; ch < nCh; ch++) {
        int k0 = ch * 16;
        {
            int c = tid & 15, r = tid >> 4;
#pragma unroll
            for (int pass = 0; pass < RPT; pass++) {
                int rl = pass * 16 + r;
                float v = 0.f;
                if (k0 + c < K) v = A[(long)(row0 + rl) * lda + k0 + c];
                sA[c][rl] = v;
            }
        }
#pragma unroll
        for (int i = 0; i < 10; i++) {
            int idx = tid + i * 256;
            int k = idx / 160, h = idx - k * 160;
            float v = 0.f;
            if (k0 + k < K && h < 150) v = W[(long)(k0 + k) * 150 + h];
            sW[k][h] = v;
        }
        __syncthreads();
#pragma unroll
        for (int k = 0; k < 16; k++) {
            float av[RPT];
#pragma unroll
            for (int rr = 0; rr < RPT; rr++) av[rr] = sA[k][rg * RPT + rr];
#pragma unroll
            for (int hh = 0; hh < 10; hh += 2) {
                float2 w = *(const float2*)&sW[k][cg * 10 + hh];
#pragma unroll
                for (int rr = 0; rr < RPT; rr++) {
                    acc[rr][hh]     += av[rr] * w.x;
                    acc[rr][hh + 1] += av[rr] * w.y;
                }
            }
        }
        __syncthreads();
    }

#pragma unroll
    for (int rr = 0; rr < RPT; rr++) {
        int row = row0 + rg * RPT + rr;
#pragma unroll
        for (int hh = 0; hh < 10; hh++) {
            int h = cg * 10 + hh;
            if (h < 150) {
                float v = acc[rr][hh];
                if (HASBIAS) v += bias[h];
                if (ACT) v = fmaxf(v, 0.f);
                C[(long)row * ldc + h] = v;
            }
        }
    }
}

// ---------------- split-K GEMM: partials, no bias/act -------------------
__global__ __launch_bounds__(256) void gemm_split(
    const float* __restrict__ Aext, long aOff, int lda,
    const float* __restrict__ W0, const float* __restrict__ W1,
    const float* __restrict__ W2,
    long partOff, int Mtot, int kPerSplit)
{
    const float* A = Aext ? Aext : (g_scratch + aOff);
    const float* W = (blockIdx.z == 0) ? W0 : ((blockIdx.z == 1) ? W1 : W2);
    float* P = g_scratch + partOff
             + ((long)(blockIdx.z * gridDim.y + blockIdx.y) * Mtot) * 160;

    __shared__ float sA[16][68];
    __shared__ float sW[16][160];

    int tid = threadIdx.x;
    int rg = tid >> 4;
    int cg = tid & 15;
    int row0 = blockIdx.x * 64;
    int kbase = blockIdx.y * kPerSplit;

    float acc[4][10];
#pragma unroll
    for (int a = 0; a < 4; a++)
#pragma unroll
        for (int b = 0; b < 10; b++) acc[a][b] = 0.f;

    int nCh = kPerSplit >> 4;
    for (int ch = 0; ch < nCh; ch++) {
        int k0 = kbase + ch * 16;
        {
            int c = tid & 15, r = tid >> 4;
#pragma unroll
            for (int pass = 0; pass < 4; pass++) {
                int rl = pass * 16 + r;
                sA[c][rl] = A[(long)(row0 + rl) * lda + k0 + c];
            }
        }
#pragma unroll
        for (int i = 0; i < 10; i++) {
            int idx = tid + i * 256;
            int k = idx / 160, h = idx - k * 160;
            sW[k][h] = (h < 150) ? W[(long)(k0 + k) * 150 + h] : 0.f;
        }
        __syncthreads();
#pragma unroll
        for (int k = 0; k < 16; k++) {
            float4 a4 = *(const float4*)&sA[k][rg * 4];
            float av0 = a4.x, av1 = a4.y, av2 = a4.z, av3 = a4.w;
#pragma unroll
            for (int hh = 0; hh < 10; hh += 2) {
                float2 w = *(const float2*)&sW[k][cg * 10 + hh];
                acc[0][hh]     += av0 * w.x;  acc[0][hh + 1] += av0 * w.y;
                acc[1][hh]     += av1 * w.x;  acc[1][hh + 1] += av1 * w.y;
                acc[2][hh]     += av2 * w.x;  acc[2][hh + 1] += av2 * w.y;
                acc[3][hh]     += av3 * w.x;  acc[3][hh + 1] += av3 * w.y;
            }
        }
        __syncthreads();
    }

#pragma unroll
    for (int rr = 0; rr < 4; rr++) {
        int row = row0 + rg * 4 + rr;
#pragma unroll
        for (int hh = 0; hh < 10; hh++) {
            int h = cg * 10 + hh;
            if (h < 150) P[(long)row * 160 + h] = acc[rr][hh];
        }
    }
}

// ---------------- token reduce: h1tok = relu(sum parts + ab1) -----------
__global__ __launch_bounds__(160) void reduce_tok(const float* __restrict__ ab1)
{
    int row = blockIdx.x, c = threadIdx.x;
    float s = 0.f;
    if (c < 150) {
#pragma unroll
        for (int k = 0; k < 6; k++)
            s += g_scratch[OFF_PART + ((long)k * 2048 + row) * 160 + c];
        s = fmaxf(s + ab1[c], 0.f);
    }
    g_scratch[OFF_H1TOK + (long)row * 160 + c] = s;
}

// ---------------- 3-way reduce: mh1 / hi / hjb --------------------------
__global__ __launch_bounds__(160) void reduce_3(
    const float* __restrict__ mb1, const float* __restrict__ pb1)
{
    int row = blockIdx.x, z = blockIdx.y, c = threadIdx.x;
    float s = 0.f;
    if (c < 150) {
#pragma unroll
        for (int k = 0; k < 12; k++)
            s += g_scratch[OFF_PART + ((long)(z * 12 + k) * 256 + row) * 160 + c];
    }
    if (z == 0) {
        float v = (c < 150) ? fmaxf(s + mb1[c], 0.f) : 0.f;
        g_scratch[OFF_MH1 + (long)row * 160 + c] = v;
    } else if (z == 1) {
        g_scratch[OFF_HI + (long)row * 160 + c] = s;
    } else {
        float v = s + ((c < 150) ? pb1[c] : 0.f);
        g_scratch[OFF_HJB + (long)row * 160 + c] = v;
    }
}

// ---------------- attn = h2 . aW3 + b; we = e * attn -------------------
__global__ __launch_bounds__(256) void attn_we_kernel(
    const float* __restrict__ w3, const float* __restrict__ b3,
    const float* __restrict__ e)
{
    __shared__ float red[256];
    const float* h2 = g_scratch + OFF_H2TOK;
    float* we = g_scratch + OFF_WE;
    int t = blockIdx.x, tid = threadIdx.x;
    float v = 0.f;
    if (tid < 150) v = h2[(long)t * 160 + tid] * w3[tid];
    red[tid] = v;
    __syncthreads();
    for (int s = 128; s > 0; s >>= 1) {
        if (tid < s) red[tid] += red[tid + s];
        __syncthreads();
    }
    float attn = red[0] + b3[0];
#pragma unroll
    for (int i = 0; i < 3; i++) {
        int c = tid + i * 256;
        we[(long)t * 768 + c] = e[(long)t * 768 + c] * attn;
    }
}

// ---------------- row dot: out[r] = A[r,:150] . w + b -------------------
__global__ __launch_bounds__(256) void rowdot_kernel(
    long aOff, const float* __restrict__ w, const float* __restrict__ b,
    long oOff)
{
    __shared__ float red[256];
    const float* A = g_scratch + aOff;
    float* out = g_scratch + oOff;
    int r = blockIdx.x, tid = threadIdx.x;
    float v = 0.f;
    if (tid < 150) v = A[(long)r * 160 + tid] * w[tid];
    red[tid] = v;
    __syncthreads();
    for (int s = 128; s > 0; s >>= 1) {
        if (tid < s) red[tid] += red[tid + s];
        __syncthreads();
    }
    if (tid == 0) out[r] = red[0] + b[0];
}

// ---------------- g = [e_start | e_end | span_sum] ----------------------
__global__ __launch_bounds__(256) void gather_g_kernel(
    const float* __restrict__ e,
    const int* __restrict__ sp, const int* __restrict__ wd)
{
    const float* we = g_scratch + OFF_WE;
    float* g = g_scratch + OFF_G;
    int s = blockIdx.x, tid = threadIdx.x;
    int st = sp[s];
    int en = st + wd[s];
    if (en > TT - 1) en = TT - 1;
    if (en < 0) en = 0;
#pragma unroll
    for (int i = 0; i < 3; i++) {
        int c = tid + i * 256;
        g[(long)s * 2304 + c]        = e[(long)st * 768 + c];
        g[(long)s * 2304 + 768 + c]  = e[(long)en * 768 + c];
        float sum = 0.f;
        for (int t = st; t <= en; t++) sum += we[(long)t * 768 + c];
        g[(long)s * 2304 + 1536 + c] = sum;
    }
}

// ---------------- Wc -> transposed f16 ----------------------------------
__global__ __launch_bounds__(256) void wct_split_kernel(const float* __restrict__ Wc)
{
    long idx = (long)blockIdx.x * 256 + threadIdx.x;   // 0 .. 160*2304-1
    int n = (int)(idx / 2304);
    int k = (int)(idx - (long)n * 2304);
    float w = (n < 150) ? Wc[(long)k * 150 + n] : 0.f;
    __half h = __float2half_rn(w);
    g_wct[idx] = __half_as_ushort(h);
}

// ================= pair_h1: lower-triangle hij, f16 mma =================
// Grid (128 jp, 8 = 4 iblock x 2 ksplit). CTA: 2 j's (j0=2jp, j0+1),
// 64 i-rows, K-half (1152) -> partial hij into buf[ksplit].
// 512 threads = 16 warps: jsel(2) x m(2) x n(4); warp tile 32x40.
// B (Wc^T) staged once per chunk, shared by both j's.
#define PH1_A0 0
#define PH1_A1 8192
#define PH1_B  16384
#define PH1_BUF 36864
#define PH1_SMEM (2 * PH1_BUF)

__global__ void __launch_bounds__(512, 1) pair_h1_mma()
{
    extern __shared__ __align__(1024) char smem[];
    uint32_t sb = smem_u32(smem);

    const float* g = g_scratch + OFF_G;

    int tid  = threadIdx.x;
    int lane = tid & 31;
    int wid  = tid >> 5;
    int jp   = blockIdx.x;
    int yy   = blockIdx.y;
    int ib   = yy >> 1;
    int ksh  = yy & 1;

    int j0 = jp * 2;
    int fj = j0 & ~15;
    int i0 = fj + ib * 64;
    if (i0 >= 256) return;
    int M = 256 - i0;
    if (M > 64) M = 64;

    float* hbuf = g_scratch + (ksh ? OFF_H1P2 : OFF_H1P);
    int kbase = ksh * 1152;

    int jsel = wid >> 3;             // which j this warp computes
    int wm   = ((wid >> 2) & 1) * 32;
    int wn   = (wid & 3) * 40;

    float acc[2][5][4];
#pragma unroll
    for (int a = 0; a < 2; a++)
#pragma unroll
        for (int b = 0; b < 5; b++)
#pragma unroll
            for (int c = 0; c < 4; c++) acc[a][b][c] = 0.f;

    // staging coords: thread handles row arow (0..63), 8 k-values at seg*8
    int arow = tid >> 3;
    int seg  = tid & 7;
    int gi_row = i0 + arow; if (gi_row > 255) gi_row = 255;
    const float* gi_base  = g + (long)gi_row * 2304 + seg * 8;
    const float* gj0_base = g + (long)j0 * 2304 + seg * 8;
    const float* gj1_base = g + (long)(j0 + 1) * 2304 + seg * 8;

    auto stage = [&](int ch) {
        uint32_t tb = sb + (uint32_t)(ch & 1) * PH1_BUF;
        int k0 = kbase + ch * 64;
        {
            const float4* gi4 = (const float4*)(gi_base + k0);
            float4 a0 = gi4[0], a1 = gi4[1];
            uint32_t sw = SWZ((uint32_t)(arow * 128 + seg * 16));
            {
                const float4* gj4 = (const float4*)(gj0_base + k0);
                float4 w0 = gj4[0], w1 = gj4[1];
                uint32_t h01 = pack_h2(a0.x * w0.x, a0.y * w0.y);
                uint32_t h23 = pack_h2(a0.z * w0.z, a0.w * w0.w);
                uint32_t h45 = pack_h2(a1.x * w1.x, a1.y * w1.y);
                uint32_t h67 = pack_h2(a1.z * w1.z, a1.w * w1.w);
                STS128(h01, h23, h45, h67, tb + PH1_A0 + sw);
            }
            {
                const float4* gj4 = (const float4*)(gj1_base + k0);
                float4 w0 = gj4[0], w1 = gj4[1];
                uint32_t h01 = pack_h2(a0.x * w0.x, a0.y * w0.y);
                uint32_t h23 = pack_h2(a0.z * w0.z, a0.w * w0.w);
                uint32_t h45 = pack_h2(a1.x * w1.x, a1.y * w1.y);
                uint32_t h67 = pack_h2(a1.z * w1.z, a1.w * w1.w);
                STS128(h01, h23, h45, h67, tb + PH1_A1 + sw);
            }
        }
        // B: 160 rows x 64 k f16 = 1280 x 16B, 512 threads
#pragma unroll
        for (int t = 0; t < 3; t++) {
            int idx = tid + t * 512;
            if (idx < 1280) {
                int n = idx >> 3, u = idx & 7;
                uint4 v = *(const uint4*)(g_wct + (long)n * 2304 + k0 + u * 8);
                uint32_t sw = SWZ((uint32_t)(n * 128 + u * 16));
                STS128(v.x, v.y, v.z, v.w, tb + PH1_B + sw);
            }
        }
    };

    stage(0);
    __syncthreads();

    for (int ch = 0; ch < 18; ch++) {
        if (ch < 17) stage(ch + 1);
        uint32_t tb = sb + (uint32_t)(ch & 1) * PH1_BUF;
        uint32_t ta = tb + (jsel ? PH1_A1 : PH1_A0);
        if (wm < M) {
#pragma unroll
            for (int ks = 0; ks < 4; ks++) {
                uint32_t Bf[5][2];
                {
                    int m = lane >> 3;
                    int n = wn + (m >> 1) * 8 + (lane & 7);
                    uint32_t off = SWZ((uint32_t)(n * 128 + ks * 32 + (m & 1) * 16));
                    LDSM_X4(Bf[0][0], Bf[0][1], Bf[1][0], Bf[1][1], tb + PH1_B + off);
                }
                {
                    int m = lane >> 3;
                    int n = wn + 16 + (m >> 1) * 8 + (lane & 7);
                    uint32_t off = SWZ((uint32_t)(n * 128 + ks * 32 + (m & 1) * 16));
                    LDSM_X4(Bf[2][0], Bf[2][1], Bf[3][0], Bf[3][1], tb + PH1_B + off);
                }
                {
                    int n = wn + 32 + (lane & 7);
                    uint32_t off = SWZ((uint32_t)(n * 128 + ks * 32 + ((lane >> 3) & 1) * 16));
                    LDSM_X2(Bf[4][0], Bf[4][1], tb + PH1_B + off);
                }
#pragma unroll
                for (int mt = 0; mt < 2; mt++) {
                    if (wm + mt * 16 >= M) continue;
                    int r = wm + mt * 16 + (lane & 15);
                    uint32_t aoff = SWZ((uint32_t)(r * 128 + ks * 32 + (lane >> 4) * 16));
                    uint32_t A0, A1, A2, A3;
                    LDSM_X4(A0, A1, A2, A3, ta + aoff);
#pragma unroll
                    for (int nt = 0; nt < 5; nt++)
                        MMAF16(acc[mt][nt], A0, A1, A2, A3, Bf[nt][0], Bf[nt][1]);
                }
            }
        }
        __syncthreads();
    }

    // ---- epilogue: store RAW partial hij ----
    if (wm < M) {
        int j = j0 + jsel;
#pragma unroll
        for (int mt = 0; mt < 2; mt++) {
            if (wm + mt * 16 >= M) continue;
#pragma unroll
            for (int nt = 0; nt < 5; nt++) {
                int c = wn + nt * 8 + (lane & 3) * 2;
#pragma unroll
                for (int h = 0; h < 2; h++) {
                    int i = i0 + wm + mt * 16 + (lane >> 2) + h * 8;
                    *(float2*)(hbuf + ((long)i * 256 + j) * 160 + c) =
                        make_float2(acc[mt][nt][h * 2], acc[mt][nt][h * 2 + 1]);
                }
            }
        }
    }
}

// ---------------- per-pair: h1 assemble + h2 GEMM + score + clip --------
__global__ __launch_bounds__(256) void pair_out_kernel(
    const float* __restrict__ W2, const float* __restrict__ pb2,
    const float* __restrict__ w3, const float* __restrict__ pb3,
    float* __restrict__ out)
{
    __shared__ float sH1[32][160];
    __shared__ float sW2[32][160];
    __shared__ float sRed[32][16];

    const float* h1p  = g_scratch + OFF_H1P;
    const float* h1p2 = g_scratch + OFF_H1P2;
    const float* m    = g_scratch + OFF_M;
    const float* hi   = g_scratch + OFF_HI;
    const float* hjb  = g_scratch + OFF_HJB;

    int tid = threadIdx.x;
    int pg = tid >> 4, hg = tid & 15;
    long p0 = (long)blockIdx.x * 32;
    int i_fix = (int)(p0 >> 8);
    int j0 = (int)(p0 & 255);

    // assemble h1 = relu(hij_p0 + hij_p1 + hi_i + hjb_j); mirror for i<j
    {
        int r = tid >> 3, q = tid & 7;
        int j = j0 + r;
        long src = (j <= i_fix) ? ((long)i_fix * 256 + j) : ((long)j * 256 + i_fix);
        const float4* s4a = (const float4*)(h1p + src * 160);
        const float4* s4b = (const float4*)(h1p2 + src * 160);
        const float4* hi4 = (const float4*)(hi + (long)i_fix * 160);
        const float4* hb4 = (const float4*)(hjb + (long)j * 160);
        float4* d4 = (float4*)&sH1[r][0];
#pragma unroll
        for (int v = 0; v < 5; v++) {
            int idx = q + v * 8;
            float4 a = s4a[idx], a2 = s4b[idx], b = hi4[idx], c = hb4[idx];
            float4 o;
            o.x = fmaxf(a.x + a2.x + b.x + c.x, 0.f);
            o.y = fmaxf(a.y + a2.y + b.y + c.y, 0.f);
            o.z = fmaxf(a.z + a2.z + b.z + c.z, 0.f);
            o.w = fmaxf(a.w + a2.w + b.w + c.w, 0.f);
            d4[idx] = o;
        }
    }

    float acc[2][10];
#pragma unroll
    for (int a = 0; a < 2; a++)
#pragma unroll
        for (int b = 0; b < 10; b++) acc[a][b] = 0.f;

    for (int kc = 0; kc < 5; kc++) {
        int kb = kc * 32;
#pragma unroll
        for (int i = 0; i < 20; i++) {
            int idx = tid + i * 256;
            int e = idx / 160, h = idx - e * 160;
            int kk = kb + e;
            sW2[e][h] = (kk < 150 && h < 150) ? W2[(long)kk * 150 + h] : 0.f;
        }
        __syncthreads();
#pragma unroll 8
        for (int e = 0; e < 32; e++) {
            float x0 = sH1[pg * 2][kb + e];
            float x1 = sH1[pg * 2 + 1][kb + e];
#pragma unroll
            for (int hh = 0; hh < 10; hh += 2) {
                float2 w = *(const float2*)&sW2[e][hg * 10 + hh];
                acc[0][hh]     += x0 * w.x;  acc[0][hh + 1] += x0 * w.y;
                acc[1][hh]     += x1 * w.x;  acc[1][hh + 1] += x1 * w.y;
            }
        }
        __syncthreads();
    }

#pragma unroll
    for (int pp = 0; pp < 2; pp++) {
        float sacc = 0.f;
#pragma unroll
        for (int hh = 0; hh < 10; hh++) {
            int h = hg * 10 + hh;
            if (h < 150) {
                float v = fmaxf(acc[pp][hh] + pb2[h], 0.f);
                sacc += v * w3[h];
            }
        }
        sRed[pg * 2 + pp][hg] = sacc;
    }
    __syncthreads();
    if (tid < 32) {
        float s = pb3[0];
#pragma unroll
        for (int h = 0; h < 16; h++) s += sRed[tid][h];
        long pr = p0 + tid;
        int i = (int)(pr >> 8), jj = (int)(pr & 255);
        float v = (m[i] + m[jj] + s) * (1.f / 3.f);
        v = fminf(fmaxf(v, 0.f), 1.f);
        out[pr] = v;
    }
}

// ---------------- launch ------------------------------------------------
extern "C" void kernel_launch(void* const* d_in, const int* in_sizes, int n_in,
                              void* d_out, int out_size)
{
    const float* e   = (const float*)d_in[0];
    const int*   sp  = (const int*)d_in[1];
    const int*   wd  = (const int*)d_in[2];
    const float* aW1 = (const float*)d_in[3];
    const float* ab1 = (const float*)d_in[4];
    const float* aW2 = (const float*)d_in[5];
    const float* ab2 = (const float*)d_in[6];
    const float* aW3 = (const float*)d_in[7];
    const float* ab3 = (const float*)d_in[8];
    const float* mW1 = (const float*)d_in[9];
    const float* mb1 = (const float*)d_in[10];
    const float* mW2 = (const float*)d_in[11];
    const float* mb2 = (const float*)d_in[12];
    const float* mW3 = (const float*)d_in[13];
    const float* mb3 = (const float*)d_in[14];
    const float* pW1 = (const float*)d_in[15];
    const float* pb1 = (const float*)d_in[16];
    const float* pW2 = (const float*)d_in[17];
    const float* pb2 = (const float*)d_in[18];
    const float* pW3 = (const float*)d_in[19];
    const float* pb3 = (const float*)d_in[20];
    float* out = (float*)d_out;

    cudaFuncSetAttribute(pair_h1_mma, cudaFuncAttributeMaxDynamicSharedMemorySize,
                         PH1_SMEM);

    // Wc transpose -> f16 (independent)
    wct_split_kernel<<<1440, 256>>>(pW1 + 4608L * 150);

    // token MLP layer 1: split-K (6 x 128) -> partials -> reduce
    gemm_split<<<dim3(32, 6, 1), 256>>>(e, 0, 768, aW1, nullptr, nullptr,
                                        OFF_PART, 2048, 128);
    reduce_tok<<<2048, 160>>>(ab1);
    gemm150<1, 1, 16><<<2048 / 16, 256>>>(nullptr, OFF_H1TOK, 160, aW2, ab2,
                                          OFF_H2TOK, 160, 2048, 150);
    attn_we_kernel<<<2048, 256>>>(aW3, ab3, e);

    // span features
    gather_g_kernel<<<256, 256>>>(e, sp, wd);

    // fused mh1 / hi / hjb: split-K (12 x 192) x 3 weights -> reduce
    gemm_split<<<dim3(4, 12, 3), 256>>>(nullptr, OFF_G, 2304,
                                        mW1, pW1, pW1 + 2304L * 150,
                                        OFF_PART, 256, 192);
    reduce_3<<<dim3(256, 3), 160>>>(mb1, pb1);

    // lower-triangle hij on tensor cores (f16, 2 j's per CTA, K-split 2)
    pair_h1_mma<<<dim3(128, 8), 512, PH1_SMEM>>>();

    // m MLP tail
    gemm150<1, 1, 16><<<256 / 16, 256>>>(nullptr, OFF_MH1, 160, mW2, mb2,
                                         OFF_MH2, 160, 256, 150);
    rowdot_kernel<<<256, 256>>>(OFF_MH2, mW3, mb3, OFF_M);

    // pairwise output (handles partial-sum + mirror + bias + relu)
    pair_out_kernel<<<65536 / 32, 256>>>(pW2, pb2, pW3, pb3, out);
}

// round 8
// speedup vs baseline: 5.7090x; 1.0230x over previous
#include <cuda_runtime.h>
#include <cuda_fp16.h>
#include <cstdint>

// Problem constants
#define TT 2048
#define EE 768
#define SSP 256
#define HHD 150
#define E3D 2304

// ---------------- scratch (device global, zero-init .bss) ----------------
static constexpr long OFF_H1TOK = 0;
static constexpr long OFF_H2TOK = OFF_H1TOK + 2048L * 160;
static constexpr long OFF_WE    = OFF_H2TOK + 2048L * 160;
static constexpr long OFF_G     = OFF_WE    + 2048L * 768;
static constexpr long OFF_MH1   = OFF_G     + 256L * 2304;
static constexpr long OFF_MH2   = OFF_MH1   + 256L * 160;
static constexpr long OFF_M     = OFF_MH2   + 256L * 160;
static constexpr long OFF_HI    = OFF_M     + 256L;
static constexpr long OFF_HJB   = OFF_HI    + 256L * 160;
static constexpr long OFF_H1P   = OFF_HJB   + 256L * 160;
static constexpr long SCRATCH_TOTAL = OFF_H1P + 65536L * 160;
// split-K partial buffers for the skinny GEMMs alias the h1p region
// (consumed by reduce kernels before pair_h1 writes it; single stream)
static constexpr long OFF_PART  = OFF_H1P;

__device__ __align__(16) float g_scratch[SCRATCH_TOTAL];

// Wc transposed, f16: [160 n][2304 k], n>=150 zero-padded
__device__ __align__(16) unsigned short g_wct[160L * 2304];

// ======================= helpers ==========================
__device__ __forceinline__ uint32_t smem_u32(const void* p) {
    uint32_t a;
    asm("{ .reg .u64 t; cvta.to.shared.u64 t, %1; cvt.u32.u64 %0, t; }"
        : "=r"(a) : "l"(p));
    return a;
}
#define SWZ(x) ((x) ^ (((x) >> 3) & 0x70))
#define STS128(a0, a1, a2, a3, addr) \
    asm volatile("st.shared.v4.b32 [%0], {%1,%2,%3,%4};" \
                 :: "r"(addr), "r"(a0), "r"(a1), "r"(a2), "r"(a3) : "memory")

__device__ __forceinline__ uint32_t pack_h2(float lo, float hi) {
    uint32_t d;
    asm("cvt.rn.f16x2.f32 %0, %1, %2;" : "=r"(d) : "f"(hi), "f"(lo));
    return d;
}

#define LDSM_X4(r0, r1, r2, r3, a) \
    asm volatile("ldmatrix.sync.aligned.m8n8.x4.shared.b16 {%0,%1,%2,%3}, [%4];" \
                 : "=r"(r0), "=r"(r1), "=r"(r2), "=r"(r3) : "r"(a))
#define LDSM_X2(r0, r1, a) \
    asm volatile("ldmatrix.sync.aligned.m8n8.x2.shared.b16 {%0,%1}, [%2];" \
                 : "=r"(r0), "=r"(r1) : "r"(a))
#define MMAF16(c, A0, A1, A2, A3, B0, B1) \
    asm volatile("mma.sync.aligned.m16n8k16.row.col.f32.f16.f16.f32 " \
                 "{%0,%1,%2,%3}, {%4,%5,%6,%7}, {%8,%9}, {%0,%1,%2,%3};" \
                 : "+f"((c)[0]), "+f"((c)[1]), "+f"((c)[2]), "+f"((c)[3]) \
                 : "r"(A0), "r"(A1), "r"(A2), "r"(A3), "r"(B0), "r"(B1))

// ---------------- gemm150: C[M,150] = act(A[M,K] @ W[K,150] + b) --------
template <int ACT, int HASBIAS, int BM>
__global__ __launch_bounds__(256) void gemm150(
    const float* __restrict__ Aext, long aOff, int lda,
    const float* __restrict__ W,
    const float* __restrict__ bias,
    long cOff, int ldc, int M, int K)
{
    constexpr int RPT = BM / 16;
    const float* A = Aext ? Aext : (g_scratch + aOff);
    float* C = g_scratch + cOff;

    __shared__ float sA[16][BM + 4];
    __shared__ float sW[16][160];

    int tid = threadIdx.x;
    int rg = tid >> 4;
    int cg = tid & 15;
    int row0 = blockIdx.x * BM;

    float acc[RPT][10];
#pragma unroll
    for (int a = 0; a < RPT; a++)
#pragma unroll
        for (int b = 0; b < 10; b++) acc[a][b] = 0.f;

    int nCh = (K + 15) >> 4;
    for (int ch = 0; ch < nCh; ch++) {
        int k0 = ch * 16;
        {
            int c = tid & 15, r = tid >> 4;
#pragma unroll
            for (int pass = 0; pass < RPT; pass++) {
                int rl = pass * 16 + r;
                float v = 0.f;
                if (k0 + c < K) v = A[(long)(row0 + rl) * lda + k0 + c];
                sA[c][rl] = v;
            }
        }
#pragma unroll
        for (int i = 0; i < 10; i++) {
            int idx = tid + i * 256;
            int k = idx / 160, h = idx - k * 160;
            float v = 0.f;
            if (k0 + k < K && h < 150) v = W[(long)(k0 + k) * 150 + h];
            sW[k][h] = v;
        }
        __syncthreads();
#pragma unroll
        for (int k = 0; k < 16; k++) {
            float av[RPT];
#pragma unroll
            for (int rr = 0; rr < RPT; rr++) av[rr] = sA[k][rg * RPT + rr];
#pragma unroll
            for (int hh = 0; hh < 10; hh += 2) {
                float2 w = *(const float2*)&sW[k][cg * 10 + hh];
#pragma unroll
                for (int rr = 0; rr < RPT; rr++) {
                    acc[rr][hh]     += av[rr] * w.x;
                    acc[rr][hh + 1] += av[rr] * w.y;
                }
            }
        }
        __syncthreads();
    }

#pragma unroll
    for (int rr = 0; rr < RPT; rr++) {
        int row = row0 + rg * RPT + rr;
#pragma unroll
        for (int hh = 0; hh < 10; hh++) {
            int h = cg * 10 + hh;
            if (h < 150) {
                float v = acc[rr][hh];
                if (HASBIAS) v += bias[h];
                if (ACT) v = fmaxf(v, 0.f);
                C[(long)row * ldc + h] = v;
            }
        }
    }
}

// ---------------- split-K GEMM: partials, no bias/act -------------------
__global__ __launch_bounds__(256) void gemm_split(
    const float* __restrict__ Aext, long aOff, int lda,
    const float* __restrict__ W0, const float* __restrict__ W1,
    const float* __restrict__ W2,
    long partOff, int Mtot, int kPerSplit)
{
    const float* A = Aext ? Aext : (g_scratch + aOff);
    const float* W = (blockIdx.z == 0) ? W0 : ((blockIdx.z == 1) ? W1 : W2);
    float* P = g_scratch + partOff
             + ((long)(blockIdx.z * gridDim.y + blockIdx.y) * Mtot) * 160;

    __shared__ float sA[16][68];
    __shared__ float sW[16][160];

    int tid = threadIdx.x;
    int rg = tid >> 4;
    int cg = tid & 15;
    int row0 = blockIdx.x * 64;
    int kbase = blockIdx.y * kPerSplit;

    float acc[4][10];
#pragma unroll
    for (int a = 0; a < 4; a++)
#pragma unroll
        for (int b = 0; b < 10; b++) acc[a][b] = 0.f;

    int nCh = kPerSplit >> 4;
    for (int ch = 0; ch < nCh; ch++) {
        int k0 = kbase + ch * 16;
        {
            int c = tid & 15, r = tid >> 4;
#pragma unroll
            for (int pass = 0; pass < 4; pass++) {
                int rl = pass * 16 + r;
                sA[c][rl] = A[(long)(row0 + rl) * lda + k0 + c];
            }
        }
#pragma unroll
        for (int i = 0; i < 10; i++) {
            int idx = tid + i * 256;
            int k = idx / 160, h = idx - k * 160;
            sW[k][h] = (h < 150) ? W[(long)(k0 + k) * 150 + h] : 0.f;
        }
        __syncthreads();
#pragma unroll
        for (int k = 0; k < 16; k++) {
            float4 a4 = *(const float4*)&sA[k][rg * 4];
            float av0 = a4.x, av1 = a4.y, av2 = a4.z, av3 = a4.w;
#pragma unroll
            for (int hh = 0; hh < 10; hh += 2) {
                float2 w = *(const float2*)&sW[k][cg * 10 + hh];
                acc[0][hh]     += av0 * w.x;  acc[0][hh + 1] += av0 * w.y;
                acc[1][hh]     += av1 * w.x;  acc[1][hh + 1] += av1 * w.y;
                acc[2][hh]     += av2 * w.x;  acc[2][hh + 1] += av2 * w.y;
                acc[3][hh]     += av3 * w.x;  acc[3][hh + 1] += av3 * w.y;
            }
        }
        __syncthreads();
    }

#pragma unroll
    for (int rr = 0; rr < 4; rr++) {
        int row = row0 + rg * 4 + rr;
#pragma unroll
        for (int hh = 0; hh < 10; hh++) {
            int h = cg * 10 + hh;
            if (h < 150) P[(long)row * 160 + h] = acc[rr][hh];
        }
    }
}

// ---------------- token reduce: h1tok = relu(sum parts + ab1) -----------
__global__ __launch_bounds__(160) void reduce_tok(const float* __restrict__ ab1)
{
    int row = blockIdx.x, c = threadIdx.x;
    float s = 0.f;
    if (c < 150) {
#pragma unroll
        for (int k = 0; k < 6; k++)
            s += g_scratch[OFF_PART + ((long)k * 2048 + row) * 160 + c];
        s = fmaxf(s + ab1[c], 0.f);
    }
    g_scratch[OFF_H1TOK + (long)row * 160 + c] = s;
}

// ---------------- 3-way reduce: mh1 / hi / hjb --------------------------
__global__ __launch_bounds__(160) void reduce_3(
    const float* __restrict__ mb1, const float* __restrict__ pb1)
{
    int row = blockIdx.x, z = blockIdx.y, c = threadIdx.x;
    float s = 0.f;
    if (c < 150) {
#pragma unroll
        for (int k = 0; k < 12; k++)
            s += g_scratch[OFF_PART + ((long)(z * 12 + k) * 256 + row) * 160 + c];
    }
    if (z == 0) {
        float v = (c < 150) ? fmaxf(s + mb1[c], 0.f) : 0.f;
        g_scratch[OFF_MH1 + (long)row * 160 + c] = v;
    } else if (z == 1) {
        g_scratch[OFF_HI + (long)row * 160 + c] = s;
    } else {
        float v = s + ((c < 150) ? pb1[c] : 0.f);
        g_scratch[OFF_HJB + (long)row * 160 + c] = v;
    }
}

// ---------------- attn = h2 . aW3 + b; we = e * attn -------------------
__global__ __launch_bounds__(256) void attn_we_kernel(
    const float* __restrict__ w3, const float* __restrict__ b3,
    const float* __restrict__ e)
{
    __shared__ float red[256];
    const float* h2 = g_scratch + OFF_H2TOK;
    float* we = g_scratch + OFF_WE;
    int t = blockIdx.x, tid = threadIdx.x;
    float v = 0.f;
    if (tid < 150) v = h2[(long)t * 160 + tid] * w3[tid];
    red[tid] = v;
    __syncthreads();
    for (int s = 128; s > 0; s >>= 1) {
        if (tid < s) red[tid] += red[tid + s];
        __syncthreads();
    }
    float attn = red[0] + b3[0];
#pragma unroll
    for (int i = 0; i < 3; i++) {
        int c = tid + i * 256;
        we[(long)t * 768 + c] = e[(long)t * 768 + c] * attn;
    }
}

// ---------------- row dot: out[r] = A[r,:150] . w + b -------------------
__global__ __launch_bounds__(256) void rowdot_kernel(
    long aOff, const float* __restrict__ w, const float* __restrict__ b,
    long oOff)
{
    __shared__ float red[256];
    const float* A = g_scratch + aOff;
    float* out = g_scratch + oOff;
    int r = blockIdx.x, tid = threadIdx.x;
    float v = 0.f;
    if (tid < 150) v = A[(long)r * 160 + tid] * w[tid];
    red[tid] = v;
    __syncthreads();
    for (int s = 128; s > 0; s >>= 1) {
        if (tid < s) red[tid] += red[tid + s];
        __syncthreads();
    }
    if (tid == 0) out[r] = red[0] + b[0];
}

// ---------------- g = [e_start | e_end | span_sum] ----------------------
__global__ __launch_bounds__(256) void gather_g_kernel(
    const float* __restrict__ e,
    const int* __restrict__ sp, const int* __restrict__ wd)
{
    const float* we = g_scratch + OFF_WE;
    float* g = g_scratch + OFF_G;
    int s = blockIdx.x, tid = threadIdx.x;
    int st = sp[s];
    int en = st + wd[s];
    if (en > TT - 1) en = TT - 1;
    if (en < 0) en = 0;
#pragma unroll
    for (int i = 0; i < 3; i++) {
        int c = tid + i * 256;
        g[(long)s * 2304 + c]        = e[(long)st * 768 + c];
        g[(long)s * 2304 + 768 + c]  = e[(long)en * 768 + c];
        float sum = 0.f;
        for (int t = st; t <= en; t++) sum += we[(long)t * 768 + c];
        g[(long)s * 2304 + 1536 + c] = sum;
    }
}

// ---------------- Wc -> transposed f16 ----------------------------------
__global__ __launch_bounds__(256) void wct_split_kernel(const float* __restrict__ Wc)
{
    long idx = (long)blockIdx.x * 256 + threadIdx.x;   // 0 .. 160*2304-1
    int n = (int)(idx / 2304);
    int k = (int)(idx - (long)n * 2304);
    float w = (n < 150) ? Wc[(long)k * 150 + n] : 0.f;
    __half h = __float2half_rn(w);
    g_wct[idx] = __half_as_ushort(h);
}

// ================= pair_h1: lower-triangle hij, f16 mma =================
// Grid (64 jq, 4 ib). CTA: 4 j's (j0=4jq..j0+3), 64 i-rows, full K=2304.
// 512 threads = 16 warps: jsel(4) x n(4); warp tile 64i x 40n (acc[4][5][4]).
// B (Wc^T) staged once per chunk, shared by all 4 j's; gi LDG shared too.
// Stores RAW hij into h1p (lower triangle at 16-row granularity).
#define PH1_A  0
#define PH1_B  32768
#define PH1_BUF 53248
#define PH1_SMEM (2 * PH1_BUF)

__global__ void __launch_bounds__(512, 1) pair_h1_mma()
{
    extern __shared__ __align__(1024) char smem[];
    uint32_t sb = smem_u32(smem);

    const float* g = g_scratch + OFF_G;
    float* h1p     = g_scratch + OFF_H1P;

    int tid  = threadIdx.x;
    int lane = tid & 31;
    int wid  = tid >> 5;
    int jq   = blockIdx.x;
    int ib   = blockIdx.y;

    int j0 = jq * 4;
    int fj = j0 & ~15;
    int i0 = fj + ib * 64;
    if (i0 >= 256) return;
    int M = 256 - i0;
    if (M > 64) M = 64;

    int jsel = wid >> 2;             // which j this warp computes (0..3)
    int wn   = (wid & 3) * 40;       // n-tile

    float acc[4][5][4];
#pragma unroll
    for (int a = 0; a < 4; a++)
#pragma unroll
        for (int b = 0; b < 5; b++)
#pragma unroll
            for (int c = 0; c < 4; c++) acc[a][b][c] = 0.f;

    // staging coords: thread handles row arow (0..63), 8 k-values at seg*8
    int arow = tid >> 3;
    int seg  = tid & 7;
    int gi_row = i0 + arow; if (gi_row > 255) gi_row = 255;
    const float* gi_base = g + (long)gi_row * 2304 + seg * 8;

    auto stage = [&](int ch) {
        uint32_t tb = sb + (uint32_t)(ch & 1) * PH1_BUF;
        int k0 = ch * 64;
        {
            const float4* gi4 = (const float4*)(gi_base + k0);
            float4 a0 = gi4[0], a1 = gi4[1];
            uint32_t sw = SWZ((uint32_t)(arow * 128 + seg * 16));
#pragma unroll
            for (int jj = 0; jj < 4; jj++) {
                const float4* gj4 =
                    (const float4*)(g + (long)(j0 + jj) * 2304 + seg * 8 + k0);
                float4 w0 = gj4[0], w1 = gj4[1];
                uint32_t h01 = pack_h2(a0.x * w0.x, a0.y * w0.y);
                uint32_t h23 = pack_h2(a0.z * w0.z, a0.w * w0.w);
                uint32_t h45 = pack_h2(a1.x * w1.x, a1.y * w1.y);
                uint32_t h67 = pack_h2(a1.z * w1.z, a1.w * w1.w);
                STS128(h01, h23, h45, h67,
                       tb + PH1_A + (uint32_t)jj * 8192 + sw);
            }
        }
        // B: 160 rows x 64 k f16 = 1280 x 16B, 512 threads
#pragma unroll
        for (int t = 0; t < 3; t++) {
            int idx = tid + t * 512;
            if (idx < 1280) {
                int n = idx >> 3, u = idx & 7;
                uint4 v = *(const uint4*)(g_wct + (long)n * 2304 + k0 + u * 8);
                uint32_t sw = SWZ((uint32_t)(n * 128 + u * 16));
                STS128(v.x, v.y, v.z, v.w, tb + PH1_B + sw);
            }
        }
    };

    stage(0);
    __syncthreads();

    for (int ch = 0; ch < 36; ch++) {
        if (ch < 35) stage(ch + 1);
        uint32_t tb = sb + (uint32_t)(ch & 1) * PH1_BUF;
        uint32_t ta = tb + PH1_A + (uint32_t)jsel * 8192;
        {
#pragma unroll
            for (int ks = 0; ks < 4; ks++) {
                uint32_t Bf[5][2];
                {
                    int m = lane >> 3;
                    int n = wn + (m >> 1) * 8 + (lane & 7);
                    uint32_t off = SWZ((uint32_t)(n * 128 + ks * 32 + (m & 1) * 16));
                    LDSM_X4(Bf[0][0], Bf[0][1], Bf[1][0], Bf[1][1], tb + PH1_B + off);
                }
                {
                    int m = lane >> 3;
                    int n = wn + 16 + (m >> 1) * 8 + (lane & 7);
                    uint32_t off = SWZ((uint32_t)(n * 128 + ks * 32 + (m & 1) * 16));
                    LDSM_X4(Bf[2][0], Bf[2][1], Bf[3][0], Bf[3][1], tb + PH1_B + off);
                }
                {
                    int n = wn + 32 + (lane & 7);
                    uint32_t off = SWZ((uint32_t)(n * 128 + ks * 32 + ((lane >> 3) & 1) * 16));
                    LDSM_X2(Bf[4][0], Bf[4][1], tb + PH1_B + off);
                }
#pragma unroll
                for (int mt = 0; mt < 4; mt++) {
                    if (mt * 16 >= M) continue;
                    int r = mt * 16 + (lane & 15);
                    uint32_t aoff = SWZ((uint32_t)(r * 128 + ks * 32 + (lane >> 4) * 16));
                    uint32_t A0, A1, A2, A3;
                    LDSM_X4(A0, A1, A2, A3, ta + aoff);
#pragma unroll
                    for (int nt = 0; nt < 5; nt++)
                        MMAF16(acc[mt][nt], A0, A1, A2, A3, Bf[nt][0], Bf[nt][1]);
                }
            }
        }
        __syncthreads();
    }

    // ---- epilogue: store RAW hij ----
    {
        int j = j0 + jsel;
#pragma unroll
        for (int mt = 0; mt < 4; mt++) {
            if (mt * 16 >= M) continue;
#pragma unroll
            for (int nt = 0; nt < 5; nt++) {
                int c = wn + nt * 8 + (lane & 3) * 2;
#pragma unroll
                for (int h = 0; h < 2; h++) {
                    int i = i0 + mt * 16 + (lane >> 2) + h * 8;
                    *(float2*)(h1p + ((long)i * 256 + j) * 160 + c) =
                        make_float2(acc[mt][nt][h * 2], acc[mt][nt][h * 2 + 1]);
                }
            }
        }
    }
}

// ---------------- per-pair: h1 assemble + h2 GEMM + score + clip --------
__global__ __launch_bounds__(256) void pair_out_kernel(
    const float* __restrict__ W2, const float* __restrict__ pb2,
    const float* __restrict__ w3, const float* __restrict__ pb3,
    float* __restrict__ out)
{
    __shared__ float sH1[32][160];
    __shared__ float sW2[32][160];
    __shared__ float sRed[32][16];

    const float* h1p = g_scratch + OFF_H1P;
    const float* m   = g_scratch + OFF_M;
    const float* hi  = g_scratch + OFF_HI;
    const float* hjb = g_scratch + OFF_HJB;

    int tid = threadIdx.x;
    int pg = tid >> 4, hg = tid & 15;
    long p0 = (long)blockIdx.x * 32;
    int i_fix = (int)(p0 >> 8);
    int j0 = (int)(p0 & 255);

    // assemble h1 = relu(hij + hi_i + hjb_j); mirror read for i<j
    {
        int r = tid >> 3, q = tid & 7;
        int j = j0 + r;
        long src = (j <= i_fix) ? ((long)i_fix * 256 + j) : ((long)j * 256 + i_fix);
        const float4* s4 = (const float4*)(h1p + src * 160);
        const float4* hi4 = (const float4*)(hi + (long)i_fix * 160);
        const float4* hb4 = (const float4*)(hjb + (long)j * 160);
        float4* d4 = (float4*)&sH1[r][0];
#pragma unroll
        for (int v = 0; v < 5; v++) {
            int idx = q + v * 8;
            float4 a = s4[idx], b = hi4[idx], c = hb4[idx];
            float4 o;
            o.x = fmaxf(a.x + b.x + c.x, 0.f);
            o.y = fmaxf(a.y + b.y + c.y, 0.f);
            o.z = fmaxf(a.z + b.z + c.z, 0.f);
            o.w = fmaxf(a.w + b.w + c.w, 0.f);
            d4[idx] = o;
        }
    }

    float acc[2][10];
#pragma unroll
    for (int a = 0; a < 2; a++)
#pragma unroll
        for (int b = 0; b < 10; b++) acc[a][b] = 0.f;

    for (int kc = 0; kc < 5; kc++) {
        int kb = kc * 32;
#pragma unroll
        for (int i = 0; i < 20; i++) {
            int idx = tid + i * 256;
            int e = idx / 160, h = idx - e * 160;
            int kk = kb + e;
            sW2[e][h] = (kk < 150 && h < 150) ? W2[(long)kk * 150 + h] : 0.f;
        }
        __syncthreads();
#pragma unroll 8
        for (int e = 0; e < 32; e++) {
            float x0 = sH1[pg * 2][kb + e];
            float x1 = sH1[pg * 2 + 1][kb + e];
#pragma unroll
            for (int hh = 0; hh < 10; hh += 2) {
                float2 w = *(const float2*)&sW2[e][hg * 10 + hh];
                acc[0][hh]     += x0 * w.x;  acc[0][hh + 1] += x0 * w.y;
                acc[1][hh]     += x1 * w.x;  acc[1][hh + 1] += x1 * w.y;
            }
        }
        __syncthreads();
    }

#pragma unroll
    for (int pp = 0; pp < 2; pp++) {
        float sacc = 0.f;
#pragma unroll
        for (int hh = 0; hh < 10; hh++) {
            int h = hg * 10 + hh;
            if (h < 150) {
                float v = fmaxf(acc[pp][hh] + pb2[h], 0.f);
                sacc += v * w3[h];
            }
        }
        sRed[pg * 2 + pp][hg] = sacc;
    }
    __syncthreads();
    if (tid < 32) {
        float s = pb3[0];
#pragma unroll
        for (int h = 0; h < 16; h++) s += sRed[tid][h];
        long pr = p0 + tid;
        int i = (int)(pr >> 8), jj = (int)(pr & 255);
        float v = (m[i] + m[jj] + s) * (1.f / 3.f);
        v = fminf(fmaxf(v, 0.f), 1.f);
        out[pr] = v;
    }
}

// ---------------- launch ------------------------------------------------
extern "C" void kernel_launch(void* const* d_in, const int* in_sizes, int n_in,
                              void* d_out, int out_size)
{
    const float* e   = (const float*)d_in[0];
    const int*   sp  = (const int*)d_in[1];
    const int*   wd  = (const int*)d_in[2];
    const float* aW1 = (const float*)d_in[3];
    const float* ab1 = (const float*)d_in[4];
    const float* aW2 = (const float*)d_in[5];
    const float* ab2 = (const float*)d_in[6];
    const float* aW3 = (const float*)d_in[7];
    const float* ab3 = (const float*)d_in[8];
    const float* mW1 = (const float*)d_in[9];
    const float* mb1 = (const float*)d_in[10];
    const float* mW2 = (const float*)d_in[11];
    const float* mb2 = (const float*)d_in[12];
    const float* mW3 = (const float*)d_in[13];
    const float* mb3 = (const float*)d_in[14];
    const float* pW1 = (const float*)d_in[15];
    const float* pb1 = (const float*)d_in[16];
    const float* pW2 = (const float*)d_in[17];
    const float* pb2 = (const float*)d_in[18];
    const float* pW3 = (const float*)d_in[19];
    const float* pb3 = (const float*)d_in[20];
    float* out = (float*)d_out;

    cudaFuncSetAttribute(pair_h1_mma, cudaFuncAttributeMaxDynamicSharedMemorySize,
                         PH1_SMEM);

    // Wc transpose -> f16 (independent)
    wct_split_kernel<<<1440, 256>>>(pW1 + 4608L * 150);

    // token MLP layer 1: split-K (6 x 128) -> partials -> reduce
    gemm_split<<<dim3(32, 6, 1), 256>>>(e, 0, 768, aW1, nullptr, nullptr,
                                        OFF_PART, 2048, 128);
    reduce_tok<<<2048, 160>>>(ab1);
    gemm150<1, 1, 16><<<2048 / 16, 256>>>(nullptr, OFF_H1TOK, 160, aW2, ab2,
                                          OFF_H2TOK, 160, 2048, 150);
    attn_we_kernel<<<2048, 256>>>(aW3, ab3, e);

    // span features
    gather_g_kernel<<<256, 256>>>(e, sp, wd);

    // fused mh1 / hi / hjb: split-K (12 x 192) x 3 weights -> reduce
    gemm_split<<<dim3(4, 12, 3), 256>>>(nullptr, OFF_G, 2304,
                                        mW1, pW1, pW1 + 2304L * 150,
                                        OFF_PART, 256, 192);
    reduce_3<<<dim3(256, 3), 160>>>(mb1, pb1);

    // lower-triangle hij on tensor cores (f16, 4 j's per CTA, full K)
    pair_h1_mma<<<dim3(64, 4), 512, PH1_SMEM>>>();

    // m MLP tail
    gemm150<1, 1, 16><<<256 / 16, 256>>>(nullptr, OFF_MH1, 160, mW2, mb2,
                                         OFF_MH2, 160, 256, 150);
    rowdot_kernel<<<256, 256>>>(OFF_MH2, mW3, mb3, OFF_M);

    // pairwise output (handles mirror + bias + relu)
    pair_out_kernel<<<65536 / 32, 256>>>(pW2, pb2, pW3, pb3, out);
}

// round 9
// speedup vs baseline: 8.4095x; 1.4730x over previous
#include <cuda_runtime.h>
#include <cuda_fp16.h>
#include <cstdint>

// Problem constants
#define TT 2048
#define EE 768
#define SSP 256
#define HHD 150
#define E3D 2304

// ---------------- scratch (device global, zero-init .bss) ----------------
static constexpr long OFF_H1TOK = 0;
static constexpr long OFF_WE    = OFF_H1TOK + 2048L * 160;
static constexpr long OFF_G     = OFF_WE    + 2048L * 768;
static constexpr long OFF_MH1   = OFF_G     + 256L * 2304;
static constexpr long OFF_MH2   = OFF_MH1   + 256L * 160;
static constexpr long OFF_M     = OFF_MH2   + 256L * 160;
static constexpr long OFF_HI    = OFF_M     + 256L;
static constexpr long OFF_HJB   = OFF_HI    + 256L * 160;
static constexpr long OFF_H1P   = OFF_HJB   + 256L * 160;
static constexpr long SCRATCH_TOTAL = OFF_H1P + 65536L * 160;
// split-K partial buffers alias the h1p region (consumed before pair_h1)
static constexpr long OFF_PART  = OFF_H1P;

__device__ __align__(16) float g_scratch[SCRATCH_TOTAL];

// Wc transposed, f16: [160 n][2304 k]
__device__ __align__(16) unsigned short g_wct[160L * 2304];
// W2 transposed, f16: [160 n][160 k]
__device__ __align__(16) unsigned short g_w2t[160L * 160];

// ======================= helpers ==========================
__device__ __forceinline__ uint32_t smem_u32(const void* p) {
    uint32_t a;
    asm("{ .reg .u64 t; cvta.to.shared.u64 t, %1; cvt.u32.u64 %0, t; }"
        : "=r"(a) : "l"(p));
    return a;
}
#define SWZ(x) ((x) ^ (((x) >> 3) & 0x70))
#define STS128(a0, a1, a2, a3, addr) \
    asm volatile("st.shared.v4.b32 [%0], {%1,%2,%3,%4};" \
                 :: "r"(addr), "r"(a0), "r"(a1), "r"(a2), "r"(a3) : "memory")

__device__ __forceinline__ uint32_t pack_h2(float lo, float hi) {
    uint32_t d;
    asm("cvt.rn.f16x2.f32 %0, %1, %2;" : "=r"(d) : "f"(hi), "f"(lo));
    return d;
}

#define LDSM_X4(r0, r1, r2, r3, a) \
    asm volatile("ldmatrix.sync.aligned.m8n8.x4.shared.b16 {%0,%1,%2,%3}, [%4];" \
                 : "=r"(r0), "=r"(r1), "=r"(r2), "=r"(r3) : "r"(a))
#define LDSM_X2(r0, r1, a) \
    asm volatile("ldmatrix.sync.aligned.m8n8.x2.shared.b16 {%0,%1}, [%2];" \
                 : "=r"(r0), "=r"(r1) : "r"(a))
#define MMAF16(c, A0, A1, A2, A3, B0, B1) \
    asm volatile("mma.sync.aligned.m16n8k16.row.col.f32.f16.f16.f32 " \
                 "{%0,%1,%2,%3}, {%4,%5,%6,%7}, {%8,%9}, {%0,%1,%2,%3};" \
                 : "+f"((c)[0]), "+f"((c)[1]), "+f"((c)[2]), "+f"((c)[3]) \
                 : "r"(A0), "r"(A1), "r"(A2), "r"(A3), "r"(B0), "r"(B1))

// ---------------- gemm150: C[M,150] = act(A[M,K] @ W[K,150] + b) --------
template <int ACT, int HASBIAS, int BM>
__global__ __launch_bounds__(256) void gemm150(
    const float* __restrict__ Aext, long aOff, int lda,
    const float* __restrict__ W,
    const float* __restrict__ bias,
    long cOff, int ldc, int M, int K)
{
    constexpr int RPT = BM / 16;
    const float* A = Aext ? Aext : (g_scratch + aOff);
    float* C = g_scratch + cOff;

    __shared__ float sA[16][BM + 4];
    __shared__ float sW[16][160];

    int tid = threadIdx.x;
    int rg = tid >> 4;
    int cg = tid & 15;
    int row0 = blockIdx.x * BM;

    float acc[RPT][10];
#pragma unroll
    for (int a = 0; a < RPT; a++)
#pragma unroll
        for (int b = 0; b < 10; b++) acc[a][b] = 0.f;

    int nCh = (K + 15) >> 4;
    for (int ch = 0; ch < nCh; ch++) {
        int k0 = ch * 16;
        {
            int c = tid & 15, r = tid >> 4;
#pragma unroll
            for (int pass = 0; pass < RPT; pass++) {
                int rl = pass * 16 + r;
                float v = 0.f;
                if (k0 + c < K) v = A[(long)(row0 + rl) * lda + k0 + c];
                sA[c][rl] = v;
            }
        }
#pragma unroll
        for (int i = 0; i < 10; i++) {
            int idx = tid + i * 256;
            int k = idx / 160, h = idx - k * 160;
            float v = 0.f;
            if (k0 + k < K && h < 150) v = W[(long)(k0 + k) * 150 + h];
            sW[k][h] = v;
        }
        __syncthreads();
#pragma unroll
        for (int k = 0; k < 16; k++) {
            float av[RPT];
#pragma unroll
            for (int rr = 0; rr < RPT; rr++) av[rr] = sA[k][rg * RPT + rr];
#pragma unroll
            for (int hh = 0; hh < 10; hh += 2) {
                float2 w = *(const float2*)&sW[k][cg * 10 + hh];
#pragma unroll
                for (int rr = 0; rr < RPT; rr++) {
                    acc[rr][hh]     += av[rr] * w.x;
                    acc[rr][hh + 1] += av[rr] * w.y;
                }
            }
        }
        __syncthreads();
    }

#pragma unroll
    for (int rr = 0; rr < RPT; rr++) {
        int row = row0 + rg * RPT + rr;
#pragma unroll
        for (int hh = 0; hh < 10; hh++) {
            int h = cg * 10 + hh;
            if (h < 150) {
                float v = acc[rr][hh];
                if (HASBIAS) v += bias[h];
                if (ACT) v = fmaxf(v, 0.f);
                C[(long)row * ldc + h] = v;
            }
        }
    }
}

// ------- fused token layer2 + attn dot + we = e*attn (16 tokens/CTA) ----
__global__ __launch_bounds__(256) void tok2_attn_we_kernel(
    const float* __restrict__ W,  const float* __restrict__ b2,
    const float* __restrict__ w3, const float* __restrict__ b3,
    const float* __restrict__ e)
{
    const float* A = g_scratch + OFF_H1TOK;
    float* we = g_scratch + OFF_WE;

    __shared__ float sA[16][20];
    __shared__ float sW[16][160];
    __shared__ float sRed[16][16];
    __shared__ float sAttn[16];

    int tid = threadIdx.x;
    int rg = tid >> 4;
    int cg = tid & 15;
    int row0 = blockIdx.x * 16;

    float acc[10];
#pragma unroll
    for (int b = 0; b < 10; b++) acc[b] = 0.f;

    for (int ch = 0; ch < 10; ch++) {
        int k0 = ch * 16;
        {
            int c = tid & 15, r = tid >> 4;
            float v = 0.f;
            if (k0 + c < 150) v = A[(long)(row0 + r) * 160 + k0 + c];
            sA[c][r] = v;
        }
#pragma unroll
        for (int i = 0; i < 10; i++) {
            int idx = tid + i * 256;
            int k = idx / 160, h = idx - k * 160;
            float v = 0.f;
            if (k0 + k < 150 && h < 150) v = W[(long)(k0 + k) * 150 + h];
            sW[k][h] = v;
        }
        __syncthreads();
#pragma unroll
        for (int k = 0; k < 16; k++) {
            float av = sA[k][rg];
#pragma unroll
            for (int hh = 0; hh < 10; hh += 2) {
                float2 w = *(const float2*)&sW[k][cg * 10 + hh];
                acc[hh]     += av * w.x;
                acc[hh + 1] += av * w.y;
            }
        }
        __syncthreads();
    }

    // partial dot relu(acc + b2) . w3
    float part = 0.f;
#pragma unroll
    for (int hh = 0; hh < 10; hh++) {
        int h = cg * 10 + hh;
        if (h < 150) part += fmaxf(acc[hh] + b2[h], 0.f) * w3[h];
    }
    sRed[rg][cg] = part;
    __syncthreads();
    if (tid < 16) {
        float s = b3[0];
#pragma unroll
        for (int c = 0; c < 16; c++) s += sRed[tid][c];
        sAttn[tid] = s;
    }
    __syncthreads();
    // we = e * attn : 16 tokens x 768 = 12288 floats, 48 per thread
#pragma unroll
    for (int it = 0; it < 48; it++) {
        int lin = it * 256 + tid;
        int r = lin / 768, c = lin - r * 768;
        long t = row0 + r;
        we[t * 768 + c] = e[t * 768 + c] * sAttn[r];
    }
}

// ---------------- split-K GEMM: partials, no bias/act -------------------
__global__ __launch_bounds__(256) void gemm_split(
    const float* __restrict__ Aext, long aOff, int lda,
    const float* __restrict__ W0, const float* __restrict__ W1,
    const float* __restrict__ W2,
    long partOff, int Mtot, int kPerSplit)
{
    const float* A = Aext ? Aext : (g_scratch + aOff);
    const float* W = (blockIdx.z == 0) ? W0 : ((blockIdx.z == 1) ? W1 : W2);
    float* P = g_scratch + partOff
             + ((long)(blockIdx.z * gridDim.y + blockIdx.y) * Mtot) * 160;

    __shared__ float sA[16][68];
    __shared__ float sW[16][160];

    int tid = threadIdx.x;
    int rg = tid >> 4;
    int cg = tid & 15;
    int row0 = blockIdx.x * 64;
    int kbase = blockIdx.y * kPerSplit;

    float acc[4][10];
#pragma unroll
    for (int a = 0; a < 4; a++)
#pragma unroll
        for (int b = 0; b < 10; b++) acc[a][b] = 0.f;

    int nCh = kPerSplit >> 4;
    for (int ch = 0; ch < nCh; ch++) {
        int k0 = kbase + ch * 16;
        {
            int c = tid & 15, r = tid >> 4;
#pragma unroll
            for (int pass = 0; pass < 4; pass++) {
                int rl = pass * 16 + r;
                sA[c][rl] = A[(long)(row0 + rl) * lda + k0 + c];
            }
        }
#pragma unroll
        for (int i = 0; i < 10; i++) {
            int idx = tid + i * 256;
            int k = idx / 160, h = idx - k * 160;
            sW[k][h] = (h < 150) ? W[(long)(k0 + k) * 150 + h] : 0.f;
        }
        __syncthreads();
#pragma unroll
        for (int k = 0; k < 16; k++) {
            float4 a4 = *(const float4*)&sA[k][rg * 4];
            float av0 = a4.x, av1 = a4.y, av2 = a4.z, av3 = a4.w;
#pragma unroll
            for (int hh = 0; hh < 10; hh += 2) {
                float2 w = *(const float2*)&sW[k][cg * 10 + hh];
                acc[0][hh]     += av0 * w.x;  acc[0][hh + 1] += av0 * w.y;
                acc[1][hh]     += av1 * w.x;  acc[1][hh + 1] += av1 * w.y;
                acc[2][hh]     += av2 * w.x;  acc[2][hh + 1] += av2 * w.y;
                acc[3][hh]     += av3 * w.x;  acc[3][hh + 1] += av3 * w.y;
            }
        }
        __syncthreads();
    }

#pragma unroll
    for (int rr = 0; rr < 4; rr++) {
        int row = row0 + rg * 4 + rr;
#pragma unroll
        for (int hh = 0; hh < 10; hh++) {
            int h = cg * 10 + hh;
            if (h < 150) P[(long)row * 160 + h] = acc[rr][hh];
        }
    }
}

// ---------------- token reduce: h1tok = relu(sum parts + ab1) -----------
__global__ __launch_bounds__(160) void reduce_tok(const float* __restrict__ ab1)
{
    int row = blockIdx.x, c = threadIdx.x;
    float s = 0.f;
    if (c < 150) {
#pragma unroll
        for (int k = 0; k < 6; k++)
            s += g_scratch[OFF_PART + ((long)k * 2048 + row) * 160 + c];
        s = fmaxf(s + ab1[c], 0.f);
    }
    g_scratch[OFF_H1TOK + (long)row * 160 + c] = s;
}

// ---------------- 3-way reduce: mh1 / hi / hjb --------------------------
__global__ __launch_bounds__(160) void reduce_3(
    const float* __restrict__ mb1, const float* __restrict__ pb1)
{
    int row = blockIdx.x, z = blockIdx.y, c = threadIdx.x;
    float s = 0.f;
    if (c < 150) {
#pragma unroll
        for (int k = 0; k < 12; k++)
            s += g_scratch[OFF_PART + ((long)(z * 12 + k) * 256 + row) * 160 + c];
    }
    if (z == 0) {
        float v = (c < 150) ? fmaxf(s + mb1[c], 0.f) : 0.f;
        g_scratch[OFF_MH1 + (long)row * 160 + c] = v;
    } else if (z == 1) {
        g_scratch[OFF_HI + (long)row * 160 + c] = s;
    } else {
        float v = s + ((c < 150) ? pb1[c] : 0.f);
        g_scratch[OFF_HJB + (long)row * 160 + c] = v;
    }
}

// ---------------- row dot: out[r] = A[r,:150] . w + b -------------------
__global__ __launch_bounds__(256) void rowdot_kernel(
    long aOff, const float* __restrict__ w, const float* __restrict__ b,
    long oOff)
{
    __shared__ float red[256];
    const float* A = g_scratch + aOff;
    float* out = g_scratch + oOff;
    int r = blockIdx.x, tid = threadIdx.x;
    float v = 0.f;
    if (tid < 150) v = A[(long)r * 160 + tid] * w[tid];
    red[tid] = v;
    __syncthreads();
    for (int s = 128; s > 0; s >>= 1) {
        if (tid < s) red[tid] += red[tid + s];
        __syncthreads();
    }
    if (tid == 0) out[r] = red[0] + b[0];
}

// ---------------- g = [e_start | e_end | span_sum] ----------------------
__global__ __launch_bounds__(256) void gather_g_kernel(
    const float* __restrict__ e,
    const int* __restrict__ sp, const int* __restrict__ wd)
{
    const float* we = g_scratch + OFF_WE;
    float* g = g_scratch + OFF_G;
    int s = blockIdx.x, tid = threadIdx.x;
    int st = sp[s];
    int en = st + wd[s];
    if (en > TT - 1) en = TT - 1;
    if (en < 0) en = 0;
#pragma unroll
    for (int i = 0; i < 3; i++) {
        int c = tid + i * 256;
        g[(long)s * 2304 + c]        = e[(long)st * 768 + c];
        g[(long)s * 2304 + 768 + c]  = e[(long)en * 768 + c];
        float sum = 0.f;
        for (int t = st; t <= en; t++) sum += we[(long)t * 768 + c];
        g[(long)s * 2304 + 1536 + c] = sum;
    }
}

// ---------------- Wc -> transposed f16 ----------------------------------
__global__ __launch_bounds__(256) void wct_split_kernel(const float* __restrict__ Wc)
{
    long idx = (long)blockIdx.x * 256 + threadIdx.x;
    int n = (int)(idx / 2304);
    int k = (int)(idx - (long)n * 2304);
    float w = (n < 150) ? Wc[(long)k * 150 + n] : 0.f;
    g_wct[idx] = __half_as_ushort(__float2half_rn(w));
}

// ---------------- W2 -> transposed f16 [160][160] -----------------------
__global__ __launch_bounds__(256) void w2t_prep_kernel(const float* __restrict__ W2)
{
    int idx = blockIdx.x * 256 + threadIdx.x;   // 0..25599
    int n = idx / 160, k = idx - n * 160;
    float w = (n < 150 && k < 150) ? W2[(long)k * 150 + n] : 0.f;
    g_w2t[idx] = __half_as_ushort(__float2half_rn(w));
}

// ================= pair_h1: lower-triangle hij, f16 mma =================
#define PH1_A  0
#define PH1_B  32768
#define PH1_BUF 53248
#define PH1_SMEM (2 * PH1_BUF)

__global__ void __launch_bounds__(512, 1) pair_h1_mma()
{
    extern __shared__ __align__(1024) char smem[];
    uint32_t sb = smem_u32(smem);

    const float* g = g_scratch + OFF_G;
    float* h1p     = g_scratch + OFF_H1P;

    int tid  = threadIdx.x;
    int lane = tid & 31;
    int wid  = tid >> 5;
    int jq   = blockIdx.x;
    int ib   = blockIdx.y;

    int j0 = jq * 4;
    int fj = j0 & ~15;
    int i0 = fj + ib * 64;
    if (i0 >= 256) return;
    int M = 256 - i0;
    if (M > 64) M = 64;

    int jsel = wid >> 2;
    int wn   = (wid & 3) * 40;

    float acc[4][5][4];
#pragma unroll
    for (int a = 0; a < 4; a++)
#pragma unroll
        for (int b = 0; b < 5; b++)
#pragma unroll
            for (int c = 0; c < 4; c++) acc[a][b][c] = 0.f;

    int arow = tid >> 3;
    int seg  = tid & 7;
    int gi_row = i0 + arow; if (gi_row > 255) gi_row = 255;
    const float* gi_base = g + (long)gi_row * 2304 + seg * 8;

    auto stage = [&](int ch) {
        uint32_t tb = sb + (uint32_t)(ch & 1) * PH1_BUF;
        int k0 = ch * 64;
        {
            const float4* gi4 = (const float4*)(gi_base + k0);
            float4 a0 = gi4[0], a1 = gi4[1];
            uint32_t sw = SWZ((uint32_t)(arow * 128 + seg * 16));
#pragma unroll
            for (int jj = 0; jj < 4; jj++) {
                const float4* gj4 =
                    (const float4*)(g + (long)(j0 + jj) * 2304 + seg * 8 + k0);
                float4 w0 = gj4[0], w1 = gj4[1];
                uint32_t h01 = pack_h2(a0.x * w0.x, a0.y * w0.y);
                uint32_t h23 = pack_h2(a0.z * w0.z, a0.w * w0.w);
                uint32_t h45 = pack_h2(a1.x * w1.x, a1.y * w1.y);
                uint32_t h67 = pack_h2(a1.z * w1.z, a1.w * w1.w);
                STS128(h01, h23, h45, h67,
                       tb + PH1_A + (uint32_t)jj * 8192 + sw);
            }
        }
#pragma unroll
        for (int t = 0; t < 3; t++) {
            int idx = tid + t * 512;
            if (idx < 1280) {
                int n = idx >> 3, u = idx & 7;
                uint4 v = *(const uint4*)(g_wct + (long)n * 2304 + k0 + u * 8);
                uint32_t sw = SWZ((uint32_t)(n * 128 + u * 16));
                STS128(v.x, v.y, v.z, v.w, tb + PH1_B + sw);
            }
        }
    };

    stage(0);
    __syncthreads();

    for (int ch = 0; ch < 36; ch++) {
        if (ch < 35) stage(ch + 1);
        uint32_t tb = sb + (uint32_t)(ch & 1) * PH1_BUF;
        uint32_t ta = tb + PH1_A + (uint32_t)jsel * 8192;
#pragma unroll
        for (int ks = 0; ks < 4; ks++) {
            uint32_t Bf[5][2];
            {
                int m = lane >> 3;
                int n = wn + (m >> 1) * 8 + (lane & 7);
                uint32_t off = SWZ((uint32_t)(n * 128 + ks * 32 + (m & 1) * 16));
                LDSM_X4(Bf[0][0], Bf[0][1], Bf[1][0], Bf[1][1], tb + PH1_B + off);
            }
            {
                int m = lane >> 3;
                int n = wn + 16 + (m >> 1) * 8 + (lane & 7);
                uint32_t off = SWZ((uint32_t)(n * 128 + ks * 32 + (m & 1) * 16));
                LDSM_X4(Bf[2][0], Bf[2][1], Bf[3][0], Bf[3][1], tb + PH1_B + off);
            }
            {
                int n = wn + 32 + (lane & 7);
                uint32_t off = SWZ((uint32_t)(n * 128 + ks * 32 + ((lane >> 3) & 1) * 16));
                LDSM_X2(Bf[4][0], Bf[4][1], tb + PH1_B + off);
            }
#pragma unroll
            for (int mt = 0; mt < 4; mt++) {
                if (mt * 16 >= M) continue;
                int r = mt * 16 + (lane & 15);
                uint32_t aoff = SWZ((uint32_t)(r * 128 + ks * 32 + (lane >> 4) * 16));
                uint32_t A0, A1, A2, A3;
                LDSM_X4(A0, A1, A2, A3, ta + aoff);
#pragma unroll
                for (int nt = 0; nt < 5; nt++)
                    MMAF16(acc[mt][nt], A0, A1, A2, A3, Bf[nt][0], Bf[nt][1]);
            }
        }
        __syncthreads();
    }

    {
        int j = j0 + jsel;
#pragma unroll
        for (int mt = 0; mt < 4; mt++) {
            if (mt * 16 >= M) continue;
#pragma unroll
            for (int nt = 0; nt < 5; nt++) {
                int c = wn + nt * 8 + (lane & 3) * 2;
#pragma unroll
                for (int h = 0; h < 2; h++) {
                    int i = i0 + mt * 16 + (lane >> 2) + h * 8;
                    *(float2*)(h1p + ((long)i * 256 + j) * 160 + c) =
                        make_float2(acc[mt][nt][h * 2], acc[mt][nt][h * 2 + 1]);
                }
            }
        }
    }
}

// ============ pair_out on tensor cores (64 pairs/CTA, f16) ==============
// A (h1, assembled+relu'd, f16): [3 kblk][64 p][64 k]  swizzled
// B (W2^T f16):                  [3 kblk][160 n][64 k] swizzled
#define PO_A 0
#define PO_B 24576
#define PO_RED 86016
#define PO_SMEM (86016 + 64 * 4 * 4)

__global__ void __launch_bounds__(256, 2) pair_out_mma(
    const float* __restrict__ pb2, const float* __restrict__ w3,
    const float* __restrict__ pb3, float* __restrict__ out)
{
    extern __shared__ __align__(1024) char smem[];
    uint32_t sb = smem_u32(smem);
    float* sRed = (float*)(smem + PO_RED);     // [64][4]

    const float* h1p = g_scratch + OFF_H1P;
    const float* mm  = g_scratch + OFF_M;
    const float* hi  = g_scratch + OFF_HI;
    const float* hjb = g_scratch + OFF_HJB;

    int tid  = threadIdx.x;
    int lane = tid & 31;
    int wid  = tid >> 5;
    long p0 = (long)blockIdx.x * 64;
    int i_fix = (int)(p0 >> 8);
    int j0 = (int)(p0 & 255);

    int wm = (wid >> 2) * 32;
    int wn = (wid & 3) * 40;

    // ---- stage A: assemble h1 = relu(hij + hi + hjb), f16, swizzled ----
    {
        const float* hirow = hi + (long)i_fix * 160;
#pragma unroll
        for (int t = 0; t < 8; t++) {
            int idx = tid + t * 256;        // p = idx>>5, seg = idx&31
            int p = idx >> 5, seg = idx & 31;
            if (seg < 20) {
                int j = j0 + p;
                long src = (j <= i_fix) ? ((long)i_fix * 256 + j)
                                        : ((long)j * 256 + i_fix);
                int kc = seg * 8;
                const float4* s4 = (const float4*)(h1p + src * 160 + kc);
                const float4* h4 = (const float4*)(hirow + kc);
                const float4* b4 = (const float4*)(hjb + (long)j * 160 + kc);
                float4 x0 = s4[0], x1 = s4[1];
                float4 y0 = h4[0], y1 = h4[1];
                float4 z0 = b4[0], z1 = b4[1];
                float f0 = fmaxf(x0.x + y0.x + z0.x, 0.f);
                float f1 = fmaxf(x0.y + y0.y + z0.y, 0.f);
                float f2 = fmaxf(x0.z + y0.z + z0.z, 0.f);
                float f3 = fmaxf(x0.w + y0.w + z0.w, 0.f);
                float f4 = fmaxf(x1.x + y1.x + z1.x, 0.f);
                float f5 = fmaxf(x1.y + y1.y + z1.y, 0.f);
                float f6 = fmaxf(x1.z + y1.z + z1.z, 0.f);
                float f7 = fmaxf(x1.w + y1.w + z1.w, 0.f);
                uint32_t h01 = pack_h2(f0, f1), h23 = pack_h2(f2, f3);
                uint32_t h45 = pack_h2(f4, f5), h67 = pack_h2(f6, f7);
                int kblk = seg >> 3, uu = seg & 7;
                uint32_t addr = sb + PO_A + (uint32_t)kblk * 8192
                              + SWZ((uint32_t)(p * 128 + uu * 16));
                STS128(h01, h23, h45, h67, addr);
            }
        }
    }
    // ---- stage B: W2^T f16 ----
    {
#pragma unroll
        for (int t = 0; t < 15; t++) {
            int idx = tid + t * 256;        // 0..3839: n = idx/24, u = idx%24
            if (idx < 3840) {
                int n = idx / 24, u = idx - n * 24;
                int kblk = u >> 3, uu = u & 7;
                int k0 = kblk * 64 + uu * 8;
                uint4 v = make_uint4(0, 0, 0, 0);
                if (k0 < 160) v = *(const uint4*)(g_w2t + (long)n * 160 + k0);
                uint32_t addr = sb + PO_B + (uint32_t)kblk * 20480
                              + SWZ((uint32_t)(n * 128 + uu * 16));
                STS128(v.x, v.y, v.z, v.w, addr);
            }
        }
    }
    __syncthreads();

    float acc[2][5][4];
#pragma unroll
    for (int a = 0; a < 2; a++)
#pragma unroll
        for (int b = 0; b < 5; b++)
#pragma unroll
            for (int c = 0; c < 4; c++) acc[a][b][c] = 0.f;

#pragma unroll
    for (int kblk = 0; kblk < 3; kblk++) {
        uint32_t ta = sb + PO_A + (uint32_t)kblk * 8192;
        uint32_t tbb = sb + PO_B + (uint32_t)kblk * 20480;
        int kmax = (kblk == 2) ? 2 : 4;
#pragma unroll
        for (int ks = 0; ks < 4; ks++) {
            if (ks >= kmax) break;
            uint32_t Bf[5][2];
            {
                int m = lane >> 3;
                int n = wn + (m >> 1) * 8 + (lane & 7);
                uint32_t off = SWZ((uint32_t)(n * 128 + ks * 32 + (m & 1) * 16));
                LDSM_X4(Bf[0][0], Bf[0][1], Bf[1][0], Bf[1][1], tbb + off);
            }
            {
                int m = lane >> 3;
                int n = wn + 16 + (m >> 1) * 8 + (lane & 7);
                uint32_t off = SWZ((uint32_t)(n * 128 + ks * 32 + (m & 1) * 16));
                LDSM_X4(Bf[2][0], Bf[2][1], Bf[3][0], Bf[3][1], tbb + off);
            }
            {
                int n = wn + 32 + (lane & 7);
                uint32_t off = SWZ((uint32_t)(n * 128 + ks * 32 + ((lane >> 3) & 1) * 16));
                LDSM_X2(Bf[4][0], Bf[4][1], tbb + off);
            }
#pragma unroll
            for (int mt = 0; mt < 2; mt++) {
                int r = wm + mt * 16 + (lane & 15);
                uint32_t aoff = SWZ((uint32_t)(r * 128 + ks * 32 + (lane >> 4) * 16));
                uint32_t A0, A1, A2, A3;
                LDSM_X4(A0, A1, A2, A3, ta + aoff);
#pragma unroll
                for (int nt = 0; nt < 5; nt++)
                    MMAF16(acc[mt][nt], A0, A1, A2, A3, Bf[nt][0], Bf[nt][1]);
            }
        }
    }

    // ---- epilogue: s = relu(h2 + pb2) . w3, reduce, clip, write --------
    float part[2][2] = {{0.f, 0.f}, {0.f, 0.f}};
#pragma unroll
    for (int nt = 0; nt < 5; nt++) {
        int c = wn + nt * 8 + (lane & 3) * 2;
        float b0 = 0.f, w0 = 0.f, b1 = 0.f, w1 = 0.f;
        if (c < 150)     { b0 = pb2[c];     w0 = w3[c]; }
        if (c + 1 < 150) { b1 = pb2[c + 1]; w1 = w3[c + 1]; }
#pragma unroll
        for (int mt = 0; mt < 2; mt++)
#pragma unroll
            for (int h = 0; h < 2; h++) {
                part[mt][h] += fmaxf(acc[mt][nt][h * 2] + b0, 0.f) * w0
                             + fmaxf(acc[mt][nt][h * 2 + 1] + b1, 0.f) * w1;
            }
    }
#pragma unroll
    for (int mt = 0; mt < 2; mt++)
#pragma unroll
        for (int h = 0; h < 2; h++) {
            part[mt][h] += __shfl_xor_sync(0xffffffff, part[mt][h], 1);
            part[mt][h] += __shfl_xor_sync(0xffffffff, part[mt][h], 2);
        }
    if ((lane & 3) == 0) {
#pragma unroll
        for (int mt = 0; mt < 2; mt++)
#pragma unroll
            for (int h = 0; h < 2; h++) {
                int row = wm + mt * 16 + (lane >> 2) + h * 8;
                sRed[row * 4 + (wid & 3)] = part[mt][h];
            }
    }
    __syncthreads();
    if (tid < 64) {
        float s = pb3[0] + sRed[tid * 4] + sRed[tid * 4 + 1]
                + sRed[tid * 4 + 2] + sRed[tid * 4 + 3];
        long pr = p0 + tid;
        int jj = (int)(pr & 255);
        float v = (mm[i_fix] + mm[jj] + s) * (1.f / 3.f);
        v = fminf(fmaxf(v, 0.f), 1.f);
        out[pr] = v;
    }
}

// ---------------- launch ------------------------------------------------
extern "C" void kernel_launch(void* const* d_in, const int* in_sizes, int n_in,
                              void* d_out, int out_size)
{
    const float* e   = (const float*)d_in[0];
    const int*   sp  = (const int*)d_in[1];
    const int*   wd  = (const int*)d_in[2];
    const float* aW1 = (const float*)d_in[3];
    const float* ab1 = (const float*)d_in[4];
    const float* aW2 = (const float*)d_in[5];
    const float* ab2 = (const float*)d_in[6];
    const float* aW3 = (const float*)d_in[7];
    const float* ab3 = (const float*)d_in[8];
    const float* mW1 = (const float*)d_in[9];
    const float* mb1 = (const float*)d_in[10];
    const float* mW2 = (const float*)d_in[11];
    const float* mb2 = (const float*)d_in[12];
    const float* mW3 = (const float*)d_in[13];
    const float* mb3 = (const float*)d_in[14];
    const float* pW1 = (const float*)d_in[15];
    const float* pb1 = (const float*)d_in[16];
    const float* pW2 = (const float*)d_in[17];
    const float* pb2 = (const float*)d_in[18];
    const float* pW3 = (const float*)d_in[19];
    const float* pb3 = (const float*)d_in[20];
    float* out = (float*)d_out;

    cudaFuncSetAttribute(pair_h1_mma, cudaFuncAttributeMaxDynamicSharedMemorySize,
                         PH1_SMEM);
    cudaFuncSetAttribute(pair_out_mma, cudaFuncAttributeMaxDynamicSharedMemorySize,
                         PO_SMEM);

    // weight preps (independent)
    wct_split_kernel<<<1440, 256>>>(pW1 + 4608L * 150);
    w2t_prep_kernel<<<100, 256>>>(pW2);

    // token MLP layer 1: split-K (6 x 128) -> partials -> reduce
    gemm_split<<<dim3(32, 6, 1), 256>>>(e, 0, 768, aW1, nullptr, nullptr,
                                        OFF_PART, 2048, 128);
    reduce_tok<<<2048, 160>>>(ab1);
    // fused layer2 + attn + we
    tok2_attn_we_kernel<<<128, 256>>>(aW2, ab2, aW3, ab3, e);

    // span features
    gather_g_kernel<<<256, 256>>>(e, sp, wd);

    // fused mh1 / hi / hjb: split-K (12 x 192) x 3 weights -> reduce
    gemm_split<<<dim3(4, 12, 3), 256>>>(nullptr, OFF_G, 2304,
                                        mW1, pW1, pW1 + 2304L * 150,
                                        OFF_PART, 256, 192);
    reduce_3<<<dim3(256, 3), 160>>>(mb1, pb1);

    // lower-triangle hij on tensor cores (f16, 4 j's per CTA, full K)
    pair_h1_mma<<<dim3(64, 4), 512, PH1_SMEM>>>();

    // m MLP tail
    gemm150<1, 1, 16><<<256 / 16, 256>>>(nullptr, OFF_MH1, 160, mW2, mb2,
                                         OFF_MH2, 160, 256, 150);
    rowdot_kernel<<<256, 256>>>(OFF_MH2, mW3, mb3, OFF_M);

    // pairwise output on tensor cores
    pair_out_mma<<<1024, 256, PO_SMEM>>>(pb2, pW3, pb3, out);
}